// round 1
// baseline (speedup 1.0000x reference)
#include <cuda_runtime.h>
#include <math.h>

// ---------------- scratch (device globals; allocation-free rule) ----------------
__device__ float  g_S [4096*512];    // residual stream, [B,T,D]
__device__ float  g_T1[4096*2048];   // ffn hidden / qkv / pw1 out
__device__ float  g_T2[4096*512];
__device__ float  g_T3[4096*512];
__device__ float  g_DD[8*2047];      // rel-pos bias table [h][rel+1023]
__device__ float2 g_part[1024];      // groupnorm partials
__device__ float2 g_mv[4];           // (mean, inv_std) per batch

__device__ __forceinline__ float gelu_f(float x){
    return 0.5f * x * (1.0f + erff(x * 0.70710678118654752440f));
}
__device__ __forceinline__ float sigm(float x){ return 1.0f/(1.0f + expf(-x)); }

// ---------------- transposes ----------------
__global__ void transpose_bdt_btd(const float* __restrict__ in, float* __restrict__ out){
    __shared__ float tile[32][33];
    int b = blockIdx.z;
    int t0 = blockIdx.x*32, d0 = blockIdx.y*32;
    int lx = threadIdx.x, ly = threadIdx.y;
    #pragma unroll
    for (int i=0;i<32;i+=8)
        tile[ly+i][lx] = in[((size_t)b*512 + d0+ly+i)*1024 + t0 + lx];
    __syncthreads();
    #pragma unroll
    for (int i=0;i<32;i+=8)
        out[((size_t)b*1024 + t0+ly+i)*512 + d0 + lx] = tile[lx][ly+i];
}
__global__ void transpose_btd_bdt(const float* __restrict__ in, float* __restrict__ out){
    __shared__ float tile[32][33];
    int b = blockIdx.z;
    int d0 = blockIdx.x*32, t0 = blockIdx.y*32;
    int lx = threadIdx.x, ly = threadIdx.y;
    #pragma unroll
    for (int i=0;i<32;i+=8)
        tile[ly+i][lx] = in[((size_t)b*1024 + t0+ly+i)*512 + d0 + lx];
    __syncthreads();
    #pragma unroll
    for (int i=0;i<32;i+=8)
        out[((size_t)b*512 + d0+ly+i)*1024 + t0 + lx] = tile[lx][ly+i];
}

// ---------------- generic SGEMM: C = epi(A[MxK] @ B[KxN] + bias) ----------------
// 128x128 tile, Ktile=8, 256 threads, 8x8 micro (split 4+4 for conflict-free lds128)
template<bool GELU_, bool RES_>
__global__ void __launch_bounds__(256,2) sgemm_k(
    const float* __restrict__ A, const float* __restrict__ B,
    const float* __restrict__ bias, const float* __restrict__ res,
    float* __restrict__ C, int M, int N, int Kd, float rscale)
{
    __shared__ float As[8][132];
    __shared__ float Bs[8][132];
    int tid = threadIdx.x;
    int row0 = blockIdx.y*128, col0 = blockIdx.x*128;
    int am = tid >> 1,  ak = (tid & 1)*4;
    int bk = tid >> 5,  bn = (tid & 31)*4;
    int tx = tid & 15,  ty = tid >> 4;

    const float* Ap = A + (size_t)(row0+am)*Kd + ak;
    const float* Bp = B + (size_t)bk*N + col0 + bn;
    float4 a4 = *(const float4*)Ap;
    float4 b4 = *(const float4*)Bp;

    float acc[8][8];
    #pragma unroll
    for (int i=0;i<8;i++)
        #pragma unroll
        for (int j=0;j<8;j++) acc[i][j]=0.f;

    int nk = Kd >> 3;
    for (int kt=0; kt<nk; ++kt){
        As[ak+0][am]=a4.x; As[ak+1][am]=a4.y; As[ak+2][am]=a4.z; As[ak+3][am]=a4.w;
        *(float4*)&Bs[bk][bn] = b4;
        __syncthreads();
        if (kt+1 < nk){
            a4 = *(const float4*)(Ap + (size_t)(kt+1)*8);
            b4 = *(const float4*)(Bp + (size_t)(kt+1)*8*N);
        }
        #pragma unroll
        for (int kk=0;kk<8;kk++){
            float ar[8], br[8];
            *(float4*)&ar[0] = *(const float4*)&As[kk][ty*4];
            *(float4*)&ar[4] = *(const float4*)&As[kk][64 + ty*4];
            *(float4*)&br[0] = *(const float4*)&Bs[kk][tx*4];
            *(float4*)&br[4] = *(const float4*)&Bs[kk][64 + tx*4];
            #pragma unroll
            for (int i=0;i<8;i++)
                #pragma unroll
                for (int j=0;j<8;j++) acc[i][j] = fmaf(ar[i], br[j], acc[i][j]);
        }
        __syncthreads();
    }
    #pragma unroll
    for (int i=0;i<8;i++){
        int r = row0 + ((i<4) ? (ty*4+i) : (64 + ty*4 + (i-4)));
        #pragma unroll
        for (int j=0;j<8;j++){
            int c = col0 + ((j<4) ? (tx*4+j) : (64 + tx*4 + (j-4)));
            float v = acc[i][j] + bias[c];
            if (GELU_) v = gelu_f(v);
            if (RES_)  v = res[(size_t)r*N + c] + rscale*v;
            C[(size_t)r*N + c] = v;
        }
    }
}

// ---------------- relative-position bias table ----------------
__global__ void build_dd_k(const float* __restrict__ rel_embed, float* __restrict__ ddt){
    int idx = blockIdx.x*256 + threadIdx.x;
    if (idx >= 8*2047) return;
    int h = idx / 2047;
    int rpos = idx % 2047;
    int rel = rpos - 1023;
    int sign = (rel >= 0) ? 1 : 0;
    int a = (rel >= 0) ? rel : -rel;
    int bucket;
    if (a < 80) bucket = a;
    else {
        float lr = logf((float)a / 80.0f) / logf(10.0f);   // log(MD/small)=log(10)
        int lp = 80 + (int)(lr * 80.0f);                    // trunc toward 0
        bucket = (lp < 159) ? lp : 159;
    }
    bucket += sign*160;
    if (bucket < 0) bucket = 0;
    if (bucket > 319) bucket = 319;
    ddt[h*2047 + rpos] = rel_embed[bucket*8 + h];
}

// ---------------- flash attention with gated rel-pos bias ----------------
// probs = softmax_s( q.k/8 + coef[b,h,t] * dd[h, s-t] );  out[b,t,h,dh]
// 64 queries x 64 keys per block, 256 threads (16x16), 4x4 micro-tiles.
__global__ void __launch_bounds__(256) flash_attn_k(
    const float* __restrict__ qkv,     // [B,T,3,H,DH] = row stride 1536
    const float* __restrict__ gate_u, const float* __restrict__ gate_w,
    const float* __restrict__ gate_scale, const float* __restrict__ ddt,
    float* __restrict__ out)           // [B,T,512]
{
    extern __shared__ float sm[];
    float* Qt    = sm;            // [64 d][64 m]
    float* KP    = sm + 4096;     // Kt [64 d][64 n], reused as Pt [64 n][64 m]
    float* Vs    = sm + 8192;     // [64 n][64 d]
    float* coefs = sm + 12288;    // [64]

    int tid = threadIdx.x;
    int tx = tid & 15, ty = tid >> 4;
    int t0 = blockIdx.x * 64;
    int h  = blockIdx.y;
    int b  = blockIdx.z;

    const float* qbase = qkv + (size_t)b*1024*1536 + h*64;
    const float* kbase = qbase + 512;
    const float* vbase = qbase + 1024;

    { // load Q transposed: Qt[d][m]
        int m  = tid >> 2;
        int dg = (tid & 3) * 16;
        const float* qrow = qbase + (size_t)(t0+m)*1536 + dg;
        #pragma unroll
        for (int i=0;i<4;i++){
            float4 v = *(const float4*)(qrow + i*4);
            int d = dg + i*4;
            Qt[(d+0)*64+m]=v.x; Qt[(d+1)*64+m]=v.y; Qt[(d+2)*64+m]=v.z; Qt[(d+3)*64+m]=v.w;
        }
    }
    if (tid < 64){ // per-query gate coefficient
        const float* qrow = qbase + (size_t)(t0+tid)*1536;
        float du=0.f, dw=0.f;
        #pragma unroll
        for (int d=0; d<64; d++){
            float qv = qrow[d];
            du = fmaf(qv, gate_u[h*64+d], du);
            dw = fmaf(qv, gate_w[h*64+d], dw);
        }
        float gu = sigm(du), gr = sigm(dw);
        coefs[tid] = 1.0f + gu + (1.0f-gu)*gate_scale[h]*gr;
    }

    float m_run[4], l_run[4], O[4][4];
    #pragma unroll
    for (int i=0;i<4;i++){
        m_run[i] = -3.0e38f; l_run[i] = 0.f;
        #pragma unroll
        for (int j=0;j<4;j++) O[i][j]=0.f;
    }

    for (int s0=0; s0<1024; s0+=64){
        { // load K transposed + V direct
            int m  = tid >> 2;
            int dg = (tid & 3)*16;
            const float* krow = kbase + (size_t)(s0+m)*1536 + dg;
            const float* vrow = vbase + (size_t)(s0+m)*1536 + dg;
            #pragma unroll
            for (int i=0;i<4;i++){
                float4 kv = *(const float4*)(krow + i*4);
                int d = dg + i*4;
                KP[(d+0)*64+m]=kv.x; KP[(d+1)*64+m]=kv.y; KP[(d+2)*64+m]=kv.z; KP[(d+3)*64+m]=kv.w;
                *(float4*)&Vs[m*64 + dg + i*4] = *(const float4*)(vrow + i*4);
            }
        }
        float ddr[7]; // bias values for this thread's 4x4 tile: rel = base + (j-i)
        {
            int bi = h*2047 + 1023 + (s0 - t0) + (tx - ty)*4 - 3;
            #pragma unroll
            for (int k=0;k<7;k++) ddr[k] = ddt[bi+k];
        }
        __syncthreads();

        float S[4][4];
        #pragma unroll
        for (int i=0;i<4;i++)
            #pragma unroll
            for (int j=0;j<4;j++) S[i][j]=0.f;
        #pragma unroll 8
        for (int d=0; d<64; d++){
            float4 a4 = *(const float4*)&Qt[d*64 + ty*4];
            float4 b4 = *(const float4*)&KP[d*64 + tx*4];
            float a[4]={a4.x,a4.y,a4.z,a4.w}, bb[4]={b4.x,b4.y,b4.z,b4.w};
            #pragma unroll
            for (int i=0;i<4;i++)
                #pragma unroll
                for (int j=0;j<4;j++) S[i][j] = fmaf(a[i], bb[j], S[i][j]);
        }
        float cf[4];
        #pragma unroll
        for (int i=0;i<4;i++) cf[i] = coefs[ty*4+i];
        #pragma unroll
        for (int i=0;i<4;i++)
            #pragma unroll
            for (int j=0;j<4;j++)
                S[i][j] = fmaf(S[i][j], 0.125f, cf[i]*ddr[3 + j - i]);

        // online softmax (row state redundant across the 16 tx lanes, kept consistent via shfl)
        #pragma unroll
        for (int i=0;i<4;i++){
            float mn = fmaxf(fmaxf(S[i][0],S[i][1]), fmaxf(S[i][2],S[i][3]));
            mn = fmaxf(mn, __shfl_xor_sync(0xffffffffu, mn, 1));
            mn = fmaxf(mn, __shfl_xor_sync(0xffffffffu, mn, 2));
            mn = fmaxf(mn, __shfl_xor_sync(0xffffffffu, mn, 4));
            mn = fmaxf(mn, __shfl_xor_sync(0xffffffffu, mn, 8));
            float mo = fmaxf(m_run[i], mn);
            float alpha = expf(m_run[i] - mo);
            m_run[i] = mo;
            float ls = 0.f;
            #pragma unroll
            for (int j=0;j<4;j++){ float p = expf(S[i][j]-mo); S[i][j]=p; ls += p; }
            ls += __shfl_xor_sync(0xffffffffu, ls, 1);
            ls += __shfl_xor_sync(0xffffffffu, ls, 2);
            ls += __shfl_xor_sync(0xffffffffu, ls, 4);
            ls += __shfl_xor_sync(0xffffffffu, ls, 8);
            l_run[i] = l_run[i]*alpha + ls;
            #pragma unroll
            for (int j=0;j<4;j++) O[i][j] *= alpha;
        }

        __syncthreads();   // done reading KP as K-tile
        #pragma unroll
        for (int i=0;i<4;i++)
            #pragma unroll
            for (int j=0;j<4;j++)
                KP[(tx*4+j)*64 + ty*4+i] = S[i][j];   // Pt[n][m]
        __syncthreads();

        #pragma unroll 8
        for (int n=0;n<64;n++){
            float4 a4 = *(const float4*)&KP[n*64 + ty*4];
            float4 b4 = *(const float4*)&Vs[n*64 + tx*4];
            float a[4]={a4.x,a4.y,a4.z,a4.w}, bb[4]={b4.x,b4.y,b4.z,b4.w};
            #pragma unroll
            for (int i=0;i<4;i++)
                #pragma unroll
                for (int j=0;j<4;j++) O[i][j] = fmaf(a[i], bb[j], O[i][j]);
        }
        __syncthreads();   // PV done: safe to overwrite KP/Vs next iter
    }
    #pragma unroll
    for (int i=0;i<4;i++){
        float inv = 1.0f / l_run[i];
        int t = t0 + ty*4 + i;
        float4 o4 = make_float4(O[i][0]*inv, O[i][1]*inv, O[i][2]*inv, O[i][3]*inv);
        *(float4*)&out[((size_t)(b*1024+t))*512 + h*64 + tx*4] = o4;
    }
}

// ---------------- GroupNorm(1, C) over [B,T,D]: deterministic 2-level reduction ----
__global__ void gn_partial_k(const float* __restrict__ x, float2* __restrict__ part){
    int b = blockIdx.x >> 8;
    int blk = blockIdx.x & 255;
    const float* p = x + (size_t)b*524288 + (size_t)blk*2048;
    float s=0.f, q=0.f;
    for (int i=threadIdx.x; i<2048; i+=256){ float v=p[i]; s+=v; q=fmaf(v,v,q); }
    __shared__ float ss[256], sq[256];
    ss[threadIdx.x]=s; sq[threadIdx.x]=q;
    __syncthreads();
    for (int o=128;o>0;o>>=1){
        if (threadIdx.x<o){ ss[threadIdx.x]+=ss[threadIdx.x+o]; sq[threadIdx.x]+=sq[threadIdx.x+o]; }
        __syncthreads();
    }
    if (threadIdx.x==0) part[blockIdx.x] = make_float2(ss[0], sq[0]);
}
__global__ void gn_final_k(const float2* __restrict__ part, float2* __restrict__ mv){
    int b = blockIdx.x;
    float2 v = part[b*256 + threadIdx.x];
    __shared__ float ss[256], sq[256];
    ss[threadIdx.x]=v.x; sq[threadIdx.x]=v.y;
    __syncthreads();
    for (int o=128;o>0;o>>=1){
        if (threadIdx.x<o){ ss[threadIdx.x]+=ss[threadIdx.x+o]; sq[threadIdx.x]+=sq[threadIdx.x+o]; }
        __syncthreads();
    }
    if (threadIdx.x==0){
        float mean = ss[0]*(1.0f/524288.0f);
        float var  = sq[0]*(1.0f/524288.0f) - mean*mean;
        mv[b] = make_float2(mean, rsqrtf(var + 1e-5f));
    }
}
template<bool SILU_>
__global__ void gn_apply_k(const float* __restrict__ x, const float2* __restrict__ mv,
                           const float* __restrict__ g, const float* __restrict__ be,
                           float* __restrict__ y){
    size_t idx = (size_t)blockIdx.x*256 + threadIdx.x;
    int b = (int)(idx >> 19);
    int d = (int)(idx & 511);
    float2 m = mv[b];
    float v = (x[idx]-m.x)*m.y*g[d] + be[d];
    if (SILU_) v = v*sigm(v);
    y[idx]=v;
}

// ---------------- GLU / depthwise conv ----------------
__global__ void glu_k(const float* __restrict__ in, float* __restrict__ out){
    size_t idx = (size_t)blockIdx.x*256 + threadIdx.x; // 2M
    size_t row = idx >> 9; int c = (int)(idx & 511);
    float a  = in[row*1024 + c];
    float bb = in[row*1024 + 512 + c];
    out[idx] = a * sigm(bb);
}
__global__ void dwconv_k(const float* __restrict__ in, const float* __restrict__ w,
                         const float* __restrict__ bias, float* __restrict__ out){
    int d = threadIdx.x;               // 512
    int t = blockIdx.x & 1023;
    int b = blockIdx.x >> 10;
    const float* base = in + (size_t)b*1024*512 + d;
    float acc = bias[d];
    #pragma unroll
    for (int k=0;k<31;k++){
        int tt = t + k - 15;
        if (tt >= 0 && tt < 1024)
            acc = fmaf(base[(size_t)tt*512], w[d*31+k], acc);
    }
    out[((size_t)b*1024 + t)*512 + d] = acc;
}

// ---------------- launch ----------------
extern "C" void kernel_launch(void* const* d_in, const int* in_sizes, int n_in,
                              void* d_out, int out_size) {
    const float* x      = (const float*)d_in[0];
    const float* ff1_w1 = (const float*)d_in[1];
    const float* ff1_b1 = (const float*)d_in[2];
    const float* ff1_w2 = (const float*)d_in[3];
    const float* ff1_b2 = (const float*)d_in[4];
    const float* qkv_w  = (const float*)d_in[5];
    const float* qkv_b  = (const float*)d_in[6];
    const float* out_w  = (const float*)d_in[7];
    const float* out_b  = (const float*)d_in[8];
    const float* gn1_g  = (const float*)d_in[9];
    const float* gn1_b  = (const float*)d_in[10];
    const float* pw1_w  = (const float*)d_in[11];
    const float* pw1_b  = (const float*)d_in[12];
    const float* dw_w   = (const float*)d_in[13];
    const float* dw_b   = (const float*)d_in[14];
    const float* gn2_g  = (const float*)d_in[15];
    const float* gn2_b  = (const float*)d_in[16];
    const float* pw2_w  = (const float*)d_in[17];
    const float* pw2_b  = (const float*)d_in[18];
    const float* ff2_w1 = (const float*)d_in[19];
    const float* ff2_b1 = (const float*)d_in[20];
    const float* ff2_w2 = (const float*)d_in[21];
    const float* ff2_b2 = (const float*)d_in[22];
    const float* rel_e  = (const float*)d_in[23];
    const float* gate_u = (const float*)d_in[24];
    const float* gate_w = (const float*)d_in[25];
    const float* gate_s = (const float*)d_in[26];

    float *S, *T1, *T2, *T3, *DDp; float2 *PART, *MV;
    cudaGetSymbolAddress((void**)&S,  g_S);
    cudaGetSymbolAddress((void**)&T1, g_T1);
    cudaGetSymbolAddress((void**)&T2, g_T2);
    cudaGetSymbolAddress((void**)&T3, g_T3);
    cudaGetSymbolAddress((void**)&DDp,g_DD);
    cudaGetSymbolAddress((void**)&PART, g_part);
    cudaGetSymbolAddress((void**)&MV,   g_mv);

    const int FLASH_SMEM = (4096*3 + 64) * 4;  // 49408 B
    cudaFuncSetAttribute((const void*)flash_attn_k,
                         cudaFuncAttributeMaxDynamicSharedMemorySize, FLASH_SMEM);

    dim3 tb(32,8);
    // x -> s [B,T,D]
    transpose_bdt_btd<<<dim3(32,16,4), tb>>>(x, S);
    build_dd_k<<<64,256>>>(rel_e, DDp);
    // FFN1 (half-step)
    sgemm_k<true ,false><<<dim3(16,32),256>>>(S,  ff1_w1, ff1_b1, nullptr, T1, 4096,2048, 512, 0.f);
    sgemm_k<false,true ><<<dim3( 4,32),256>>>(T1, ff1_w2, ff1_b2, S,       S,  4096, 512,2048, 0.5f);
    // QKV
    sgemm_k<false,false><<<dim3(12,32),256>>>(S,  qkv_w,  qkv_b,  nullptr, T1, 4096,1536, 512, 0.f);
    // attention
    flash_attn_k<<<dim3(16,8,4),256,FLASH_SMEM>>>(T1, gate_u, gate_w, gate_s, DDp, T2);
    sgemm_k<false,true ><<<dim3( 4,32),256>>>(T2, out_w,  out_b,  S,       S,  4096, 512, 512, 1.0f);
    // conv module
    gn_partial_k<<<1024,256>>>(S, PART);
    gn_final_k<<<4,256>>>(PART, MV);
    gn_apply_k<false><<<8192,256>>>(S, MV, gn1_g, gn1_b, T2);
    sgemm_k<false,false><<<dim3( 8,32),256>>>(T2, pw1_w,  pw1_b,  nullptr, T1, 4096,1024, 512, 0.f);
    glu_k<<<8192,256>>>(T1, T3);
    dwconv_k<<<4096,512>>>(T3, dw_w, dw_b, T2);
    gn_partial_k<<<1024,256>>>(T2, PART);
    gn_final_k<<<4,256>>>(PART, MV);
    gn_apply_k<true><<<8192,256>>>(T2, MV, gn2_g, gn2_b, T3);
    sgemm_k<false,true ><<<dim3( 4,32),256>>>(T3, pw2_w,  pw2_b,  S,       S,  4096, 512, 512, 1.0f);
    // FFN2 (half-step)
    sgemm_k<true ,false><<<dim3(16,32),256>>>(S,  ff2_w1, ff2_b1, nullptr, T1, 4096,2048, 512, 0.f);
    sgemm_k<false,true ><<<dim3( 4,32),256>>>(T1, ff2_w2, ff2_b2, S,       S,  4096, 512,2048, 0.5f);
    // s -> out [B,D,T]
    transpose_btd_bdt<<<dim3(16,32,4), tb>>>(S, (float*)d_out);
}

// round 3
// speedup vs baseline: 1.8504x; 1.8504x over previous
#include <cuda_runtime.h>
#include <math.h>
#include <cstdint>

// ---------------- scratch (device globals; allocation-free rule) ----------------
__device__ float  g_S [4096*512];    // residual stream, [B,T,D]
__device__ float  g_T1[4096*2048];   // ffn hidden / qkv / pw1 out
__device__ float  g_T2[4096*512];
__device__ float  g_T3[4096*512];
__device__ float  g_DD[8*2047];      // rel-pos bias table [h][rel+1023]
__device__ float2 g_part[1024];      // groupnorm partials
__device__ float2 g_mv[4];           // (mean, inv_std) per batch

__device__ __forceinline__ float gelu_f(float x){
    return 0.5f * x * (1.0f + erff(x * 0.70710678118654752440f));
}
__device__ __forceinline__ float sigm(float x){ return 1.0f/(1.0f + expf(-x)); }

// ---------------- async-copy helpers (sm_80+, non-arch-specific) ----------------
__device__ __forceinline__ void cpasync16(uint32_t dst, const void* src){
    asm volatile("cp.async.ca.shared.global [%0], [%1], 16;" :: "r"(dst), "l"(src));
}
#define CP_COMMIT() asm volatile("cp.async.commit_group;" ::: "memory")
template<int N>
__device__ __forceinline__ void cp_wait(){
    asm volatile("cp.async.wait_group %0;" :: "n"(N) : "memory");
}

// tf32 warp MMA: D(16x8) += A(16x8) * B(8x8). Raw fp32 regs (HW truncates to tf32).
__device__ __forceinline__ void mma8(float* c, const float* a, float b0, float b1){
    asm volatile(
        "mma.sync.aligned.m16n8k8.row.col.f32.tf32.tf32.f32 "
        "{%0,%1,%2,%3},{%4,%5,%6,%7},{%8,%9},{%0,%1,%2,%3};"
        : "+f"(c[0]), "+f"(c[1]), "+f"(c[2]), "+f"(c[3])
        : "r"(__float_as_uint(a[0])), "r"(__float_as_uint(a[1])),
          "r"(__float_as_uint(a[2])), "r"(__float_as_uint(a[3])),
          "r"(__float_as_uint(b0)),   "r"(__float_as_uint(b1)));
}

// ---------------- tensor-core tf32 GEMM: C = epi(A[MxK] @ B[KxN] + bias) -------
// CTA 128 x TN, 256 threads (8 warps: 2 row x 4 col), warp tile 64 x TN/4.
// K staged by 32 (4 mma k-steps), double-buffered cp.async pipeline.
// A smem [128][36] (pad), B smem [32][264] (pad) -> conflict-free frag reads.
template<int TN, bool GELU_, bool RES_>
__global__ void __launch_bounds__(256,1) mma_gemm_k(
    const float* __restrict__ A, const float* __restrict__ B,
    const float* __restrict__ bias, const float* __restrict__ res,
    float* __restrict__ C, int M, int N, int Kd, float rscale)
{
    constexpr int WN   = TN/4;        // warp tile N
    constexpr int NJ   = WN/8;        // n-atoms per warp
    constexpr int ASZ  = 128*36;      // floats per A buffer
    constexpr int BSZ  = 32*264;      // floats per B buffer
    constexpr int NSEG = TN/4;        // 16B segments per B row

    extern __shared__ __align__(16) float smem[];
    float* As = smem;                 // [2][128][36]
    float* Bs = smem + 2*ASZ;         // [2][32][264]

    int tid = threadIdx.x, lane = tid & 31, wid = tid >> 5;
    int wr = wid >> 2, wc = wid & 3;
    int g = lane >> 2, tg = lane & 3;
    int row0 = blockIdx.y*128, col0 = blockIdx.x*TN;

    const float* Ag = A + (size_t)row0*Kd;
    const float* Bg = B + col0;
    uint32_t sA = (uint32_t)__cvta_generic_to_shared(As);
    uint32_t sB = (uint32_t)__cvta_generic_to_shared(Bs);

    auto loadA = [&](int kt, int buf){
        int k0 = kt*32;
        uint32_t base = sA + buf*(ASZ*4);
        #pragma unroll
        for (int i = 0; i < 4; i++){
            int f = tid + i*256;
            int m = f >> 3, seg = f & 7;
            cpasync16(base + (uint32_t)(m*144 + seg*16),
                      Ag + (size_t)m*Kd + k0 + seg*4);
        }
    };
    auto loadB = [&](int kt, int buf){
        int k0 = kt*32;
        uint32_t base = sB + buf*(BSZ*4);
        #pragma unroll
        for (int i = 0; i < (32*NSEG)/256; i++){
            int f = tid + i*256;
            int k = f / NSEG, s = f % NSEG;
            cpasync16(base + (uint32_t)(k*1056 + s*16),
                      Bg + (size_t)(k0+k)*N + s*4);
        }
    };

    float acc[4][NJ][4];
    #pragma unroll
    for (int mi=0;mi<4;mi++)
        #pragma unroll
        for (int nj=0;nj<NJ;nj++)
            #pragma unroll
            for (int q=0;q<4;q++) acc[mi][nj][q]=0.f;

    int nk = Kd >> 5;
    loadA(0,0); loadB(0,0); CP_COMMIT();
    if (nk > 1){ loadA(1,1); loadB(1,1); CP_COMMIT(); }

    for (int kt = 0; kt < nk; ++kt){
        int buf = kt & 1;
        if (kt + 1 < nk) cp_wait<1>(); else cp_wait<0>();
        __syncthreads();

        const float* Ab = As + buf*ASZ + (wr*64)*36;
        const float* Bb = Bs + buf*BSZ + wc*WN;
        #pragma unroll
        for (int ks = 0; ks < 4; ++ks){
            int k0 = ks*8;
            float af[4][4];
            #pragma unroll
            for (int mi=0;mi<4;mi++){
                const float* ap = Ab + (mi*16 + g)*36 + k0 + tg;
                af[mi][0] = ap[0];
                af[mi][1] = ap[8*36];
                af[mi][2] = ap[4];
                af[mi][3] = ap[8*36 + 4];
            }
            #pragma unroll
            for (int nj=0;nj<NJ;nj++){
                float b0 = Bb[(k0+tg)*264   + nj*8 + g];
                float b1 = Bb[(k0+tg+4)*264 + nj*8 + g];
                #pragma unroll
                for (int mi=0;mi<4;mi++)
                    mma8(acc[mi][nj], af[mi], b0, b1);
            }
        }
        __syncthreads();
        if (kt + 2 < nk){ loadA(kt+2, buf); loadB(kt+2, buf); CP_COMMIT(); }
    }

    // epilogue
    #pragma unroll
    for (int nj=0;nj<NJ;nj++){
        int c = col0 + wc*WN + nj*8 + tg*2;
        float2 bi = *(const float2*)&bias[c];
        #pragma unroll
        for (int mi=0;mi<4;mi++){
            int r0 = row0 + wr*64 + mi*16 + g;
            float v0 = acc[mi][nj][0] + bi.x;
            float v1 = acc[mi][nj][1] + bi.y;
            float v2 = acc[mi][nj][2] + bi.x;
            float v3 = acc[mi][nj][3] + bi.y;
            if (GELU_){ v0=gelu_f(v0); v1=gelu_f(v1); v2=gelu_f(v2); v3=gelu_f(v3); }
            if (RES_){
                float2 r0v = *(const float2*)&res[(size_t)r0*N + c];
                float2 r1v = *(const float2*)&res[(size_t)(r0+8)*N + c];
                v0 = fmaf(rscale, v0, r0v.x); v1 = fmaf(rscale, v1, r0v.y);
                v2 = fmaf(rscale, v2, r1v.x); v3 = fmaf(rscale, v3, r1v.y);
            }
            *(float2*)&C[(size_t)r0*N + c]     = make_float2(v0, v1);
            *(float2*)&C[(size_t)(r0+8)*N + c] = make_float2(v2, v3);
        }
    }
}

// ---------------- transposes ----------------
__global__ void transpose_bdt_btd(const float* __restrict__ in, float* __restrict__ out){
    __shared__ float tile[32][33];
    int b = blockIdx.z;
    int t0 = blockIdx.x*32, d0 = blockIdx.y*32;
    int lx = threadIdx.x, ly = threadIdx.y;
    #pragma unroll
    for (int i=0;i<32;i+=8)
        tile[ly+i][lx] = in[((size_t)b*512 + d0+ly+i)*1024 + t0 + lx];
    __syncthreads();
    #pragma unroll
    for (int i=0;i<32;i+=8)
        out[((size_t)b*1024 + t0+ly+i)*512 + d0 + lx] = tile[lx][ly+i];
}
__global__ void transpose_btd_bdt(const float* __restrict__ in, float* __restrict__ out){
    __shared__ float tile[32][33];
    int b = blockIdx.z;
    int d0 = blockIdx.x*32, t0 = blockIdx.y*32;
    int lx = threadIdx.x, ly = threadIdx.y;
    #pragma unroll
    for (int i=0;i<32;i+=8)
        tile[ly+i][lx] = in[((size_t)b*1024 + t0+ly+i)*512 + d0 + lx];
    __syncthreads();
    #pragma unroll
    for (int i=0;i<32;i+=8)
        out[((size_t)b*512 + d0+ly+i)*1024 + t0 + lx] = tile[lx][ly+i];
}

// ---------------- relative-position bias table ----------------
__global__ void build_dd_k(const float* __restrict__ rel_embed, float* __restrict__ ddt){
    int idx = blockIdx.x*256 + threadIdx.x;
    if (idx >= 8*2047) return;
    int h = idx / 2047;
    int rpos = idx % 2047;
    int rel = rpos - 1023;
    int sign = (rel >= 0) ? 1 : 0;
    int a = (rel >= 0) ? rel : -rel;
    int bucket;
    if (a < 80) bucket = a;
    else {
        float lr = logf((float)a / 80.0f) / logf(10.0f);
        int lp = 80 + (int)(lr * 80.0f);
        bucket = (lp < 159) ? lp : 159;
    }
    bucket += sign*160;
    if (bucket < 0) bucket = 0;
    if (bucket > 319) bucket = 319;
    ddt[h*2047 + rpos] = rel_embed[bucket*8 + h];
}

// ---------------- flash attention with gated rel-pos bias ----------------
__global__ void __launch_bounds__(256) flash_attn_k(
    const float* __restrict__ qkv,     // [B,T,3,H,DH] = row stride 1536
    const float* __restrict__ gate_u, const float* __restrict__ gate_w,
    const float* __restrict__ gate_scale, const float* __restrict__ ddt,
    float* __restrict__ out)           // [B,T,512]
{
    extern __shared__ float sm[];
    float* Qt    = sm;            // [64 d][64 m]
    float* KP    = sm + 4096;     // Kt [64 d][64 n], reused as Pt [64 n][64 m]
    float* Vs    = sm + 8192;     // [64 n][64 d]
    float* coefs = sm + 12288;    // [64]

    int tid = threadIdx.x;
    int tx = tid & 15, ty = tid >> 4;
    int t0 = blockIdx.x * 64;
    int h  = blockIdx.y;
    int b  = blockIdx.z;

    const float* qbase = qkv + (size_t)b*1024*1536 + h*64;
    const float* kbase = qbase + 512;
    const float* vbase = qbase + 1024;

    { // load Q transposed: Qt[d][m]
        int m  = tid >> 2;
        int dg = (tid & 3) * 16;
        const float* qrow = qbase + (size_t)(t0+m)*1536 + dg;
        #pragma unroll
        for (int i=0;i<4;i++){
            float4 v = *(const float4*)(qrow + i*4);
            int d = dg + i*4;
            Qt[(d+0)*64+m]=v.x; Qt[(d+1)*64+m]=v.y; Qt[(d+2)*64+m]=v.z; Qt[(d+3)*64+m]=v.w;
        }
    }
    if (tid < 64){
        const float* qrow = qbase + (size_t)(t0+tid)*1536;
        float du=0.f, dw=0.f;
        #pragma unroll
        for (int d=0; d<64; d++){
            float qv = qrow[d];
            du = fmaf(qv, gate_u[h*64+d], du);
            dw = fmaf(qv, gate_w[h*64+d], dw);
        }
        float gu = sigm(du), gr = sigm(dw);
        coefs[tid] = 1.0f + gu + (1.0f-gu)*gate_scale[h]*gr;
    }

    float m_run[4], l_run[4], O[4][4];
    #pragma unroll
    for (int i=0;i<4;i++){
        m_run[i] = -3.0e38f; l_run[i] = 0.f;
        #pragma unroll
        for (int j=0;j<4;j++) O[i][j]=0.f;
    }

    for (int s0=0; s0<1024; s0+=64){
        {
            int m  = tid >> 2;
            int dg = (tid & 3)*16;
            const float* krow = kbase + (size_t)(s0+m)*1536 + dg;
            const float* vrow = vbase + (size_t)(s0+m)*1536 + dg;
            #pragma unroll
            for (int i=0;i<4;i++){
                float4 kv = *(const float4*)(krow + i*4);
                int d = dg + i*4;
                KP[(d+0)*64+m]=kv.x; KP[(d+1)*64+m]=kv.y; KP[(d+2)*64+m]=kv.z; KP[(d+3)*64+m]=kv.w;
                *(float4*)&Vs[m*64 + dg + i*4] = *(const float4*)(vrow + i*4);
            }
        }
        float ddr[7];
        {
            int bi = h*2047 + 1023 + (s0 - t0) + (tx - ty)*4 - 3;
            #pragma unroll
            for (int k=0;k<7;k++) ddr[k] = ddt[bi+k];
        }
        __syncthreads();

        float S[4][4];
        #pragma unroll
        for (int i=0;i<4;i++)
            #pragma unroll
            for (int j=0;j<4;j++) S[i][j]=0.f;
        #pragma unroll 8
        for (int d=0; d<64; d++){
            float4 a4 = *(const float4*)&Qt[d*64 + ty*4];
            float4 b4 = *(const float4*)&KP[d*64 + tx*4];
            float a[4]={a4.x,a4.y,a4.z,a4.w}, bb[4]={b4.x,b4.y,b4.z,b4.w};
            #pragma unroll
            for (int i=0;i<4;i++)
                #pragma unroll
                for (int j=0;j<4;j++) S[i][j] = fmaf(a[i], bb[j], S[i][j]);
        }
        float cf[4];
        #pragma unroll
        for (int i=0;i<4;i++) cf[i] = coefs[ty*4+i];
        #pragma unroll
        for (int i=0;i<4;i++)
            #pragma unroll
            for (int j=0;j<4;j++)
                S[i][j] = fmaf(S[i][j], 0.125f, cf[i]*ddr[3 + j - i]);

        #pragma unroll
        for (int i=0;i<4;i++){
            float mn = fmaxf(fmaxf(S[i][0],S[i][1]), fmaxf(S[i][2],S[i][3]));
            mn = fmaxf(mn, __shfl_xor_sync(0xffffffffu, mn, 1));
            mn = fmaxf(mn, __shfl_xor_sync(0xffffffffu, mn, 2));
            mn = fmaxf(mn, __shfl_xor_sync(0xffffffffu, mn, 4));
            mn = fmaxf(mn, __shfl_xor_sync(0xffffffffu, mn, 8));
            float mo = fmaxf(m_run[i], mn);
            float alpha = expf(m_run[i] - mo);
            m_run[i] = mo;
            float ls = 0.f;
            #pragma unroll
            for (int j=0;j<4;j++){ float p = expf(S[i][j]-mo); S[i][j]=p; ls += p; }
            ls += __shfl_xor_sync(0xffffffffu, ls, 1);
            ls += __shfl_xor_sync(0xffffffffu, ls, 2);
            ls += __shfl_xor_sync(0xffffffffu, ls, 4);
            ls += __shfl_xor_sync(0xffffffffu, ls, 8);
            l_run[i] = l_run[i]*alpha + ls;
            #pragma unroll
            for (int j=0;j<4;j++) O[i][j] *= alpha;
        }

        __syncthreads();
        #pragma unroll
        for (int i=0;i<4;i++)
            #pragma unroll
            for (int j=0;j<4;j++)
                KP[(tx*4+j)*64 + ty*4+i] = S[i][j];
        __syncthreads();

        #pragma unroll 8
        for (int n=0;n<64;n++){
            float4 a4 = *(const float4*)&KP[n*64 + ty*4];
            float4 b4 = *(const float4*)&Vs[n*64 + tx*4];
            float a[4]={a4.x,a4.y,a4.z,a4.w}, bb[4]={b4.x,b4.y,b4.z,b4.w};
            #pragma unroll
            for (int i=0;i<4;i++)
                #pragma unroll
                for (int j=0;j<4;j++) O[i][j] = fmaf(a[i], bb[j], O[i][j]);
        }
        __syncthreads();
    }
    #pragma unroll
    for (int i=0;i<4;i++){
        float inv = 1.0f / l_run[i];
        int t = t0 + ty*4 + i;
        float4 o4 = make_float4(O[i][0]*inv, O[i][1]*inv, O[i][2]*inv, O[i][3]*inv);
        *(float4*)&out[((size_t)(b*1024+t))*512 + h*64 + tx*4] = o4;
    }
}

// ---------------- GroupNorm(1, C) over [B,T,D]: deterministic 2-level reduction ----
__global__ void gn_partial_k(const float* __restrict__ x, float2* __restrict__ part){
    int b = blockIdx.x >> 8;
    int blk = blockIdx.x & 255;
    const float* p = x + (size_t)b*524288 + (size_t)blk*2048;
    float s=0.f, q=0.f;
    for (int i=threadIdx.x; i<2048; i+=256){ float v=p[i]; s+=v; q=fmaf(v,v,q); }
    __shared__ float ss[256], sq[256];
    ss[threadIdx.x]=s; sq[threadIdx.x]=q;
    __syncthreads();
    for (int o=128;o>0;o>>=1){
        if (threadIdx.x<o){ ss[threadIdx.x]+=ss[threadIdx.x+o]; sq[threadIdx.x]+=sq[threadIdx.x+o]; }
        __syncthreads();
    }
    if (threadIdx.x==0) part[blockIdx.x] = make_float2(ss[0], sq[0]);
}
__global__ void gn_final_k(const float2* __restrict__ part, float2* __restrict__ mv){
    int b = blockIdx.x;
    float2 v = part[b*256 + threadIdx.x];
    __shared__ float ss[256], sq[256];
    ss[threadIdx.x]=v.x; sq[threadIdx.x]=v.y;
    __syncthreads();
    for (int o=128;o>0;o>>=1){
        if (threadIdx.x<o){ ss[threadIdx.x]+=ss[threadIdx.x+o]; sq[threadIdx.x]+=sq[threadIdx.x+o]; }
        __syncthreads();
    }
    if (threadIdx.x==0){
        float mean = ss[0]*(1.0f/524288.0f);
        float var  = sq[0]*(1.0f/524288.0f) - mean*mean;
        mv[b] = make_float2(mean, rsqrtf(var + 1e-5f));
    }
}
template<bool SILU_>
__global__ void gn_apply_k(const float* __restrict__ x, const float2* __restrict__ mv,
                           const float* __restrict__ g, const float* __restrict__ be,
                           float* __restrict__ y){
    size_t idx = (size_t)blockIdx.x*256 + threadIdx.x;
    int b = (int)(idx >> 19);
    int d = (int)(idx & 511);
    float2 m = mv[b];
    float v = (x[idx]-m.x)*m.y*g[d] + be[d];
    if (SILU_) v = v*sigm(v);
    y[idx]=v;
}

// ---------------- GLU / depthwise conv ----------------
__global__ void glu_k(const float* __restrict__ in, float* __restrict__ out){
    size_t idx = (size_t)blockIdx.x*256 + threadIdx.x;
    size_t row = idx >> 9; int c = (int)(idx & 511);
    float a  = in[row*1024 + c];
    float bb = in[row*1024 + 512 + c];
    out[idx] = a * sigm(bb);
}
__global__ void dwconv_k(const float* __restrict__ in, const float* __restrict__ w,
                         const float* __restrict__ bias, float* __restrict__ out){
    int d = threadIdx.x;               // 512
    int t = blockIdx.x & 1023;
    int b = blockIdx.x >> 10;
    const float* base = in + (size_t)b*1024*512 + d;
    float acc = bias[d];
    #pragma unroll
    for (int k=0;k<31;k++){
        int tt = t + k - 15;
        if (tt >= 0 && tt < 1024)
            acc = fmaf(base[(size_t)tt*512], w[d*31+k], acc);
    }
    out[((size_t)b*1024 + t)*512 + d] = acc;
}

// ---------------- launch ----------------
extern "C" void kernel_launch(void* const* d_in, const int* in_sizes, int n_in,
                              void* d_out, int out_size) {
    const float* x      = (const float*)d_in[0];
    const float* ff1_w1 = (const float*)d_in[1];
    const float* ff1_b1 = (const float*)d_in[2];
    const float* ff1_w2 = (const float*)d_in[3];
    const float* ff1_b2 = (const float*)d_in[4];
    const float* qkv_w  = (const float*)d_in[5];
    const float* qkv_b  = (const float*)d_in[6];
    const float* out_w  = (const float*)d_in[7];
    const float* out_b  = (const float*)d_in[8];
    const float* gn1_g  = (const float*)d_in[9];
    const float* gn1_b  = (const float*)d_in[10];
    const float* pw1_w  = (const float*)d_in[11];
    const float* pw1_b  = (const float*)d_in[12];
    const float* dw_w   = (const float*)d_in[13];
    const float* dw_b   = (const float*)d_in[14];
    const float* gn2_g  = (const float*)d_in[15];
    const float* gn2_b  = (const float*)d_in[16];
    const float* pw2_w  = (const float*)d_in[17];
    const float* pw2_b  = (const float*)d_in[18];
    const float* ff2_w1 = (const float*)d_in[19];
    const float* ff2_b1 = (const float*)d_in[20];
    const float* ff2_w2 = (const float*)d_in[21];
    const float* ff2_b2 = (const float*)d_in[22];
    const float* rel_e  = (const float*)d_in[23];
    const float* gate_u = (const float*)d_in[24];
    const float* gate_w = (const float*)d_in[25];
    const float* gate_s = (const float*)d_in[26];

    float *S, *T1, *T2, *T3, *DDp; float2 *PART, *MV;
    cudaGetSymbolAddress((void**)&S,  g_S);
    cudaGetSymbolAddress((void**)&T1, g_T1);
    cudaGetSymbolAddress((void**)&T2, g_T2);
    cudaGetSymbolAddress((void**)&T3, g_T3);
    cudaGetSymbolAddress((void**)&DDp,g_DD);
    cudaGetSymbolAddress((void**)&PART, g_part);
    cudaGetSymbolAddress((void**)&MV,   g_mv);

    const int FLASH_SMEM = (4096*3 + 64) * 4;
    cudaFuncSetAttribute((const void*)flash_attn_k,
                         cudaFuncAttributeMaxDynamicSharedMemorySize, FLASH_SMEM);
    const int GSMEM = (2*128*36 + 2*32*264) * 4;   // 104448 B (same for both TN)
    cudaFuncSetAttribute(mma_gemm_k<256,true ,false>, cudaFuncAttributeMaxDynamicSharedMemorySize, GSMEM);
    cudaFuncSetAttribute(mma_gemm_k<256,false,false>, cudaFuncAttributeMaxDynamicSharedMemorySize, GSMEM);
    cudaFuncSetAttribute(mma_gemm_k<128,false,true >, cudaFuncAttributeMaxDynamicSharedMemorySize, GSMEM);

    dim3 tb(32,8);
    // x -> s [B,T,D]
    transpose_bdt_btd<<<dim3(32,16,4), tb>>>(x, S);
    build_dd_k<<<64,256>>>(rel_e, DDp);
    // FFN1 (half-step)
    mma_gemm_k<256,true ,false><<<dim3( 8,32),256,GSMEM>>>(S,  ff1_w1, ff1_b1, nullptr, T1, 4096,2048, 512, 0.f);
    mma_gemm_k<128,false,true ><<<dim3( 4,32),256,GSMEM>>>(T1, ff1_w2, ff1_b2, S,       S,  4096, 512,2048, 0.5f);
    // QKV
    mma_gemm_k<256,false,false><<<dim3( 6,32),256,GSMEM>>>(S,  qkv_w,  qkv_b,  nullptr, T1, 4096,1536, 512, 0.f);
    // attention
    flash_attn_k<<<dim3(16,8,4),256,FLASH_SMEM>>>(T1, gate_u, gate_w, gate_s, DDp, T2);
    mma_gemm_k<128,false,true ><<<dim3( 4,32),256,GSMEM>>>(T2, out_w,  out_b,  S,       S,  4096, 512, 512, 1.0f);
    // conv module
    gn_partial_k<<<1024,256>>>(S, PART);
    gn_final_k<<<4,256>>>(PART, MV);
    gn_apply_k<false><<<8192,256>>>(S, MV, gn1_g, gn1_b, T2);
    mma_gemm_k<256,false,false><<<dim3( 4,32),256,GSMEM>>>(T2, pw1_w,  pw1_b,  nullptr, T1, 4096,1024, 512, 0.f);
    glu_k<<<8192,256>>>(T1, T3);
    dwconv_k<<<4096,512>>>(T3, dw_w, dw_b, T2);
    gn_partial_k<<<1024,256>>>(T2, PART);
    gn_final_k<<<4,256>>>(PART, MV);
    gn_apply_k<true><<<8192,256>>>(T2, MV, gn2_g, gn2_b, T3);
    mma_gemm_k<128,false,true ><<<dim3( 4,32),256,GSMEM>>>(T3, pw2_w,  pw2_b,  S,       S,  4096, 512, 512, 1.0f);
    // FFN2 (half-step)
    mma_gemm_k<256,true ,false><<<dim3( 8,32),256,GSMEM>>>(S,  ff2_w1, ff2_b1, nullptr, T1, 4096,2048, 512, 0.f);
    mma_gemm_k<128,false,true ><<<dim3( 4,32),256,GSMEM>>>(T1, ff2_w2, ff2_b2, S,       S,  4096, 512,2048, 0.5f);
    // s -> out [B,D,T]
    transpose_btd_bdt<<<dim3(16,32,4), tb>>>(S, (float*)d_out);
}

// round 4
// speedup vs baseline: 2.0673x; 1.1172x over previous
#include <cuda_runtime.h>
#include <math.h>
#include <cstdint>

// ---------------- scratch (device globals; allocation-free rule) ----------------
__device__ float  g_S [4096*512];    // residual stream, [B,T,D]
__device__ float  g_T1[4096*2048];   // ffn hidden / qkv / pw1 out
__device__ float  g_T2[4096*512];
__device__ float  g_T3[4096*512];
__device__ float  g_DD[8*2047];      // rel-pos bias table [h][rel+1023]
__device__ float2 g_part[1024];      // groupnorm partials
__device__ float2 g_mv[4];           // (mean, inv_std) per batch

__device__ __forceinline__ float gelu_f(float x){
    return 0.5f * x * (1.0f + erff(x * 0.70710678118654752440f));
}
__device__ __forceinline__ float sigm(float x){ return 1.0f/(1.0f + expf(-x)); }

// ---------------- async-copy helpers ----------------
__device__ __forceinline__ void cpasync16(uint32_t dst, const void* src){
    asm volatile("cp.async.ca.shared.global [%0], [%1], 16;" :: "r"(dst), "l"(src));
}
#define CP_COMMIT() asm volatile("cp.async.commit_group;" ::: "memory")
template<int N>
__device__ __forceinline__ void cp_wait(){
    asm volatile("cp.async.wait_group %0;" :: "n"(N) : "memory");
}

// tf32 warp MMA: D(16x8) += A(16x8) * B(8x8). Raw fp32 regs (HW truncates to tf32).
__device__ __forceinline__ void mma8(float* c, const float* a, float b0, float b1){
    asm volatile(
        "mma.sync.aligned.m16n8k8.row.col.f32.tf32.tf32.f32 "
        "{%0,%1,%2,%3},{%4,%5,%6,%7},{%8,%9},{%0,%1,%2,%3};"
        : "+f"(c[0]), "+f"(c[1]), "+f"(c[2]), "+f"(c[3])
        : "r"(__float_as_uint(a[0])), "r"(__float_as_uint(a[1])),
          "r"(__float_as_uint(a[2])), "r"(__float_as_uint(a[3])),
          "r"(__float_as_uint(b0)),   "r"(__float_as_uint(b1)));
}

// ---------------- tensor-core tf32 GEMM: C = epi(A[MxK] @ B[KxN] + bias) -------
// CTA 128 x TN, 256 threads (8 warps: 2 row x 4 col), warp tile 64 x TN/4.
// K staged by 32 (4 mma k-steps), 4-stage cp.async pipeline (prefetch dist 3).
template<int TN, bool GELU_, bool RES_>
__global__ void __launch_bounds__(256,1) mma_gemm_k(
    const float* __restrict__ A, const float* __restrict__ B,
    const float* __restrict__ bias, const float* __restrict__ res,
    float* __restrict__ C, int M, int N, int Kd, float rscale)
{
    constexpr int WN   = TN/4;
    constexpr int NJ   = WN/8;
    constexpr int BROW = TN + 8;      // row stride (mod 32 == 8 -> conflict-free frags)
    constexpr int ASZ  = 128*36;
    constexpr int BSZ  = 32*BROW;
    constexpr int NSEG = TN/4;

    extern __shared__ __align__(16) float smem[];
    float* As = smem;                 // [4][128][36]
    float* Bs = smem + 4*ASZ;         // [4][32][BROW]

    int tid = threadIdx.x, lane = tid & 31, wid = tid >> 5;
    int wr = wid >> 2, wc = wid & 3;
    int g = lane >> 2, tg = lane & 3;
    int row0 = blockIdx.y*128, col0 = blockIdx.x*TN;

    const float* Ag = A + (size_t)row0*Kd;
    const float* Bg = B + col0;
    uint32_t sA = (uint32_t)__cvta_generic_to_shared(As);
    uint32_t sB = (uint32_t)__cvta_generic_to_shared(Bs);

    auto loadA = [&](int kt){
        int k0 = kt*32;
        uint32_t base = sA + (kt & 3)*(ASZ*4);
        #pragma unroll
        for (int i = 0; i < 4; i++){
            int f = tid + i*256;
            int m = f >> 3, seg = f & 7;
            cpasync16(base + (uint32_t)(m*144 + seg*16),
                      Ag + (size_t)m*Kd + k0 + seg*4);
        }
    };
    auto loadB = [&](int kt){
        int k0 = kt*32;
        uint32_t base = sB + (kt & 3)*(BSZ*4);
        #pragma unroll
        for (int i = 0; i < (32*NSEG)/256; i++){
            int f = tid + i*256;
            int k = f / NSEG, s = f % NSEG;
            cpasync16(base + (uint32_t)(k*(BROW*4) + s*16),
                      Bg + (size_t)(k0+k)*N + s*4);
        }
    };

    float acc[4][NJ][4];
    #pragma unroll
    for (int mi=0;mi<4;mi++)
        #pragma unroll
        for (int nj=0;nj<NJ;nj++)
            #pragma unroll
            for (int q=0;q<4;q++) acc[mi][nj][q]=0.f;

    int nk = Kd >> 5;                 // all Kd here give nk >= 16
    loadA(0); loadB(0); CP_COMMIT();
    loadA(1); loadB(1); CP_COMMIT();
    loadA(2); loadB(2); CP_COMMIT();

    for (int kt = 0; kt < nk; ++kt){
        cp_wait<2>();
        __syncthreads();              // stage kt ready; all warps done with kt-1
        if (kt + 3 < nk){ loadA(kt+3); loadB(kt+3); }
        CP_COMMIT();

        int buf = kt & 3;
        const float* Ab = As + buf*ASZ + (wr*64)*36;
        const float* Bb = Bs + buf*BSZ + wc*WN;
        #pragma unroll
        for (int ks = 0; ks < 4; ++ks){
            int k0 = ks*8;
            float af[4][4];
            #pragma unroll
            for (int mi=0;mi<4;mi++){
                const float* ap = Ab + (mi*16 + g)*36 + k0 + tg;
                af[mi][0] = ap[0];
                af[mi][1] = ap[8*36];
                af[mi][2] = ap[4];
                af[mi][3] = ap[8*36 + 4];
            }
            #pragma unroll
            for (int nj=0;nj<NJ;nj++){
                float b0 = Bb[(k0+tg)*BROW   + nj*8 + g];
                float b1 = Bb[(k0+tg+4)*BROW + nj*8 + g];
                #pragma unroll
                for (int mi=0;mi<4;mi++)
                    mma8(acc[mi][nj], af[mi], b0, b1);
            }
        }
    }

    // epilogue
    #pragma unroll
    for (int nj=0;nj<NJ;nj++){
        int c = col0 + wc*WN + nj*8 + tg*2;
        float2 bi = *(const float2*)&bias[c];
        #pragma unroll
        for (int mi=0;mi<4;mi++){
            int r0 = row0 + wr*64 + mi*16 + g;
            float v0 = acc[mi][nj][0] + bi.x;
            float v1 = acc[mi][nj][1] + bi.y;
            float v2 = acc[mi][nj][2] + bi.x;
            float v3 = acc[mi][nj][3] + bi.y;
            if (GELU_){ v0=gelu_f(v0); v1=gelu_f(v1); v2=gelu_f(v2); v3=gelu_f(v3); }
            if (RES_){
                float2 r0v = *(const float2*)&res[(size_t)r0*N + c];
                float2 r1v = *(const float2*)&res[(size_t)(r0+8)*N + c];
                v0 = fmaf(rscale, v0, r0v.x); v1 = fmaf(rscale, v1, r0v.y);
                v2 = fmaf(rscale, v2, r1v.x); v3 = fmaf(rscale, v3, r1v.y);
            }
            *(float2*)&C[(size_t)r0*N + c]     = make_float2(v0, v1);
            *(float2*)&C[(size_t)(r0+8)*N + c] = make_float2(v2, v3);
        }
    }
}

// ---------------- transposes ----------------
__global__ void transpose_bdt_btd(const float* __restrict__ in, float* __restrict__ out){
    __shared__ float tile[32][33];
    int b = blockIdx.z;
    int t0 = blockIdx.x*32, d0 = blockIdx.y*32;
    int lx = threadIdx.x, ly = threadIdx.y;
    #pragma unroll
    for (int i=0;i<32;i+=8)
        tile[ly+i][lx] = in[((size_t)b*512 + d0+ly+i)*1024 + t0 + lx];
    __syncthreads();
    #pragma unroll
    for (int i=0;i<32;i+=8)
        out[((size_t)b*1024 + t0+ly+i)*512 + d0 + lx] = tile[lx][ly+i];
}
__global__ void transpose_btd_bdt(const float* __restrict__ in, float* __restrict__ out){
    __shared__ float tile[32][33];
    int b = blockIdx.z;
    int d0 = blockIdx.x*32, t0 = blockIdx.y*32;
    int lx = threadIdx.x, ly = threadIdx.y;
    #pragma unroll
    for (int i=0;i<32;i+=8)
        tile[ly+i][lx] = in[((size_t)b*1024 + t0+ly+i)*512 + d0 + lx];
    __syncthreads();
    #pragma unroll
    for (int i=0;i<32;i+=8)
        out[((size_t)b*512 + d0+ly+i)*1024 + t0 + lx] = tile[lx][ly+i];
}

// ---------------- relative-position bias table ----------------
__global__ void build_dd_k(const float* __restrict__ rel_embed, float* __restrict__ ddt){
    int idx = blockIdx.x*256 + threadIdx.x;
    if (idx >= 8*2047) return;
    int h = idx / 2047;
    int rpos = idx % 2047;
    int rel = rpos - 1023;
    int sign = (rel >= 0) ? 1 : 0;
    int a = (rel >= 0) ? rel : -rel;
    int bucket;
    if (a < 80) bucket = a;
    else {
        float lr = logf((float)a / 80.0f) / logf(10.0f);
        int lp = 80 + (int)(lr * 80.0f);
        bucket = (lp < 159) ? lp : 159;
    }
    bucket += sign*160;
    if (bucket < 0) bucket = 0;
    if (bucket > 319) bucket = 319;
    ddt[h*2047 + rpos] = rel_embed[bucket*8 + h];
}

// ---------------- tensor-core flash attention with gated rel-pos bias ----------
// probs = softmax_s( q.k/8 + coef[b,h,t] * dd[h, s-t] );  out[b,t,h,dh]
// 64 queries/block, 128 threads (4 warps x 16 rows), tf32 mma for QK^T and PV.
__global__ void __launch_bounds__(128) flash_mma_k(
    const float* __restrict__ qkv,     // [B,T,3,H,DH] row stride 1536
    const float* __restrict__ gate_u, const float* __restrict__ gate_w,
    const float* __restrict__ gate_scale, const float* __restrict__ ddt,
    float* __restrict__ out)           // [B,T,512]
{
    extern __shared__ float sm[];
    float* Qs    = sm;                 // [64][68]
    float* Ks    = Qs + 64*68;         // [64][72]  K transposed: Ks[d][s]
    float* Vs    = Ks + 64*72;         // [64][72]  Vs[s][d]
    float* Ps    = Vs + 64*72;         // [64][68]  probs row-major
    float* dds   = Ps + 64*68;         // [128]
    float* coefs = dds + 128;          // [64]

    int tid = threadIdx.x, lane = tid & 31, wid = tid >> 5;
    int g = lane >> 2, tg = lane & 3;
    int t0 = blockIdx.x * 64;
    int h  = blockIdx.y;
    int b  = blockIdx.z;
    int m0 = wid * 16;

    const float* qbase = qkv + (size_t)b*1024*1536 + h*64;
    const float* kbase = qbase + 512;
    const float* vbase = qbase + 1024;

    { // load Q tile -> smem
        int m = tid >> 1, half = (tid & 1) * 32;
        const float* qrow = qbase + (size_t)(t0+m)*1536 + half;
        #pragma unroll
        for (int i=0;i<8;i++)
            *(float4*)&Qs[m*68 + half + i*4] = *(const float4*)(qrow + i*4);
    }
    __syncthreads();
    if (tid < 64){ // per-query gate coefficient (from smem Q)
        float du=0.f, dw=0.f;
        #pragma unroll
        for (int d=0; d<64; d++){
            float qv = Qs[tid*68 + d];
            du = fmaf(qv, gate_u[h*64+d], du);
            dw = fmaf(qv, gate_w[h*64+d], dw);
        }
        float gu = sigm(du), gr = sigm(dw);
        coefs[tid] = 1.0f + gu + (1.0f-gu)*gate_scale[h]*gr;
    }
    // Q fragments (register-resident for whole kernel)
    float qf[8][4];
    #pragma unroll
    for (int ks=0;ks<8;ks++){
        qf[ks][0] = Qs[(m0+g  )*68 + ks*8 + tg];
        qf[ks][1] = Qs[(m0+g+8)*68 + ks*8 + tg];
        qf[ks][2] = Qs[(m0+g  )*68 + ks*8 + tg + 4];
        qf[ks][3] = Qs[(m0+g+8)*68 + ks*8 + tg + 4];
    }

    float m_run[2] = {-3.0e38f, -3.0e38f}, l_run[2] = {0.f, 0.f};
    float O[8][4];
    #pragma unroll
    for (int nd=0;nd<8;nd++)
        #pragma unroll
        for (int q=0;q<4;q++) O[nd][q]=0.f;

    for (int s0 = 0; s0 < 1024; s0 += 64){
        __syncthreads();  // prev-iter K/V reads done; coefs ready on iter 0
        { // load K transposed + V
            int m = tid >> 1, half = (tid & 1) * 32;
            const float* krow = kbase + (size_t)(s0+m)*1536 + half;
            const float* vrow = vbase + (size_t)(s0+m)*1536 + half;
            #pragma unroll
            for (int i=0;i<8;i++){
                float4 kv = *(const float4*)(krow + i*4);
                int d = half + i*4;
                Ks[(d+0)*72+m]=kv.x; Ks[(d+1)*72+m]=kv.y;
                Ks[(d+2)*72+m]=kv.z; Ks[(d+3)*72+m]=kv.w;
                *(float4*)&Vs[m*72 + d] = *(const float4*)(vrow + i*4);
            }
        }
        if (tid < 127) dds[tid] = ddt[h*2047 + 960 + (s0 - t0) + tid];
        __syncthreads();

        // S = Q K^T  (per warp: 16 rows x 64 keys)
        float S[8][4];
        #pragma unroll
        for (int nj=0;nj<8;nj++)
            #pragma unroll
            for (int q=0;q<4;q++) S[nj][q]=0.f;
        #pragma unroll
        for (int ks=0;ks<8;ks++){
            #pragma unroll
            for (int nj=0;nj<8;nj++){
                float b0 = Ks[(ks*8+tg  )*72 + nj*8 + g];
                float b1 = Ks[(ks*8+tg+4)*72 + nj*8 + g];
                mma8(S[nj], qf[ks], b0, b1);
            }
        }
        // bias: S*0.125 + coef[row] * dd[col - row + 63]
        float c0 = coefs[m0+g], c1 = coefs[m0+g+8];
        #pragma unroll
        for (int nj=0;nj<8;nj++){
            int cn = nj*8 + tg*2;
            float dd0 = dds[cn     - (m0+g)   + 63];
            float dd1 = dds[cn + 1 - (m0+g)   + 63];
            float dd2 = dds[cn     - (m0+g+8) + 63];
            float dd3 = dds[cn + 1 - (m0+g+8) + 63];
            S[nj][0] = fmaf(S[nj][0], 0.125f, c0*dd0);
            S[nj][1] = fmaf(S[nj][1], 0.125f, c0*dd1);
            S[nj][2] = fmaf(S[nj][2], 0.125f, c1*dd2);
            S[nj][3] = fmaf(S[nj][3], 0.125f, c1*dd3);
        }
        // online softmax: row i=0 -> (c0,c1), i=1 -> (c2,c3); row spread over 4 tg lanes
        #pragma unroll
        for (int i=0;i<2;i++){
            float mx = -3.0e38f;
            #pragma unroll
            for (int nj=0;nj<8;nj++) mx = fmaxf(mx, fmaxf(S[nj][2*i], S[nj][2*i+1]));
            mx = fmaxf(mx, __shfl_xor_sync(0xffffffffu, mx, 1));
            mx = fmaxf(mx, __shfl_xor_sync(0xffffffffu, mx, 2));
            float mo = fmaxf(m_run[i], mx);
            float alpha = expf(m_run[i] - mo);
            m_run[i] = mo;
            float ls = 0.f;
            #pragma unroll
            for (int nj=0;nj<8;nj++){
                float p0 = expf(S[nj][2*i]   - mo);
                float p1 = expf(S[nj][2*i+1] - mo);
                S[nj][2*i] = p0; S[nj][2*i+1] = p1;
                ls += p0 + p1;
            }
            ls += __shfl_xor_sync(0xffffffffu, ls, 1);
            ls += __shfl_xor_sync(0xffffffffu, ls, 2);
            l_run[i] = l_run[i]*alpha + ls;
            #pragma unroll
            for (int nd=0;nd<8;nd++){ O[nd][2*i] *= alpha; O[nd][2*i+1] *= alpha; }
        }
        // write P (per-warp region; only warp-local sync needed)
        #pragma unroll
        for (int nj=0;nj<8;nj++){
            *(float2*)&Ps[(m0+g  )*68 + nj*8 + tg*2] = make_float2(S[nj][0], S[nj][1]);
            *(float2*)&Ps[(m0+g+8)*68 + nj*8 + tg*2] = make_float2(S[nj][2], S[nj][3]);
        }
        __syncwarp();
        // O += P V
        #pragma unroll
        for (int ko=0;ko<8;ko++){
            float pa[4];
            pa[0] = Ps[(m0+g  )*68 + ko*8 + tg];
            pa[1] = Ps[(m0+g+8)*68 + ko*8 + tg];
            pa[2] = Ps[(m0+g  )*68 + ko*8 + tg + 4];
            pa[3] = Ps[(m0+g+8)*68 + ko*8 + tg + 4];
            #pragma unroll
            for (int nd=0;nd<8;nd++){
                float b0 = Vs[(ko*8+tg  )*72 + nd*8 + g];
                float b1 = Vs[(ko*8+tg+4)*72 + nd*8 + g];
                mma8(O[nd], pa, b0, b1);
            }
        }
    }
    // epilogue
    float inv0 = 1.0f / l_run[0], inv1 = 1.0f / l_run[1];
    int r0 = t0 + m0 + g;
    #pragma unroll
    for (int nd=0;nd<8;nd++){
        int c = h*64 + nd*8 + tg*2;
        *(float2*)&out[((size_t)(b*1024 + r0  ))*512 + c] = make_float2(O[nd][0]*inv0, O[nd][1]*inv0);
        *(float2*)&out[((size_t)(b*1024 + r0+8))*512 + c] = make_float2(O[nd][2]*inv1, O[nd][3]*inv1);
    }
}

// ---------------- GroupNorm(1, C) over [B,T,D]: deterministic 2-level reduction ----
__global__ void gn_partial_k(const float* __restrict__ x, float2* __restrict__ part){
    int b = blockIdx.x >> 8;
    int blk = blockIdx.x & 255;
    const float* p = x + (size_t)b*524288 + (size_t)blk*2048;
    float s=0.f, q=0.f;
    for (int i=threadIdx.x; i<2048; i+=256){ float v=p[i]; s+=v; q=fmaf(v,v,q); }
    __shared__ float ss[256], sq[256];
    ss[threadIdx.x]=s; sq[threadIdx.x]=q;
    __syncthreads();
    for (int o=128;o>0;o>>=1){
        if (threadIdx.x<o){ ss[threadIdx.x]+=ss[threadIdx.x+o]; sq[threadIdx.x]+=sq[threadIdx.x+o]; }
        __syncthreads();
    }
    if (threadIdx.x==0) part[blockIdx.x] = make_float2(ss[0], sq[0]);
}
__global__ void gn_final_k(const float2* __restrict__ part, float2* __restrict__ mv){
    int b = blockIdx.x;
    float2 v = part[b*256 + threadIdx.x];
    __shared__ float ss[256], sq[256];
    ss[threadIdx.x]=v.x; sq[threadIdx.x]=v.y;
    __syncthreads();
    for (int o=128;o>0;o>>=1){
        if (threadIdx.x<o){ ss[threadIdx.x]+=ss[threadIdx.x+o]; sq[threadIdx.x]+=sq[threadIdx.x+o]; }
        __syncthreads();
    }
    if (threadIdx.x==0){
        float mean = ss[0]*(1.0f/524288.0f);
        float var  = sq[0]*(1.0f/524288.0f) - mean*mean;
        mv[b] = make_float2(mean, rsqrtf(var + 1e-5f));
    }
}
template<bool SILU_>
__global__ void gn_apply_k(const float* __restrict__ x, const float2* __restrict__ mv,
                           const float* __restrict__ g, const float* __restrict__ be,
                           float* __restrict__ y){
    size_t idx = (size_t)blockIdx.x*256 + threadIdx.x;
    int b = (int)(idx >> 19);
    int d = (int)(idx & 511);
    float2 m = mv[b];
    float v = (x[idx]-m.x)*m.y*g[d] + be[d];
    if (SILU_) v = v*sigm(v);
    y[idx]=v;
}

// ---------------- GLU / depthwise conv ----------------
__global__ void glu_k(const float* __restrict__ in, float* __restrict__ out){
    size_t idx = (size_t)blockIdx.x*256 + threadIdx.x;
    size_t row = idx >> 9; int c = (int)(idx & 511);
    float a  = in[row*1024 + c];
    float bb = in[row*1024 + 512 + c];
    out[idx] = a * sigm(bb);
}
__global__ void dwconv_k(const float* __restrict__ in, const float* __restrict__ w,
                         const float* __restrict__ bias, float* __restrict__ out){
    int d = threadIdx.x;               // 512
    int t = blockIdx.x & 1023;
    int b = blockIdx.x >> 10;
    const float* base = in + (size_t)b*1024*512 + d;
    float acc = bias[d];
    #pragma unroll
    for (int k=0;k<31;k++){
        int tt = t + k - 15;
        if (tt >= 0 && tt < 1024)
            acc = fmaf(base[(size_t)tt*512], w[d*31+k], acc);
    }
    out[((size_t)b*1024 + t)*512 + d] = acc;
}

// ---------------- launch ----------------
extern "C" void kernel_launch(void* const* d_in, const int* in_sizes, int n_in,
                              void* d_out, int out_size) {
    const float* x      = (const float*)d_in[0];
    const float* ff1_w1 = (const float*)d_in[1];
    const float* ff1_b1 = (const float*)d_in[2];
    const float* ff1_w2 = (const float*)d_in[3];
    const float* ff1_b2 = (const float*)d_in[4];
    const float* qkv_w  = (const float*)d_in[5];
    const float* qkv_b  = (const float*)d_in[6];
    const float* out_w  = (const float*)d_in[7];
    const float* out_b  = (const float*)d_in[8];
    const float* gn1_g  = (const float*)d_in[9];
    const float* gn1_b  = (const float*)d_in[10];
    const float* pw1_w  = (const float*)d_in[11];
    const float* pw1_b  = (const float*)d_in[12];
    const float* dw_w   = (const float*)d_in[13];
    const float* dw_b   = (const float*)d_in[14];
    const float* gn2_g  = (const float*)d_in[15];
    const float* gn2_b  = (const float*)d_in[16];
    const float* pw2_w  = (const float*)d_in[17];
    const float* pw2_b  = (const float*)d_in[18];
    const float* ff2_w1 = (const float*)d_in[19];
    const float* ff2_b1 = (const float*)d_in[20];
    const float* ff2_w2 = (const float*)d_in[21];
    const float* ff2_b2 = (const float*)d_in[22];
    const float* rel_e  = (const float*)d_in[23];
    const float* gate_u = (const float*)d_in[24];
    const float* gate_w = (const float*)d_in[25];
    const float* gate_s = (const float*)d_in[26];

    float *S, *T1, *T2, *T3, *DDp; float2 *PART, *MV;
    cudaGetSymbolAddress((void**)&S,  g_S);
    cudaGetSymbolAddress((void**)&T1, g_T1);
    cudaGetSymbolAddress((void**)&T2, g_T2);
    cudaGetSymbolAddress((void**)&T3, g_T3);
    cudaGetSymbolAddress((void**)&DDp,g_DD);
    cudaGetSymbolAddress((void**)&PART, g_part);
    cudaGetSymbolAddress((void**)&MV,   g_mv);

    const int FLASH_SMEM = (64*68 + 64*72 + 64*72 + 64*68 + 128 + 64) * 4;  // 72448
    cudaFuncSetAttribute((const void*)flash_mma_k,
                         cudaFuncAttributeMaxDynamicSharedMemorySize, FLASH_SMEM);
    const int GS256 = (4*128*36 + 4*32*264) * 4;   // 208896
    const int GS128 = (4*128*36 + 4*32*136) * 4;   // 143360
    cudaFuncSetAttribute(mma_gemm_k<256,true ,false>, cudaFuncAttributeMaxDynamicSharedMemorySize, GS256);
    cudaFuncSetAttribute(mma_gemm_k<256,false,false>, cudaFuncAttributeMaxDynamicSharedMemorySize, GS256);
    cudaFuncSetAttribute(mma_gemm_k<128,false,true >, cudaFuncAttributeMaxDynamicSharedMemorySize, GS128);

    dim3 tb(32,8);
    // x -> s [B,T,D]
    transpose_bdt_btd<<<dim3(32,16,4), tb>>>(x, S);
    build_dd_k<<<64,256>>>(rel_e, DDp);
    // FFN1 (half-step)
    mma_gemm_k<256,true ,false><<<dim3( 8,32),256,GS256>>>(S,  ff1_w1, ff1_b1, nullptr, T1, 4096,2048, 512, 0.f);
    mma_gemm_k<128,false,true ><<<dim3( 4,32),256,GS128>>>(T1, ff1_w2, ff1_b2, S,       S,  4096, 512,2048, 0.5f);
    // QKV
    mma_gemm_k<256,false,false><<<dim3( 6,32),256,GS256>>>(S,  qkv_w,  qkv_b,  nullptr, T1, 4096,1536, 512, 0.f);
    // attention
    flash_mma_k<<<dim3(16,8,4),128,FLASH_SMEM>>>(T1, gate_u, gate_w, gate_s, DDp, T2);
    mma_gemm_k<128,false,true ><<<dim3( 4,32),256,GS128>>>(T2, out_w,  out_b,  S,       S,  4096, 512, 512, 1.0f);
    // conv module
    gn_partial_k<<<1024,256>>>(S, PART);
    gn_final_k<<<4,256>>>(PART, MV);
    gn_apply_k<false><<<8192,256>>>(S, MV, gn1_g, gn1_b, T2);
    mma_gemm_k<256,false,false><<<dim3( 4,32),256,GS256>>>(T2, pw1_w,  pw1_b,  nullptr, T1, 4096,1024, 512, 0.f);
    glu_k<<<8192,256>>>(T1, T3);
    dwconv_k<<<4096,512>>>(T3, dw_w, dw_b, T2);
    gn_partial_k<<<1024,256>>>(T2, PART);
    gn_final_k<<<4,256>>>(PART, MV);
    gn_apply_k<true><<<8192,256>>>(T2, MV, gn2_g, gn2_b, T3);
    mma_gemm_k<128,false,true ><<<dim3( 4,32),256,GS128>>>(T3, pw2_w,  pw2_b,  S,       S,  4096, 512, 512, 1.0f);
    // FFN2 (half-step)
    mma_gemm_k<256,true ,false><<<dim3( 8,32),256,GS256>>>(S,  ff2_w1, ff2_b1, nullptr, T1, 4096,2048, 512, 0.f);
    mma_gemm_k<128,false,true ><<<dim3( 4,32),256,GS128>>>(T1, ff2_w2, ff2_b2, S,       S,  4096, 512,2048, 0.5f);
    // s -> out [B,D,T]
    transpose_btd_bdt<<<dim3(16,32,4), tb>>>(S, (float*)d_out);
}

// round 5
// speedup vs baseline: 2.1382x; 1.0343x over previous
#include <cuda_runtime.h>
#include <math.h>
#include <cstdint>

// ---------------- scratch (device globals; allocation-free rule) ----------------
__device__ float  g_S [4096*512];    // residual stream, [B,T,D]
__device__ float  g_T1[4096*2048];   // ffn hidden / qkv / pw1 out
__device__ float  g_T2[4096*512];
__device__ float  g_T3[4096*512];
__device__ float  g_DD[8*2047];      // rel-pos bias table [h][rel+1023]
__device__ float2 g_part[1024];      // groupnorm partials
__device__ float2 g_mv[4];           // (mean, inv_std) per batch

__device__ __forceinline__ float gelu_f(float x){
    return 0.5f * x * (1.0f + erff(x * 0.70710678118654752440f));
}
__device__ __forceinline__ float sigm(float x){ return 1.0f/(1.0f + expf(-x)); }

// ---------------- async-copy helpers ----------------
__device__ __forceinline__ void cpasync16(uint32_t dst, const void* src){
    asm volatile("cp.async.ca.shared.global [%0], [%1], 16;" :: "r"(dst), "l"(src));
}
#define CP_COMMIT() asm volatile("cp.async.commit_group;" ::: "memory")
template<int N>
__device__ __forceinline__ void cp_wait(){
    asm volatile("cp.async.wait_group %0;" :: "n"(N) : "memory");
}

// tf32 warp MMA: D(16x8) += A(16x8) * B(8x8). Raw fp32 regs (HW truncates to tf32).
__device__ __forceinline__ void mma8(float* c, const float* a, float b0, float b1){
    asm volatile(
        "mma.sync.aligned.m16n8k8.row.col.f32.tf32.tf32.f32 "
        "{%0,%1,%2,%3},{%4,%5,%6,%7},{%8,%9},{%0,%1,%2,%3};"
        : "+f"(c[0]), "+f"(c[1]), "+f"(c[2]), "+f"(c[3])
        : "r"(__float_as_uint(a[0])), "r"(__float_as_uint(a[1])),
          "r"(__float_as_uint(a[2])), "r"(__float_as_uint(a[3])),
          "r"(__float_as_uint(b0)),   "r"(__float_as_uint(b1)));
}

// ---------------- tensor-core tf32 GEMM: C = epi(A[MxK] @ B[KxN] + bias) -------
// CTA 128 x TN, 512 threads (16 warps: 4 row x 4 col), warp tile 32 x TN/4.
// K staged by 32 (4 mma k-steps), 4-stage cp.async pipeline.
template<int TN, bool GELU_, bool RES_>
__global__ void __launch_bounds__(512,1) mma_gemm_k(
    const float* __restrict__ A, const float* __restrict__ B,
    const float* __restrict__ bias, const float* __restrict__ res,
    float* __restrict__ C, int M, int N, int Kd, float rscale)
{
    constexpr int WN   = TN/4;
    constexpr int NJ   = WN/8;
    constexpr int BROW = TN + 8;      // row stride (mod 32 == 8 -> conflict-free frags)
    constexpr int ASZ  = 128*36;
    constexpr int BSZ  = 32*BROW;
    constexpr int NSEG = TN/4;

    extern __shared__ __align__(16) float smem[];
    float* As = smem;                 // [4][128][36]
    float* Bs = smem + 4*ASZ;         // [4][32][BROW]

    int tid = threadIdx.x, lane = tid & 31, wid = tid >> 5;
    int wr = wid & 3, wc = wid >> 2;
    int g = lane >> 2, tg = lane & 3;
    int row0 = blockIdx.y*128, col0 = blockIdx.x*TN;

    const float* Ag = A + (size_t)row0*Kd;
    const float* Bg = B + col0;
    uint32_t sA = (uint32_t)__cvta_generic_to_shared(As);
    uint32_t sB = (uint32_t)__cvta_generic_to_shared(Bs);

    auto loadA = [&](int kt){
        int k0 = kt*32;
        uint32_t base = sA + (kt & 3)*(ASZ*4);
        #pragma unroll
        for (int i = 0; i < 2; i++){
            int f = tid + i*512;
            int m = f >> 3, seg = f & 7;
            cpasync16(base + (uint32_t)(m*144 + seg*16),
                      Ag + (size_t)m*Kd + k0 + seg*4);
        }
    };
    auto loadB = [&](int kt){
        int k0 = kt*32;
        uint32_t base = sB + (kt & 3)*(BSZ*4);
        #pragma unroll
        for (int i = 0; i < (32*NSEG)/512; i++){
            int f = tid + i*512;
            int k = f / NSEG, s = f % NSEG;
            cpasync16(base + (uint32_t)(k*(BROW*4) + s*16),
                      Bg + (size_t)(k0+k)*N + s*4);
        }
    };

    float acc[2][NJ][4];
    #pragma unroll
    for (int mi=0;mi<2;mi++)
        #pragma unroll
        for (int nj=0;nj<NJ;nj++)
            #pragma unroll
            for (int q=0;q<4;q++) acc[mi][nj][q]=0.f;

    int nk = Kd >> 5;
    loadA(0); loadB(0); CP_COMMIT();
    loadA(1); loadB(1); CP_COMMIT();
    loadA(2); loadB(2); CP_COMMIT();

    for (int kt = 0; kt < nk; ++kt){
        cp_wait<2>();
        __syncthreads();
        if (kt + 3 < nk){ loadA(kt+3); loadB(kt+3); }
        CP_COMMIT();

        int buf = kt & 3;
        const float* Ab = As + buf*ASZ + (wr*32)*36;
        const float* Bb = Bs + buf*BSZ + wc*WN;
        #pragma unroll
        for (int ks = 0; ks < 4; ++ks){
            int k0 = ks*8;
            float af[2][4];
            #pragma unroll
            for (int mi=0;mi<2;mi++){
                const float* ap = Ab + (mi*16 + g)*36 + k0 + tg;
                af[mi][0] = ap[0];
                af[mi][1] = ap[8*36];
                af[mi][2] = ap[4];
                af[mi][3] = ap[8*36 + 4];
            }
            #pragma unroll
            for (int nj=0;nj<NJ;nj++){
                float b0 = Bb[(k0+tg)*BROW   + nj*8 + g];
                float b1 = Bb[(k0+tg+4)*BROW + nj*8 + g];
                #pragma unroll
                for (int mi=0;mi<2;mi++)
                    mma8(acc[mi][nj], af[mi], b0, b1);
            }
        }
    }

    // epilogue
    #pragma unroll
    for (int nj=0;nj<NJ;nj++){
        int c = col0 + wc*WN + nj*8 + tg*2;
        float2 bi = *(const float2*)&bias[c];
        #pragma unroll
        for (int mi=0;mi<2;mi++){
            int r0 = row0 + wr*32 + mi*16 + g;
            float v0 = acc[mi][nj][0] + bi.x;
            float v1 = acc[mi][nj][1] + bi.y;
            float v2 = acc[mi][nj][2] + bi.x;
            float v3 = acc[mi][nj][3] + bi.y;
            if (GELU_){ v0=gelu_f(v0); v1=gelu_f(v1); v2=gelu_f(v2); v3=gelu_f(v3); }
            if (RES_){
                float2 r0v = *(const float2*)&res[(size_t)r0*N + c];
                float2 r1v = *(const float2*)&res[(size_t)(r0+8)*N + c];
                v0 = fmaf(rscale, v0, r0v.x); v1 = fmaf(rscale, v1, r0v.y);
                v2 = fmaf(rscale, v2, r1v.x); v3 = fmaf(rscale, v3, r1v.y);
            }
            *(float2*)&C[(size_t)r0*N + c]     = make_float2(v0, v1);
            *(float2*)&C[(size_t)(r0+8)*N + c] = make_float2(v2, v3);
        }
    }
}

// ---------------- transposes ----------------
__global__ void transpose_bdt_btd(const float* __restrict__ in, float* __restrict__ out){
    __shared__ float tile[32][33];
    int b = blockIdx.z;
    int t0 = blockIdx.x*32, d0 = blockIdx.y*32;
    int lx = threadIdx.x, ly = threadIdx.y;
    #pragma unroll
    for (int i=0;i<32;i+=8)
        tile[ly+i][lx] = in[((size_t)b*512 + d0+ly+i)*1024 + t0 + lx];
    __syncthreads();
    #pragma unroll
    for (int i=0;i<32;i+=8)
        out[((size_t)b*1024 + t0+ly+i)*512 + d0 + lx] = tile[lx][ly+i];
}
__global__ void transpose_btd_bdt(const float* __restrict__ in, float* __restrict__ out){
    __shared__ float tile[32][33];
    int b = blockIdx.z;
    int d0 = blockIdx.x*32, t0 = blockIdx.y*32;
    int lx = threadIdx.x, ly = threadIdx.y;
    #pragma unroll
    for (int i=0;i<32;i+=8)
        tile[ly+i][lx] = in[((size_t)b*1024 + t0+ly+i)*512 + d0 + lx];
    __syncthreads();
    #pragma unroll
    for (int i=0;i<32;i+=8)
        out[((size_t)b*512 + d0+ly+i)*1024 + t0 + lx] = tile[lx][ly+i];
}

// ---------------- relative-position bias table ----------------
__global__ void build_dd_k(const float* __restrict__ rel_embed, float* __restrict__ ddt){
    int idx = blockIdx.x*256 + threadIdx.x;
    if (idx >= 8*2047) return;
    int h = idx / 2047;
    int rpos = idx % 2047;
    int rel = rpos - 1023;
    int sign = (rel >= 0) ? 1 : 0;
    int a = (rel >= 0) ? rel : -rel;
    int bucket;
    if (a < 80) bucket = a;
    else {
        float lr = logf((float)a / 80.0f) / logf(10.0f);
        int lp = 80 + (int)(lr * 80.0f);
        bucket = (lp < 159) ? lp : 159;
    }
    bucket += sign*160;
    if (bucket < 0) bucket = 0;
    if (bucket > 319) bucket = 319;
    ddt[h*2047 + rpos] = rel_embed[bucket*8 + h];
}

// ---------------- tensor-core flash attention with gated rel-pos bias ----------
__global__ void __launch_bounds__(128) flash_mma_k(
    const float* __restrict__ qkv,     // [B,T,3,H,DH] row stride 1536
    const float* __restrict__ gate_u, const float* __restrict__ gate_w,
    const float* __restrict__ gate_scale, const float* __restrict__ ddt,
    float* __restrict__ out)           // [B,T,512]
{
    extern __shared__ float sm[];
    float* Qs    = sm;                 // [64][68]
    float* Ks    = Qs + 64*68;         // [64][72]  K transposed: Ks[d][s]
    float* Vs    = Ks + 64*72;         // [64][72]  Vs[s][d]
    float* Ps    = Vs + 64*72;         // [64][68]  probs row-major
    float* dds   = Ps + 64*68;         // [128]
    float* coefs = dds + 128;          // [64]

    int tid = threadIdx.x, lane = tid & 31, wid = tid >> 5;
    int g = lane >> 2, tg = lane & 3;
    int t0 = blockIdx.x * 64;
    int h  = blockIdx.y;
    int b  = blockIdx.z;
    int m0 = wid * 16;

    const float* qbase = qkv + (size_t)b*1024*1536 + h*64;
    const float* kbase = qbase + 512;
    const float* vbase = qbase + 1024;

    { // load Q tile -> smem
        int m = tid >> 1, half = (tid & 1) * 32;
        const float* qrow = qbase + (size_t)(t0+m)*1536 + half;
        #pragma unroll
        for (int i=0;i<8;i++)
            *(float4*)&Qs[m*68 + half + i*4] = *(const float4*)(qrow + i*4);
    }
    __syncthreads();
    if (tid < 64){ // per-query gate coefficient
        float du=0.f, dw=0.f;
        #pragma unroll
        for (int d=0; d<64; d++){
            float qv = Qs[tid*68 + d];
            du = fmaf(qv, gate_u[h*64+d], du);
            dw = fmaf(qv, gate_w[h*64+d], dw);
        }
        float gu = sigm(du), gr = sigm(dw);
        coefs[tid] = 1.0f + gu + (1.0f-gu)*gate_scale[h]*gr;
    }
    // Q fragments (register-resident)
    float qf[8][4];
    #pragma unroll
    for (int ks=0;ks<8;ks++){
        qf[ks][0] = Qs[(m0+g  )*68 + ks*8 + tg];
        qf[ks][1] = Qs[(m0+g+8)*68 + ks*8 + tg];
        qf[ks][2] = Qs[(m0+g  )*68 + ks*8 + tg + 4];
        qf[ks][3] = Qs[(m0+g+8)*68 + ks*8 + tg + 4];
    }

    float m_run[2] = {-3.0e38f, -3.0e38f}, l_run[2] = {0.f, 0.f};
    float O[8][4];
    #pragma unroll
    for (int nd=0;nd<8;nd++)
        #pragma unroll
        for (int q=0;q<4;q++) O[nd][q]=0.f;

    for (int s0 = 0; s0 < 1024; s0 += 64){
        __syncthreads();
        { // load K transposed + V
            int m = tid >> 1, half = (tid & 1) * 32;
            const float* krow = kbase + (size_t)(s0+m)*1536 + half;
            const float* vrow = vbase + (size_t)(s0+m)*1536 + half;
            #pragma unroll
            for (int i=0;i<8;i++){
                float4 kv = *(const float4*)(krow + i*4);
                int d = half + i*4;
                Ks[(d+0)*72+m]=kv.x; Ks[(d+1)*72+m]=kv.y;
                Ks[(d+2)*72+m]=kv.z; Ks[(d+3)*72+m]=kv.w;
                *(float4*)&Vs[m*72 + d] = *(const float4*)(vrow + i*4);
            }
        }
        if (tid < 127) dds[tid] = ddt[h*2047 + 960 + (s0 - t0) + tid];
        __syncthreads();

        // S = Q K^T
        float S[8][4];
        #pragma unroll
        for (int nj=0;nj<8;nj++)
            #pragma unroll
            for (int q=0;q<4;q++) S[nj][q]=0.f;
        #pragma unroll
        for (int ks=0;ks<8;ks++){
            #pragma unroll
            for (int nj=0;nj<8;nj++){
                float b0 = Ks[(ks*8+tg  )*72 + nj*8 + g];
                float b1 = Ks[(ks*8+tg+4)*72 + nj*8 + g];
                mma8(S[nj], qf[ks], b0, b1);
            }
        }
        // bias
        float c0 = coefs[m0+g], c1 = coefs[m0+g+8];
        #pragma unroll
        for (int nj=0;nj<8;nj++){
            int cn = nj*8 + tg*2;
            float dd0 = dds[cn     - (m0+g)   + 63];
            float dd1 = dds[cn + 1 - (m0+g)   + 63];
            float dd2 = dds[cn     - (m0+g+8) + 63];
            float dd3 = dds[cn + 1 - (m0+g+8) + 63];
            S[nj][0] = fmaf(S[nj][0], 0.125f, c0*dd0);
            S[nj][1] = fmaf(S[nj][1], 0.125f, c0*dd1);
            S[nj][2] = fmaf(S[nj][2], 0.125f, c1*dd2);
            S[nj][3] = fmaf(S[nj][3], 0.125f, c1*dd3);
        }
        // online softmax
        #pragma unroll
        for (int i=0;i<2;i++){
            float mx = -3.0e38f;
            #pragma unroll
            for (int nj=0;nj<8;nj++) mx = fmaxf(mx, fmaxf(S[nj][2*i], S[nj][2*i+1]));
            mx = fmaxf(mx, __shfl_xor_sync(0xffffffffu, mx, 1));
            mx = fmaxf(mx, __shfl_xor_sync(0xffffffffu, mx, 2));
            float mo = fmaxf(m_run[i], mx);
            float alpha = __expf(m_run[i] - mo);
            m_run[i] = mo;
            float ls = 0.f;
            #pragma unroll
            for (int nj=0;nj<8;nj++){
                float p0 = __expf(S[nj][2*i]   - mo);
                float p1 = __expf(S[nj][2*i+1] - mo);
                S[nj][2*i] = p0; S[nj][2*i+1] = p1;
                ls += p0 + p1;
            }
            ls += __shfl_xor_sync(0xffffffffu, ls, 1);
            ls += __shfl_xor_sync(0xffffffffu, ls, 2);
            l_run[i] = l_run[i]*alpha + ls;
            #pragma unroll
            for (int nd=0;nd<8;nd++){ O[nd][2*i] *= alpha; O[nd][2*i+1] *= alpha; }
        }
        // write P (per-warp region)
        #pragma unroll
        for (int nj=0;nj<8;nj++){
            *(float2*)&Ps[(m0+g  )*68 + nj*8 + tg*2] = make_float2(S[nj][0], S[nj][1]);
            *(float2*)&Ps[(m0+g+8)*68 + nj*8 + tg*2] = make_float2(S[nj][2], S[nj][3]);
        }
        __syncwarp();
        // O += P V
        #pragma unroll
        for (int ko=0;ko<8;ko++){
            float pa[4];
            pa[0] = Ps[(m0+g  )*68 + ko*8 + tg];
            pa[1] = Ps[(m0+g+8)*68 + ko*8 + tg];
            pa[2] = Ps[(m0+g  )*68 + ko*8 + tg + 4];
            pa[3] = Ps[(m0+g+8)*68 + ko*8 + tg + 4];
            #pragma unroll
            for (int nd=0;nd<8;nd++){
                float b0 = Vs[(ko*8+tg  )*72 + nd*8 + g];
                float b1 = Vs[(ko*8+tg+4)*72 + nd*8 + g];
                mma8(O[nd], pa, b0, b1);
            }
        }
    }
    float inv0 = 1.0f / l_run[0], inv1 = 1.0f / l_run[1];
    int r0 = t0 + m0 + g;
    #pragma unroll
    for (int nd=0;nd<8;nd++){
        int c = h*64 + nd*8 + tg*2;
        *(float2*)&out[((size_t)(b*1024 + r0  ))*512 + c] = make_float2(O[nd][0]*inv0, O[nd][1]*inv0);
        *(float2*)&out[((size_t)(b*1024 + r0+8))*512 + c] = make_float2(O[nd][2]*inv1, O[nd][3]*inv1);
    }
}

// ---------------- GroupNorm(1, C) over [B,T,D]: deterministic 2-level reduction ----
__global__ void gn_partial_k(const float* __restrict__ x, float2* __restrict__ part){
    int b = blockIdx.x >> 8;
    int blk = blockIdx.x & 255;
    const float* p = x + (size_t)b*524288 + (size_t)blk*2048;
    float s=0.f, q=0.f;
    #pragma unroll
    for (int i=0;i<2;i++){
        float4 v4 = *(const float4*)(p + (threadIdx.x + i*256)*4 - threadIdx.x*4 + threadIdx.x*4);
        // (simple indexing below; the above line is replaced)
        (void)v4;
    }
    s=0.f; q=0.f;
    for (int i=threadIdx.x; i<512; i+=256){
        float4 v = *(const float4*)(p + i*4);
        s += v.x+v.y+v.z+v.w;
        q = fmaf(v.x,v.x,fmaf(v.y,v.y,fmaf(v.z,v.z,fmaf(v.w,v.w,q))));
    }
    __shared__ float ss[256], sq[256];
    ss[threadIdx.x]=s; sq[threadIdx.x]=q;
    __syncthreads();
    for (int o=128;o>0;o>>=1){
        if (threadIdx.x<o){ ss[threadIdx.x]+=ss[threadIdx.x+o]; sq[threadIdx.x]+=sq[threadIdx.x+o]; }
        __syncthreads();
    }
    if (threadIdx.x==0) part[blockIdx.x] = make_float2(ss[0], sq[0]);
}
__global__ void gn_final_k(const float2* __restrict__ part, float2* __restrict__ mv){
    int b = blockIdx.x;
    float2 v = part[b*256 + threadIdx.x];
    __shared__ float ss[256], sq[256];
    ss[threadIdx.x]=v.x; sq[threadIdx.x]=v.y;
    __syncthreads();
    for (int o=128;o>0;o>>=1){
        if (threadIdx.x<o){ ss[threadIdx.x]+=ss[threadIdx.x+o]; sq[threadIdx.x]+=sq[threadIdx.x+o]; }
        __syncthreads();
    }
    if (threadIdx.x==0){
        float mean = ss[0]*(1.0f/524288.0f);
        float var  = sq[0]*(1.0f/524288.0f) - mean*mean;
        mv[b] = make_float2(mean, rsqrtf(var + 1e-5f));
    }
}
template<bool SILU_>
__global__ void gn_apply_k(const float* __restrict__ x, const float2* __restrict__ mv,
                           const float* __restrict__ g, const float* __restrict__ be,
                           float* __restrict__ y){
    size_t i4 = (size_t)blockIdx.x*256 + threadIdx.x;   // over 512K float4s
    int b = (int)(i4 >> 17);
    int d = (int)((i4 & 127) << 2);
    float2 m = mv[b];
    float4 xv = *(const float4*)(x + i4*4);
    float4 gv = *(const float4*)(g + d);
    float4 bv = *(const float4*)(be + d);
    float4 o;
    o.x = (xv.x-m.x)*m.y*gv.x + bv.x;
    o.y = (xv.y-m.x)*m.y*gv.y + bv.y;
    o.z = (xv.z-m.x)*m.y*gv.z + bv.z;
    o.w = (xv.w-m.x)*m.y*gv.w + bv.w;
    if (SILU_){
        o.x *= sigm(o.x); o.y *= sigm(o.y); o.z *= sigm(o.z); o.w *= sigm(o.w);
    }
    *(float4*)(y + i4*4) = o;
}

// ---------------- GLU / depthwise conv ----------------
__global__ void glu_k(const float* __restrict__ in, float* __restrict__ out){
    size_t i4 = (size_t)blockIdx.x*256 + threadIdx.x;   // over 512K float4s
    size_t row = i4 >> 7; int c = (int)((i4 & 127) << 2);
    float4 a  = *(const float4*)(in + row*1024 + c);
    float4 bb = *(const float4*)(in + row*1024 + 512 + c);
    float4 o;
    o.x = a.x * sigm(bb.x); o.y = a.y * sigm(bb.y);
    o.z = a.z * sigm(bb.z); o.w = a.w * sigm(bb.w);
    *(float4*)(out + i4*4) = o;
}
__global__ void dwconv_k(const float* __restrict__ in, const float* __restrict__ w,
                         const float* __restrict__ bias, float* __restrict__ out){
    int d = threadIdx.x;               // 512
    int t = blockIdx.x & 1023;
    int b = blockIdx.x >> 10;
    const float* base = in + (size_t)b*1024*512 + d;
    float acc = bias[d];
    #pragma unroll
    for (int k=0;k<31;k++){
        int tt = t + k - 15;
        if (tt >= 0 && tt < 1024)
            acc = fmaf(base[(size_t)tt*512], w[d*31+k], acc);
    }
    out[((size_t)b*1024 + t)*512 + d] = acc;
}

// ---------------- launch ----------------
extern "C" void kernel_launch(void* const* d_in, const int* in_sizes, int n_in,
                              void* d_out, int out_size) {
    const float* x      = (const float*)d_in[0];
    const float* ff1_w1 = (const float*)d_in[1];
    const float* ff1_b1 = (const float*)d_in[2];
    const float* ff1_w2 = (const float*)d_in[3];
    const float* ff1_b2 = (const float*)d_in[4];
    const float* qkv_w  = (const float*)d_in[5];
    const float* qkv_b  = (const float*)d_in[6];
    const float* out_w  = (const float*)d_in[7];
    const float* out_b  = (const float*)d_in[8];
    const float* gn1_g  = (const float*)d_in[9];
    const float* gn1_b  = (const float*)d_in[10];
    const float* pw1_w  = (const float*)d_in[11];
    const float* pw1_b  = (const float*)d_in[12];
    const float* dw_w   = (const float*)d_in[13];
    const float* dw_b   = (const float*)d_in[14];
    const float* gn2_g  = (const float*)d_in[15];
    const float* gn2_b  = (const float*)d_in[16];
    const float* pw2_w  = (const float*)d_in[17];
    const float* pw2_b  = (const float*)d_in[18];
    const float* ff2_w1 = (const float*)d_in[19];
    const float* ff2_b1 = (const float*)d_in[20];
    const float* ff2_w2 = (const float*)d_in[21];
    const float* ff2_b2 = (const float*)d_in[22];
    const float* rel_e  = (const float*)d_in[23];
    const float* gate_u = (const float*)d_in[24];
    const float* gate_w = (const float*)d_in[25];
    const float* gate_s = (const float*)d_in[26];

    float *S, *T1, *T2, *T3, *DDp; float2 *PART, *MV;
    cudaGetSymbolAddress((void**)&S,  g_S);
    cudaGetSymbolAddress((void**)&T1, g_T1);
    cudaGetSymbolAddress((void**)&T2, g_T2);
    cudaGetSymbolAddress((void**)&T3, g_T3);
    cudaGetSymbolAddress((void**)&DDp,g_DD);
    cudaGetSymbolAddress((void**)&PART, g_part);
    cudaGetSymbolAddress((void**)&MV,   g_mv);

    const int FLASH_SMEM = (64*68 + 64*72 + 64*72 + 64*68 + 128 + 64) * 4;  // 72448
    cudaFuncSetAttribute((const void*)flash_mma_k,
                         cudaFuncAttributeMaxDynamicSharedMemorySize, FLASH_SMEM);
    const int GS256 = (4*128*36 + 4*32*264) * 4;   // 208896
    const int GS128 = (4*128*36 + 4*32*136) * 4;   // 143360
    cudaFuncSetAttribute(mma_gemm_k<256,true ,false>, cudaFuncAttributeMaxDynamicSharedMemorySize, GS256);
    cudaFuncSetAttribute(mma_gemm_k<256,false,false>, cudaFuncAttributeMaxDynamicSharedMemorySize, GS256);
    cudaFuncSetAttribute(mma_gemm_k<128,false,true >, cudaFuncAttributeMaxDynamicSharedMemorySize, GS128);

    dim3 tb(32,8);
    // x -> s [B,T,D]
    transpose_bdt_btd<<<dim3(32,16,4), tb>>>(x, S);
    build_dd_k<<<64,256>>>(rel_e, DDp);
    // FFN1 (half-step)
    mma_gemm_k<256,true ,false><<<dim3( 8,32),512,GS256>>>(S,  ff1_w1, ff1_b1, nullptr, T1, 4096,2048, 512, 0.f);
    mma_gemm_k<128,false,true ><<<dim3( 4,32),512,GS128>>>(T1, ff1_w2, ff1_b2, S,       S,  4096, 512,2048, 0.5f);
    // QKV
    mma_gemm_k<256,false,false><<<dim3( 6,32),512,GS256>>>(S,  qkv_w,  qkv_b,  nullptr, T1, 4096,1536, 512, 0.f);
    // attention
    flash_mma_k<<<dim3(16,8,4),128,FLASH_SMEM>>>(T1, gate_u, gate_w, gate_s, DDp, T2);
    mma_gemm_k<128,false,true ><<<dim3( 4,32),512,GS128>>>(T2, out_w,  out_b,  S,       S,  4096, 512, 512, 1.0f);
    // conv module
    gn_partial_k<<<1024,256>>>(S, PART);
    gn_final_k<<<4,256>>>(PART, MV);
    gn_apply_k<false><<<2048,256>>>(S, MV, gn1_g, gn1_b, T2);
    mma_gemm_k<256,false,false><<<dim3( 4,32),512,GS256>>>(T2, pw1_w,  pw1_b,  nullptr, T1, 4096,1024, 512, 0.f);
    glu_k<<<2048,256>>>(T1, T3);
    dwconv_k<<<4096,512>>>(T3, dw_w, dw_b, T2);
    gn_partial_k<<<1024,256>>>(T2, PART);
    gn_final_k<<<4,256>>>(PART, MV);
    gn_apply_k<true><<<2048,256>>>(T2, MV, gn2_g, gn2_b, T3);
    mma_gemm_k<128,false,true ><<<dim3( 4,32),512,GS128>>>(T3, pw2_w,  pw2_b,  S,       S,  4096, 512, 512, 1.0f);
    // FFN2 (half-step)
    mma_gemm_k<256,true ,false><<<dim3( 8,32),512,GS256>>>(S,  ff2_w1, ff2_b1, nullptr, T1, 4096,2048, 512, 0.f);
    mma_gemm_k<128,false,true ><<<dim3( 4,32),512,GS128>>>(T1, ff2_w2, ff2_b2, S,       S,  4096, 512,2048, 0.5f);
    // s -> out [B,D,T]
    transpose_btd_bdt<<<dim3(16,32,4), tb>>>(S, (float*)d_out);
}

// round 6
// speedup vs baseline: 2.1885x; 1.0235x over previous
#include <cuda_runtime.h>
#include <math.h>
#include <cstdint>

// ---------------- scratch (device globals; allocation-free rule) ----------------
__device__ float  g_S [4096*512];    // residual stream, [B,T,D]
__device__ float  g_T1[4096*2048];   // ffn hidden / qkv / pw1 out
__device__ float  g_T2[4096*512];
__device__ float  g_T3[4096*512];
__device__ float  g_DD[8*2047];      // rel-pos bias table [h][rel+1023]
__device__ float  g_WP[512*1024 + 1024]; // permuted pw1 weights + bias
__device__ float2 g_part[1024];      // groupnorm partials
__device__ float2 g_mv[4];           // (mean, inv_std) per batch

__device__ __forceinline__ float gelu_f(float x){
    return 0.5f * x * (1.0f + erff(x * 0.70710678118654752440f));
}
__device__ __forceinline__ float sigm(float x){ return 1.0f/(1.0f + expf(-x)); }

// ---------------- async-copy helpers ----------------
__device__ __forceinline__ void cpasync16(uint32_t dst, const void* src){
    asm volatile("cp.async.ca.shared.global [%0], [%1], 16;" :: "r"(dst), "l"(src));
}
#define CP_COMMIT() asm volatile("cp.async.commit_group;" ::: "memory")
template<int N>
__device__ __forceinline__ void cp_wait(){
    asm volatile("cp.async.wait_group %0;" :: "n"(N) : "memory");
}

// tf32 warp MMA: D(16x8) += A(16x8) * B(8x8). Raw fp32 regs (HW truncates to tf32).
__device__ __forceinline__ void mma8(float* c, const float* a, float b0, float b1){
    asm volatile(
        "mma.sync.aligned.m16n8k8.row.col.f32.tf32.tf32.f32 "
        "{%0,%1,%2,%3},{%4,%5,%6,%7},{%8,%9},{%0,%1,%2,%3};"
        : "+f"(c[0]), "+f"(c[1]), "+f"(c[2]), "+f"(c[3])
        : "r"(__float_as_uint(a[0])), "r"(__float_as_uint(a[1])),
          "r"(__float_as_uint(a[2])), "r"(__float_as_uint(a[3])),
          "r"(__float_as_uint(b0)),   "r"(__float_as_uint(b1)));
}

// ---------------- tensor-core tf32 GEMM: C = epi(A[MxK] @ B[KxN] + bias) -------
// CTA 128 x TN, 256 threads (8 warps: 2 row x 4 col), warp tile 64 x TN/4 (MI=4).
// K staged by 32 (4 mma k-steps), 4-buffer cp.async pipeline (dist 3),
// register double-buffered fragments across k-steps.
// EPI: 0 = bias, 1 = bias+GELU, 2 = bias+residual, 3 = bias+GLU(even,odd)
template<int TN, int EPI>
__global__ void __launch_bounds__(256,1) mma_gemm_k(
    const float* __restrict__ A, const float* __restrict__ B,
    const float* __restrict__ bias, const float* __restrict__ res,
    float* __restrict__ C, int M, int N, int Kd, float rscale, int Cs)
{
    constexpr int WN   = TN/4;
    constexpr int NJ   = WN/8;
    constexpr int BROW = TN + 8;
    constexpr int ASZ  = 128*36;
    constexpr int BSZ  = 32*BROW;
    constexpr int NSEG = TN/4;

    extern __shared__ __align__(16) float smem[];
    float* As = smem;                 // [4][128][36]
    float* Bs = smem + 4*ASZ;         // [4][32][BROW]

    int tid = threadIdx.x, lane = tid & 31, wid = tid >> 5;
    int wr = wid >> 2, wc = wid & 3;
    int g = lane >> 2, tg = lane & 3;
    int row0 = blockIdx.y*128, col0 = blockIdx.x*TN;

    const float* Ag = A + (size_t)row0*Kd;
    const float* Bg = B + col0;
    uint32_t sA = (uint32_t)__cvta_generic_to_shared(As);
    uint32_t sB = (uint32_t)__cvta_generic_to_shared(Bs);

    auto loadA = [&](int kt){
        int k0 = kt*32;
        uint32_t base = sA + (kt & 3)*(ASZ*4);
        #pragma unroll
        for (int i = 0; i < 4; i++){
            int f = tid + i*256;
            int m = f >> 3, seg = f & 7;
            cpasync16(base + (uint32_t)(m*144 + seg*16),
                      Ag + (size_t)m*Kd + k0 + seg*4);
        }
    };
    auto loadB = [&](int kt){
        int k0 = kt*32;
        uint32_t base = sB + (kt & 3)*(BSZ*4);
        #pragma unroll
        for (int i = 0; i < (32*NSEG)/256; i++){
            int f = tid + i*256;
            int k = f / NSEG, s = f % NSEG;
            cpasync16(base + (uint32_t)(k*(BROW*4) + s*16),
                      Bg + (size_t)(k0+k)*N + s*4);
        }
    };

    float acc[4][NJ][4];
    #pragma unroll
    for (int mi=0;mi<4;mi++)
        #pragma unroll
        for (int nj=0;nj<NJ;nj++)
            #pragma unroll
            for (int q=0;q<4;q++) acc[mi][nj][q]=0.f;

    int nk = Kd >> 5;
    loadA(0); loadB(0); CP_COMMIT();
    loadA(1); loadB(1); CP_COMMIT();
    loadA(2); loadB(2); CP_COMMIT();

    float af[2][4][4], bf[2][NJ][2];

    for (int kt = 0; kt < nk; ++kt){
        cp_wait<2>();
        __syncthreads();
        if (kt + 3 < nk){ loadA(kt+3); loadB(kt+3); }
        CP_COMMIT();

        int buf = kt & 3;
        const float* Ab = As + buf*ASZ + (wr*64)*36;
        const float* Bb = Bs + buf*BSZ + wc*WN;

        // prime fragments for ks=0
        #pragma unroll
        for (int mi=0;mi<4;mi++){
            const float* ap = Ab + (mi*16 + g)*36 + tg;
            af[0][mi][0] = ap[0];
            af[0][mi][1] = ap[8*36];
            af[0][mi][2] = ap[4];
            af[0][mi][3] = ap[8*36 + 4];
        }
        #pragma unroll
        for (int nj=0;nj<NJ;nj++){
            bf[0][nj][0] = Bb[(tg  )*BROW + nj*8 + g];
            bf[0][nj][1] = Bb[(tg+4)*BROW + nj*8 + g];
        }
        #pragma unroll
        for (int ks = 0; ks < 4; ++ks){
            int cur = ks & 1, nxt = cur ^ 1;
            if (ks < 3){
                int k0 = (ks+1)*8;
                #pragma unroll
                for (int mi=0;mi<4;mi++){
                    const float* ap = Ab + (mi*16 + g)*36 + k0 + tg;
                    af[nxt][mi][0] = ap[0];
                    af[nxt][mi][1] = ap[8*36];
                    af[nxt][mi][2] = ap[4];
                    af[nxt][mi][3] = ap[8*36 + 4];
                }
                #pragma unroll
                for (int nj=0;nj<NJ;nj++){
                    bf[nxt][nj][0] = Bb[(k0+tg  )*BROW + nj*8 + g];
                    bf[nxt][nj][1] = Bb[(k0+tg+4)*BROW + nj*8 + g];
                }
            }
            #pragma unroll
            for (int nj=0;nj<NJ;nj++)
                #pragma unroll
                for (int mi=0;mi<4;mi++)
                    mma8(acc[mi][nj], af[cur][mi], bf[cur][nj][0], bf[cur][nj][1]);
        }
    }

    // epilogue
    #pragma unroll
    for (int nj=0;nj<NJ;nj++){
        int c = col0 + wc*WN + nj*8 + tg*2;
        float2 bi = *(const float2*)&bias[c];
        #pragma unroll
        for (int mi=0;mi<4;mi++){
            int r0 = row0 + wr*64 + mi*16 + g;
            float v0 = acc[mi][nj][0] + bi.x;
            float v1 = acc[mi][nj][1] + bi.y;
            float v2 = acc[mi][nj][2] + bi.x;
            float v3 = acc[mi][nj][3] + bi.y;
            if (EPI == 1){ v0=gelu_f(v0); v1=gelu_f(v1); v2=gelu_f(v2); v3=gelu_f(v3); }
            if (EPI == 2){
                float2 r0v = *(const float2*)&res[(size_t)r0*Cs + c];
                float2 r1v = *(const float2*)&res[(size_t)(r0+8)*Cs + c];
                v0 = fmaf(rscale, v0, r0v.x); v1 = fmaf(rscale, v1, r0v.y);
                v2 = fmaf(rscale, v2, r1v.x); v3 = fmaf(rscale, v3, r1v.y);
            }
            if (EPI == 3){
                int co = (c >> 1);   // pairs (even,odd) -> one GLU output
                C[(size_t)r0*Cs + co]     = v0 * sigm(v1);
                C[(size_t)(r0+8)*Cs + co] = v2 * sigm(v3);
            } else {
                *(float2*)&C[(size_t)r0*Cs + c]     = make_float2(v0, v1);
                *(float2*)&C[(size_t)(r0+8)*Cs + c] = make_float2(v2, v3);
            }
        }
    }
}

// ---------------- pw1 weight interleave: wp[:,2c]=w[:,c], wp[:,2c+1]=w[:,c+512] ----
__global__ void permute_pw1_k(const float* __restrict__ w, const float* __restrict__ b,
                              float* __restrict__ wp){
    int o = blockIdx.x*256 + threadIdx.x;      // 512*1024
    int row = o >> 10, c = o & 1023;
    int j = (c >> 1) + (c & 1)*512;
    wp[o] = w[row*1024 + j];
    if (o < 1024) wp[512*1024 + o] = b[(o >> 1) + (o & 1)*512];
}

// ---------------- transposes ----------------
__global__ void transpose_bdt_btd(const float* __restrict__ in, float* __restrict__ out){
    __shared__ float tile[32][33];
    int b = blockIdx.z;
    int t0 = blockIdx.x*32, d0 = blockIdx.y*32;
    int lx = threadIdx.x, ly = threadIdx.y;
    #pragma unroll
    for (int i=0;i<32;i+=8)
        tile[ly+i][lx] = in[((size_t)b*512 + d0+ly+i)*1024 + t0 + lx];
    __syncthreads();
    #pragma unroll
    for (int i=0;i<32;i+=8)
        out[((size_t)b*1024 + t0+ly+i)*512 + d0 + lx] = tile[lx][ly+i];
}
__global__ void transpose_btd_bdt(const float* __restrict__ in, float* __restrict__ out){
    __shared__ float tile[32][33];
    int b = blockIdx.z;
    int d0 = blockIdx.x*32, t0 = blockIdx.y*32;
    int lx = threadIdx.x, ly = threadIdx.y;
    #pragma unroll
    for (int i=0;i<32;i+=8)
        tile[ly+i][lx] = in[((size_t)b*1024 + t0+ly+i)*512 + d0 + lx];
    __syncthreads();
    #pragma unroll
    for (int i=0;i<32;i+=8)
        out[((size_t)b*512 + d0+ly+i)*1024 + t0 + lx] = tile[lx][ly+i];
}

// ---------------- relative-position bias table ----------------
__global__ void build_dd_k(const float* __restrict__ rel_embed, float* __restrict__ ddt){
    int idx = blockIdx.x*256 + threadIdx.x;
    if (idx >= 8*2047) return;
    int h = idx / 2047;
    int rpos = idx % 2047;
    int rel = rpos - 1023;
    int sign = (rel >= 0) ? 1 : 0;
    int a = (rel >= 0) ? rel : -rel;
    int bucket;
    if (a < 80) bucket = a;
    else {
        float lr = logf((float)a / 80.0f) / logf(10.0f);
        int lp = 80 + (int)(lr * 80.0f);
        bucket = (lp < 159) ? lp : 159;
    }
    bucket += sign*160;
    if (bucket < 0) bucket = 0;
    if (bucket > 319) bucket = 319;
    ddt[h*2047 + rpos] = rel_embed[bucket*8 + h];
}

// ---------------- tensor-core flash attention with gated rel-pos bias ----------
__global__ void __launch_bounds__(128) flash_mma_k(
    const float* __restrict__ qkv,     // [B,T,3,H,DH] row stride 1536
    const float* __restrict__ gate_u, const float* __restrict__ gate_w,
    const float* __restrict__ gate_scale, const float* __restrict__ ddt,
    float* __restrict__ out)           // [B,T,512]
{
    extern __shared__ float sm[];
    float* Qs    = sm;                 // [64][68]
    float* Ks    = Qs + 64*68;         // [64][72]  K transposed: Ks[d][s]
    float* Vs    = Ks + 64*72;         // [64][72]  Vs[s][d]
    float* Ps    = Vs + 64*72;         // [64][68]
    float* dds   = Ps + 64*68;         // [128]
    float* coefs = dds + 128;          // [64]

    int tid = threadIdx.x, lane = tid & 31, wid = tid >> 5;
    int g = lane >> 2, tg = lane & 3;
    int t0 = blockIdx.x * 64;
    int h  = blockIdx.y;
    int b  = blockIdx.z;
    int m0 = wid * 16;

    const float* qbase = qkv + (size_t)b*1024*1536 + h*64;
    const float* kbase = qbase + 512;
    const float* vbase = qbase + 1024;

    {
        int m = tid >> 1, half = (tid & 1) * 32;
        const float* qrow = qbase + (size_t)(t0+m)*1536 + half;
        #pragma unroll
        for (int i=0;i<8;i++)
            *(float4*)&Qs[m*68 + half + i*4] = *(const float4*)(qrow + i*4);
    }
    __syncthreads();
    if (tid < 64){
        float du=0.f, dw=0.f;
        #pragma unroll
        for (int d=0; d<64; d++){
            float qv = Qs[tid*68 + d];
            du = fmaf(qv, gate_u[h*64+d], du);
            dw = fmaf(qv, gate_w[h*64+d], dw);
        }
        float gu = sigm(du), gr = sigm(dw);
        coefs[tid] = 1.0f + gu + (1.0f-gu)*gate_scale[h]*gr;
    }
    float qf[8][4];
    #pragma unroll
    for (int ks=0;ks<8;ks++){
        qf[ks][0] = Qs[(m0+g  )*68 + ks*8 + tg];
        qf[ks][1] = Qs[(m0+g+8)*68 + ks*8 + tg];
        qf[ks][2] = Qs[(m0+g  )*68 + ks*8 + tg + 4];
        qf[ks][3] = Qs[(m0+g+8)*68 + ks*8 + tg + 4];
    }

    float m_run[2] = {-3.0e38f, -3.0e38f}, l_run[2] = {0.f, 0.f};
    float O[8][4];
    #pragma unroll
    for (int nd=0;nd<8;nd++)
        #pragma unroll
        for (int q=0;q<4;q++) O[nd][q]=0.f;

    for (int s0 = 0; s0 < 1024; s0 += 64){
        __syncthreads();
        {
            int m = tid >> 1, half = (tid & 1) * 32;
            const float* krow = kbase + (size_t)(s0+m)*1536 + half;
            const float* vrow = vbase + (size_t)(s0+m)*1536 + half;
            #pragma unroll
            for (int i=0;i<8;i++){
                float4 kv = *(const float4*)(krow + i*4);
                int d = half + i*4;
                Ks[(d+0)*72+m]=kv.x; Ks[(d+1)*72+m]=kv.y;
                Ks[(d+2)*72+m]=kv.z; Ks[(d+3)*72+m]=kv.w;
                *(float4*)&Vs[m*72 + d] = *(const float4*)(vrow + i*4);
            }
        }
        if (tid < 127) dds[tid] = ddt[h*2047 + 960 + (s0 - t0) + tid];
        __syncthreads();

        float S[8][4];
        #pragma unroll
        for (int nj=0;nj<8;nj++)
            #pragma unroll
            for (int q=0;q<4;q++) S[nj][q]=0.f;
        #pragma unroll
        for (int ks=0;ks<8;ks++){
            #pragma unroll
            for (int nj=0;nj<8;nj++){
                float b0 = Ks[(ks*8+tg  )*72 + nj*8 + g];
                float b1 = Ks[(ks*8+tg+4)*72 + nj*8 + g];
                mma8(S[nj], qf[ks], b0, b1);
            }
        }
        float c0 = coefs[m0+g], c1 = coefs[m0+g+8];
        #pragma unroll
        for (int nj=0;nj<8;nj++){
            int cn = nj*8 + tg*2;
            float dd0 = dds[cn     - (m0+g)   + 63];
            float dd1 = dds[cn + 1 - (m0+g)   + 63];
            float dd2 = dds[cn     - (m0+g+8) + 63];
            float dd3 = dds[cn + 1 - (m0+g+8) + 63];
            S[nj][0] = fmaf(S[nj][0], 0.125f, c0*dd0);
            S[nj][1] = fmaf(S[nj][1], 0.125f, c0*dd1);
            S[nj][2] = fmaf(S[nj][2], 0.125f, c1*dd2);
            S[nj][3] = fmaf(S[nj][3], 0.125f, c1*dd3);
        }
        #pragma unroll
        for (int i=0;i<2;i++){
            float mx = -3.0e38f;
            #pragma unroll
            for (int nj=0;nj<8;nj++) mx = fmaxf(mx, fmaxf(S[nj][2*i], S[nj][2*i+1]));
            mx = fmaxf(mx, __shfl_xor_sync(0xffffffffu, mx, 1));
            mx = fmaxf(mx, __shfl_xor_sync(0xffffffffu, mx, 2));
            float mo = fmaxf(m_run[i], mx);
            float alpha = __expf(m_run[i] - mo);
            m_run[i] = mo;
            float ls = 0.f;
            #pragma unroll
            for (int nj=0;nj<8;nj++){
                float p0 = __expf(S[nj][2*i]   - mo);
                float p1 = __expf(S[nj][2*i+1] - mo);
                S[nj][2*i] = p0; S[nj][2*i+1] = p1;
                ls += p0 + p1;
            }
            ls += __shfl_xor_sync(0xffffffffu, ls, 1);
            ls += __shfl_xor_sync(0xffffffffu, ls, 2);
            l_run[i] = l_run[i]*alpha + ls;
            #pragma unroll
            for (int nd=0;nd<8;nd++){ O[nd][2*i] *= alpha; O[nd][2*i+1] *= alpha; }
        }
        #pragma unroll
        for (int nj=0;nj<8;nj++){
            *(float2*)&Ps[(m0+g  )*68 + nj*8 + tg*2] = make_float2(S[nj][0], S[nj][1]);
            *(float2*)&Ps[(m0+g+8)*68 + nj*8 + tg*2] = make_float2(S[nj][2], S[nj][3]);
        }
        __syncwarp();
        #pragma unroll
        for (int ko=0;ko<8;ko++){
            float pa[4];
            pa[0] = Ps[(m0+g  )*68 + ko*8 + tg];
            pa[1] = Ps[(m0+g+8)*68 + ko*8 + tg];
            pa[2] = Ps[(m0+g  )*68 + ko*8 + tg + 4];
            pa[3] = Ps[(m0+g+8)*68 + ko*8 + tg + 4];
            #pragma unroll
            for (int nd=0;nd<8;nd++){
                float b0 = Vs[(ko*8+tg  )*72 + nd*8 + g];
                float b1 = Vs[(ko*8+tg+4)*72 + nd*8 + g];
                mma8(O[nd], pa, b0, b1);
            }
        }
    }
    float inv0 = 1.0f / l_run[0], inv1 = 1.0f / l_run[1];
    int r0 = t0 + m0 + g;
    #pragma unroll
    for (int nd=0;nd<8;nd++){
        int c = h*64 + nd*8 + tg*2;
        *(float2*)&out[((size_t)(b*1024 + r0  ))*512 + c] = make_float2(O[nd][0]*inv0, O[nd][1]*inv0);
        *(float2*)&out[((size_t)(b*1024 + r0+8))*512 + c] = make_float2(O[nd][2]*inv1, O[nd][3]*inv1);
    }
}

// ---------------- GroupNorm(1, C): deterministic 2-level reduction ----
__global__ void gn_partial_k(const float* __restrict__ x, float2* __restrict__ part){
    int b = blockIdx.x >> 8;
    int blk = blockIdx.x & 255;
    const float* p = x + (size_t)b*524288 + (size_t)blk*2048;
    float s=0.f, q=0.f;
    for (int i=threadIdx.x; i<512; i+=256){
        float4 v = *(const float4*)(p + i*4);
        s += v.x+v.y+v.z+v.w;
        q = fmaf(v.x,v.x,fmaf(v.y,v.y,fmaf(v.z,v.z,fmaf(v.w,v.w,q))));
    }
    __shared__ float ss[256], sq[256];
    ss[threadIdx.x]=s; sq[threadIdx.x]=q;
    __syncthreads();
    for (int o=128;o>0;o>>=1){
        if (threadIdx.x<o){ ss[threadIdx.x]+=ss[threadIdx.x+o]; sq[threadIdx.x]+=sq[threadIdx.x+o]; }
        __syncthreads();
    }
    if (threadIdx.x==0) part[blockIdx.x] = make_float2(ss[0], sq[0]);
}
__global__ void gn_final_k(const float2* __restrict__ part, float2* __restrict__ mv){
    int b = blockIdx.x;
    float2 v = part[b*256 + threadIdx.x];
    __shared__ float ss[256], sq[256];
    ss[threadIdx.x]=v.x; sq[threadIdx.x]=v.y;
    __syncthreads();
    for (int o=128;o>0;o>>=1){
        if (threadIdx.x<o){ ss[threadIdx.x]+=ss[threadIdx.x+o]; sq[threadIdx.x]+=sq[threadIdx.x+o]; }
        __syncthreads();
    }
    if (threadIdx.x==0){
        float mean = ss[0]*(1.0f/524288.0f);
        float var  = sq[0]*(1.0f/524288.0f) - mean*mean;
        mv[b] = make_float2(mean, rsqrtf(var + 1e-5f));
    }
}
template<bool SILU_>
__global__ void gn_apply_k(const float* __restrict__ x, const float2* __restrict__ mv,
                           const float* __restrict__ g, const float* __restrict__ be,
                           float* __restrict__ y){
    size_t i4 = (size_t)blockIdx.x*256 + threadIdx.x;
    int b = (int)(i4 >> 17);
    int d = (int)((i4 & 127) << 2);
    float2 m = mv[b];
    float4 xv = *(const float4*)(x + i4*4);
    float4 gv = *(const float4*)(g + d);
    float4 bv = *(const float4*)(be + d);
    float4 o;
    o.x = (xv.x-m.x)*m.y*gv.x + bv.x;
    o.y = (xv.y-m.x)*m.y*gv.y + bv.y;
    o.z = (xv.z-m.x)*m.y*gv.z + bv.z;
    o.w = (xv.w-m.x)*m.y*gv.w + bv.w;
    if (SILU_){
        o.x *= sigm(o.x); o.y *= sigm(o.y); o.z *= sigm(o.z); o.w *= sigm(o.w);
    }
    *(float4*)(y + i4*4) = o;
}

// ---------------- depthwise conv ----------------
__global__ void dwconv_k(const float* __restrict__ in, const float* __restrict__ w,
                         const float* __restrict__ bias, float* __restrict__ out){
    int d = threadIdx.x;               // 512
    int t = blockIdx.x & 1023;
    int b = blockIdx.x >> 10;
    const float* base = in + (size_t)b*1024*512 + d;
    float acc = bias[d];
    #pragma unroll
    for (int k=0;k<31;k++){
        int tt = t + k - 15;
        if (tt >= 0 && tt < 1024)
            acc = fmaf(base[(size_t)tt*512], w[d*31+k], acc);
    }
    out[((size_t)b*1024 + t)*512 + d] = acc;
}

// ---------------- launch ----------------
extern "C" void kernel_launch(void* const* d_in, const int* in_sizes, int n_in,
                              void* d_out, int out_size) {
    const float* x      = (const float*)d_in[0];
    const float* ff1_w1 = (const float*)d_in[1];
    const float* ff1_b1 = (const float*)d_in[2];
    const float* ff1_w2 = (const float*)d_in[3];
    const float* ff1_b2 = (const float*)d_in[4];
    const float* qkv_w  = (const float*)d_in[5];
    const float* qkv_b  = (const float*)d_in[6];
    const float* out_w  = (const float*)d_in[7];
    const float* out_b  = (const float*)d_in[8];
    const float* gn1_g  = (const float*)d_in[9];
    const float* gn1_b  = (const float*)d_in[10];
    const float* pw1_w  = (const float*)d_in[11];
    const float* pw1_b  = (const float*)d_in[12];
    const float* dw_w   = (const float*)d_in[13];
    const float* dw_b   = (const float*)d_in[14];
    const float* gn2_g  = (const float*)d_in[15];
    const float* gn2_b  = (const float*)d_in[16];
    const float* pw2_w  = (const float*)d_in[17];
    const float* pw2_b  = (const float*)d_in[18];
    const float* ff2_w1 = (const float*)d_in[19];
    const float* ff2_b1 = (const float*)d_in[20];
    const float* ff2_w2 = (const float*)d_in[21];
    const float* ff2_b2 = (const float*)d_in[22];
    const float* rel_e  = (const float*)d_in[23];
    const float* gate_u = (const float*)d_in[24];
    const float* gate_w = (const float*)d_in[25];
    const float* gate_s = (const float*)d_in[26];

    float *S, *T1, *T2, *T3, *DDp, *WP; float2 *PART, *MV;
    cudaGetSymbolAddress((void**)&S,  g_S);
    cudaGetSymbolAddress((void**)&T1, g_T1);
    cudaGetSymbolAddress((void**)&T2, g_T2);
    cudaGetSymbolAddress((void**)&T3, g_T3);
    cudaGetSymbolAddress((void**)&DDp,g_DD);
    cudaGetSymbolAddress((void**)&WP, g_WP);
    cudaGetSymbolAddress((void**)&PART, g_part);
    cudaGetSymbolAddress((void**)&MV,   g_mv);

    const int FLASH_SMEM = (64*68 + 64*72 + 64*72 + 64*68 + 128 + 64) * 4;  // 72448
    cudaFuncSetAttribute((const void*)flash_mma_k,
                         cudaFuncAttributeMaxDynamicSharedMemorySize, FLASH_SMEM);
    const int GS256 = (4*128*36 + 4*32*264) * 4;   // 208896
    const int GS128 = (4*128*36 + 4*32*136) * 4;   // 143360
    cudaFuncSetAttribute(mma_gemm_k<256,0>, cudaFuncAttributeMaxDynamicSharedMemorySize, GS256);
    cudaFuncSetAttribute(mma_gemm_k<256,1>, cudaFuncAttributeMaxDynamicSharedMemorySize, GS256);
    cudaFuncSetAttribute(mma_gemm_k<256,3>, cudaFuncAttributeMaxDynamicSharedMemorySize, GS256);
    cudaFuncSetAttribute(mma_gemm_k<128,2>, cudaFuncAttributeMaxDynamicSharedMemorySize, GS128);

    dim3 tb(32,8);
    // x -> s [B,T,D]
    transpose_bdt_btd<<<dim3(32,16,4), tb>>>(x, S);
    build_dd_k<<<64,256>>>(rel_e, DDp);
    permute_pw1_k<<<2048,256>>>(pw1_w, pw1_b, WP);
    // FFN1 (half-step)
    mma_gemm_k<256,1><<<dim3( 8,32),256,GS256>>>(S,  ff1_w1, ff1_b1, nullptr, T1, 4096,2048, 512, 0.f, 2048);
    mma_gemm_k<128,2><<<dim3( 4,32),256,GS128>>>(T1, ff1_w2, ff1_b2, S,       S,  4096, 512,2048, 0.5f, 512);
    // QKV
    mma_gemm_k<256,0><<<dim3( 6,32),256,GS256>>>(S,  qkv_w,  qkv_b,  nullptr, T1, 4096,1536, 512, 0.f, 1536);
    // attention
    flash_mma_k<<<dim3(16,8,4),128,FLASH_SMEM>>>(T1, gate_u, gate_w, gate_s, DDp, T2);
    mma_gemm_k<128,2><<<dim3( 4,32),256,GS128>>>(T2, out_w,  out_b,  S,       S,  4096, 512, 512, 1.0f, 512);
    // conv module
    gn_partial_k<<<1024,256>>>(S, PART);
    gn_final_k<<<4,256>>>(PART, MV);
    gn_apply_k<false><<<2048,256>>>(S, MV, gn1_g, gn1_b, T2);
    // pw1 + fused GLU (permuted weights) -> T3 [4096,512]
    mma_gemm_k<256,3><<<dim3( 4,32),256,GS256>>>(T2, WP, WP + 512*1024, nullptr, T3, 4096,1024, 512, 0.f, 512);
    dwconv_k<<<4096,512>>>(T3, dw_w, dw_b, T2);
    gn_partial_k<<<1024,256>>>(T2, PART);
    gn_final_k<<<4,256>>>(PART, MV);
    gn_apply_k<true><<<2048,256>>>(T2, MV, gn2_g, gn2_b, T3);
    mma_gemm_k<128,2><<<dim3( 4,32),256,GS128>>>(T3, pw2_w,  pw2_b,  S,       S,  4096, 512, 512, 1.0f, 512);
    // FFN2 (half-step)
    mma_gemm_k<256,1><<<dim3( 8,32),256,GS256>>>(S,  ff2_w1, ff2_b1, nullptr, T1, 4096,2048, 512, 0.f, 2048);
    mma_gemm_k<128,2><<<dim3( 4,32),256,GS128>>>(T1, ff2_w2, ff2_b2, S,       S,  4096, 512,2048, 0.5f, 512);
    // s -> out [B,D,T]
    transpose_btd_bdt<<<dim3(16,32,4), tb>>>(S, (float*)d_out);
}

// round 7
// speedup vs baseline: 2.6733x; 1.2215x over previous
#include <cuda_runtime.h>
#include <cuda_fp16.h>
#include <math.h>
#include <cstdint>

// ---------------- scratch (device globals; allocation-free rule) ----------------
__device__ float  g_S [4096*512];      // residual stream fp32 [B,T,D]
__device__ float  g_T1[4096*1536];     // qkv out fp32
__device__ float  g_T2[4096*512];      // gn in / dwconv out
__device__ float  g_T3[4096*512];      // GLU out (dwconv in)
__device__ __half g_Sh [4096*512];     // fp16 mirror of S
__device__ __half g_T1h[4096*2048];    // ffn hidden fp16
__device__ __half g_T2h[4096*512];     // flash out / gn1 out fp16
__device__ __half g_T3h[4096*512];     // gn2 out fp16
__device__ __half g_W  [6029312];      // all transposed fp16 weights
__device__ float  g_BP [1024];         // permuted pw1 bias
__device__ float  g_DD [8*2047];       // rel-pos bias table
__device__ float2 g_part[1024];
__device__ float2 g_mv[4];

// weight offsets (halves)
#define W_FF1A 0u
#define W_FF1B 1048576u
#define W_QKV  2097152u
#define W_OUT  2883584u
#define W_PW1  3145728u
#define W_PW2  3670016u
#define W_FF2A 3932160u
#define W_FF2B 4980736u

__device__ __forceinline__ float gelu_f(float x){
    return 0.5f * x * (1.0f + erff(x * 0.70710678118654752440f));
}
__device__ __forceinline__ float sigm(float x){ return 1.0f/(1.0f + expf(-x)); }

// ---------------- async-copy helpers ----------------
__device__ __forceinline__ void cpasync16(uint32_t dst, const void* src){
    asm volatile("cp.async.ca.shared.global [%0], [%1], 16;" :: "r"(dst), "l"(src));
}
#define CP_COMMIT() asm volatile("cp.async.commit_group;" ::: "memory")
template<int N>
__device__ __forceinline__ void cp_wait(){
    asm volatile("cp.async.wait_group %0;" :: "n"(N) : "memory");
}

// fp16 warp MMA: D(16x8,f32) += A(16x16,f16) * B(16x8,f16)
__device__ __forceinline__ void mma16(float* c, const uint32_t* a, uint32_t b0, uint32_t b1){
    asm volatile(
        "mma.sync.aligned.m16n8k16.row.col.f32.f16.f16.f32 "
        "{%0,%1,%2,%3},{%4,%5,%6,%7},{%8,%9},{%0,%1,%2,%3};"
        : "+f"(c[0]), "+f"(c[1]), "+f"(c[2]), "+f"(c[3])
        : "r"(a[0]), "r"(a[1]), "r"(a[2]), "r"(a[3]), "r"(b0), "r"(b1));
}
// tf32 warp MMA (flash keeps fp32 inputs)
__device__ __forceinline__ void mma8(float* c, const float* a, float b0, float b1){
    asm volatile(
        "mma.sync.aligned.m16n8k8.row.col.f32.tf32.tf32.f32 "
        "{%0,%1,%2,%3},{%4,%5,%6,%7},{%8,%9},{%0,%1,%2,%3};"
        : "+f"(c[0]), "+f"(c[1]), "+f"(c[2]), "+f"(c[3])
        : "r"(__float_as_uint(a[0])), "r"(__float_as_uint(a[1])),
          "r"(__float_as_uint(a[2])), "r"(__float_as_uint(a[3])),
          "r"(__float_as_uint(b0)),   "r"(__float_as_uint(b1)));
}

// ---------------- fp16 tensor GEMM: C = epi(A[MxK] @ B^T + bias) -------------
// A fp16 [M][Kd]; B fp16 [N][Kd] (pre-transposed). CTA 128 x TN, 256 threads,
// 8 warps (2 row x 4 col), warp tile 64 x TN/4. K staged by 32 (2 k16 steps),
// 4-buffer cp.async pipeline.
// EPI: 0=bias->f32 | 1=bias+GELU->f16 | 2=bias+res->f32+f16 | 3=bias+GLU->f32
template<int TN, int EPI>
__global__ void __launch_bounds__(256,1) hgemm_k(
    const __half* __restrict__ A, const __half* __restrict__ B,
    const float* __restrict__ bias, const float* __restrict__ res,
    float* __restrict__ C, __half* __restrict__ Ch,
    int Kd, float rscale, int Cs)
{
    constexpr int WN   = TN/4;
    constexpr int NJ   = WN/8;
    constexpr int A_ST = 128*40;           // halves per A stage
    constexpr int B_ST = TN*40;            // halves per B stage

    extern __shared__ __align__(16) __half smh[];
    __half* Ash = smh;                     // [4][128][40]
    __half* Bsh = smh + 4*A_ST;            // [4][TN][40]

    int tid = threadIdx.x, lane = tid & 31, wid = tid >> 5;
    int wr = wid >> 2, wc = wid & 3;
    int g = lane >> 2, tg = lane & 3;
    int row0 = blockIdx.y*128, col0 = blockIdx.x*TN;

    const __half* Ag = A + (size_t)row0*Kd;
    const __half* Bg = B + (size_t)col0*Kd;
    uint32_t sA = (uint32_t)__cvta_generic_to_shared(Ash);
    uint32_t sB = (uint32_t)__cvta_generic_to_shared(Bsh);

    auto loadA = [&](int kt){
        int k0 = kt*32;
        uint32_t base = sA + (kt & 3)*(A_ST*2);
        #pragma unroll
        for (int i = 0; i < 2; i++){
            int f = tid + i*256;
            int m = f >> 2, seg = f & 3;
            cpasync16(base + (uint32_t)(m*80 + seg*16),
                      Ag + (size_t)m*Kd + k0 + seg*8);
        }
    };
    auto loadB = [&](int kt){
        int k0 = kt*32;
        uint32_t base = sB + (kt & 3)*(B_ST*2);
        #pragma unroll
        for (int i = 0; i < TN/64; i++){
            int f = tid + i*256;
            int n = f >> 2, seg = f & 3;
            cpasync16(base + (uint32_t)(n*80 + seg*16),
                      Bg + (size_t)n*Kd + k0 + seg*8);
        }
    };

    float acc[4][NJ][4];
    #pragma unroll
    for (int mi=0;mi<4;mi++)
        #pragma unroll
        for (int nj=0;nj<NJ;nj++)
            #pragma unroll
            for (int q=0;q<4;q++) acc[mi][nj][q]=0.f;

    int nk = Kd >> 5;
    loadA(0); loadB(0); CP_COMMIT();
    loadA(1); loadB(1); CP_COMMIT();
    loadA(2); loadB(2); CP_COMMIT();

    for (int kt = 0; kt < nk; ++kt){
        cp_wait<2>();
        __syncthreads();
        if (kt + 3 < nk){ loadA(kt+3); loadB(kt+3); }
        CP_COMMIT();

        int buf = kt & 3;
        const __half* Ab = Ash + buf*A_ST + (wr*64)*40;
        const __half* Bb = Bsh + buf*B_ST + (wc*WN)*40;
        #pragma unroll
        for (int ks = 0; ks < 2; ++ks){
            int k0h = ks*16;
            uint32_t a[4][4];
            #pragma unroll
            for (int mi=0;mi<4;mi++){
                const __half* ap = Ab + (mi*16+g)*40 + k0h + 2*tg;
                a[mi][0] = *(const uint32_t*)ap;
                a[mi][1] = *(const uint32_t*)(ap + 8*40);
                a[mi][2] = *(const uint32_t*)(ap + 8);
                a[mi][3] = *(const uint32_t*)(ap + 8*40 + 8);
            }
            #pragma unroll
            for (int nj=0;nj<NJ;nj++){
                const __half* bp = Bb + (nj*8+g)*40 + k0h + 2*tg;
                uint32_t b0 = *(const uint32_t*)bp;
                uint32_t b1 = *(const uint32_t*)(bp + 8);
                #pragma unroll
                for (int mi=0;mi<4;mi++)
                    mma16(acc[mi][nj], a[mi], b0, b1);
            }
        }
    }

    // epilogue
    #pragma unroll
    for (int nj=0;nj<NJ;nj++){
        int c = col0 + wc*WN + nj*8 + tg*2;
        float2 bi = *(const float2*)&bias[c];
        #pragma unroll
        for (int mi=0;mi<4;mi++){
            int r0 = row0 + wr*64 + mi*16 + g;
            float v0 = acc[mi][nj][0] + bi.x;
            float v1 = acc[mi][nj][1] + bi.y;
            float v2 = acc[mi][nj][2] + bi.x;
            float v3 = acc[mi][nj][3] + bi.y;
            if (EPI == 1){
                v0=gelu_f(v0); v1=gelu_f(v1); v2=gelu_f(v2); v3=gelu_f(v3);
                *(__half2*)&Ch[(size_t)r0*Cs + c]     = __floats2half2_rn(v0, v1);
                *(__half2*)&Ch[(size_t)(r0+8)*Cs + c] = __floats2half2_rn(v2, v3);
            } else if (EPI == 2){
                float2 r0v = *(const float2*)&res[(size_t)r0*Cs + c];
                float2 r1v = *(const float2*)&res[(size_t)(r0+8)*Cs + c];
                v0 = fmaf(rscale, v0, r0v.x); v1 = fmaf(rscale, v1, r0v.y);
                v2 = fmaf(rscale, v2, r1v.x); v3 = fmaf(rscale, v3, r1v.y);
                *(float2*)&C[(size_t)r0*Cs + c]     = make_float2(v0, v1);
                *(float2*)&C[(size_t)(r0+8)*Cs + c] = make_float2(v2, v3);
                *(__half2*)&Ch[(size_t)r0*Cs + c]     = __floats2half2_rn(v0, v1);
                *(__half2*)&Ch[(size_t)(r0+8)*Cs + c] = __floats2half2_rn(v2, v3);
            } else if (EPI == 3){
                int co = c >> 1;
                C[(size_t)r0*Cs + co]     = v0 * sigm(v1);
                C[(size_t)(r0+8)*Cs + co] = v2 * sigm(v3);
            } else {
                *(float2*)&C[(size_t)r0*Cs + c]     = make_float2(v0, v1);
                *(float2*)&C[(size_t)(r0+8)*Cs + c] = make_float2(v2, v3);
            }
        }
    }
}

// ---------------- weight transpose+convert: fp32 [K][N] -> fp16 [n][K] ---------
__global__ void wconv_t(const float* __restrict__ in, __half* __restrict__ out,
                        int K, int N, int colOff, unsigned outBase, int rowStride){
    __shared__ float t[32][33];
    int n0 = blockIdx.x*32, k0 = blockIdx.y*32;
    int lx = threadIdx.x, ly = threadIdx.y;
    #pragma unroll
    for (int i=0;i<32;i+=8)
        t[ly+i][lx] = in[(size_t)(k0+ly+i)*N + colOff + n0 + lx];
    __syncthreads();
    #pragma unroll
    for (int i=0;i<32;i+=8)
        out[outBase + (size_t)(n0+ly+i)*K*rowStride + k0 + lx] = __float2half(t[lx][ly+i]);
}
__global__ void bperm_k(const float* __restrict__ b, float* __restrict__ bp){
    int c = blockIdx.x*256 + threadIdx.x;
    if (c < 1024) bp[c] = b[(c>>1) + (c&1)*512];
}

// ---------------- transposes ----------------
__global__ void transpose_bdt_btd(const float* __restrict__ in, float* __restrict__ out,
                                  __half* __restrict__ outh){
    __shared__ float tile[32][33];
    int b = blockIdx.z;
    int t0 = blockIdx.x*32, d0 = blockIdx.y*32;
    int lx = threadIdx.x, ly = threadIdx.y;
    #pragma unroll
    for (int i=0;i<32;i+=8)
        tile[ly+i][lx] = in[((size_t)b*512 + d0+ly+i)*1024 + t0 + lx];
    __syncthreads();
    #pragma unroll
    for (int i=0;i<32;i+=8){
        float v = tile[lx][ly+i];
        size_t o = ((size_t)b*1024 + t0+ly+i)*512 + d0 + lx;
        out[o] = v;
        outh[o] = __float2half(v);
    }
}
__global__ void transpose_btd_bdt(const float* __restrict__ in, float* __restrict__ out){
    __shared__ float tile[32][33];
    int b = blockIdx.z;
    int d0 = blockIdx.x*32, t0 = blockIdx.y*32;
    int lx = threadIdx.x, ly = threadIdx.y;
    #pragma unroll
    for (int i=0;i<32;i+=8)
        tile[ly+i][lx] = in[((size_t)b*1024 + t0+ly+i)*512 + d0 + lx];
    __syncthreads();
    #pragma unroll
    for (int i=0;i<32;i+=8)
        out[((size_t)b*512 + d0+ly+i)*1024 + t0 + lx] = tile[lx][ly+i];
}

// ---------------- relative-position bias table ----------------
__global__ void build_dd_k(const float* __restrict__ rel_embed, float* __restrict__ ddt){
    int idx = blockIdx.x*256 + threadIdx.x;
    if (idx >= 8*2047) return;
    int h = idx / 2047;
    int rpos = idx % 2047;
    int rel = rpos - 1023;
    int sign = (rel >= 0) ? 1 : 0;
    int a = (rel >= 0) ? rel : -rel;
    int bucket;
    if (a < 80) bucket = a;
    else {
        float lr = logf((float)a / 80.0f) / logf(10.0f);
        int lp = 80 + (int)(lr * 80.0f);
        bucket = (lp < 159) ? lp : 159;
    }
    bucket += sign*160;
    if (bucket < 0) bucket = 0;
    if (bucket > 319) bucket = 319;
    ddt[h*2047 + rpos] = rel_embed[bucket*8 + h];
}

// ---------------- tensor-core flash attention with gated rel-pos bias ----------
__global__ void __launch_bounds__(128) flash_mma_k(
    const float* __restrict__ qkv,     // [B,T,3,H,DH] row stride 1536
    const float* __restrict__ gate_u, const float* __restrict__ gate_w,
    const float* __restrict__ gate_scale, const float* __restrict__ ddt,
    __half* __restrict__ outh)         // fp16 [B,T,512]
{
    extern __shared__ float sm[];
    float* Qs    = sm;                 // [64][68]
    float* Ks    = Qs + 64*68;         // [64][72]
    float* Vs    = Ks + 64*72;         // [64][72]
    float* Ps    = Vs + 64*72;         // [64][68]
    float* dds   = Ps + 64*68;         // [128]
    float* coefs = dds + 128;          // [64]

    int tid = threadIdx.x, lane = tid & 31, wid = tid >> 5;
    int g = lane >> 2, tg = lane & 3;
    int t0 = blockIdx.x * 64;
    int h  = blockIdx.y;
    int b  = blockIdx.z;
    int m0 = wid * 16;

    const float* qbase = qkv + (size_t)b*1024*1536 + h*64;
    const float* kbase = qbase + 512;
    const float* vbase = qbase + 1024;

    {
        int m = tid >> 1, half = (tid & 1) * 32;
        const float* qrow = qbase + (size_t)(t0+m)*1536 + half;
        #pragma unroll
        for (int i=0;i<8;i++)
            *(float4*)&Qs[m*68 + half + i*4] = *(const float4*)(qrow + i*4);
    }
    __syncthreads();
    if (tid < 64){
        float du=0.f, dw=0.f;
        #pragma unroll
        for (int d=0; d<64; d++){
            float qv = Qs[tid*68 + d];
            du = fmaf(qv, gate_u[h*64+d], du);
            dw = fmaf(qv, gate_w[h*64+d], dw);
        }
        float gu = sigm(du), gr = sigm(dw);
        coefs[tid] = 1.0f + gu + (1.0f-gu)*gate_scale[h]*gr;
    }
    float qf[8][4];
    #pragma unroll
    for (int ks=0;ks<8;ks++){
        qf[ks][0] = Qs[(m0+g  )*68 + ks*8 + tg];
        qf[ks][1] = Qs[(m0+g+8)*68 + ks*8 + tg];
        qf[ks][2] = Qs[(m0+g  )*68 + ks*8 + tg + 4];
        qf[ks][3] = Qs[(m0+g+8)*68 + ks*8 + tg + 4];
    }

    float m_run[2] = {-3.0e38f, -3.0e38f}, l_run[2] = {0.f, 0.f};
    float O[8][4];
    #pragma unroll
    for (int nd=0;nd<8;nd++)
        #pragma unroll
        for (int q=0;q<4;q++) O[nd][q]=0.f;

    for (int s0 = 0; s0 < 1024; s0 += 64){
        __syncthreads();
        {
            int m = tid >> 1, half = (tid & 1) * 32;
            const float* krow = kbase + (size_t)(s0+m)*1536 + half;
            const float* vrow = vbase + (size_t)(s0+m)*1536 + half;
            #pragma unroll
            for (int i=0;i<8;i++){
                float4 kv = *(const float4*)(krow + i*4);
                int d = half + i*4;
                Ks[(d+0)*72+m]=kv.x; Ks[(d+1)*72+m]=kv.y;
                Ks[(d+2)*72+m]=kv.z; Ks[(d+3)*72+m]=kv.w;
                *(float4*)&Vs[m*72 + d] = *(const float4*)(vrow + i*4);
            }
        }
        if (tid < 127) dds[tid] = ddt[h*2047 + 960 + (s0 - t0) + tid];
        __syncthreads();

        float S[8][4];
        #pragma unroll
        for (int nj=0;nj<8;nj++)
            #pragma unroll
            for (int q=0;q<4;q++) S[nj][q]=0.f;
        #pragma unroll
        for (int ks=0;ks<8;ks++){
            #pragma unroll
            for (int nj=0;nj<8;nj++){
                float b0 = Ks[(ks*8+tg  )*72 + nj*8 + g];
                float b1 = Ks[(ks*8+tg+4)*72 + nj*8 + g];
                mma8(S[nj], qf[ks], b0, b1);
            }
        }
        float c0 = coefs[m0+g], c1 = coefs[m0+g+8];
        #pragma unroll
        for (int nj=0;nj<8;nj++){
            int cn = nj*8 + tg*2;
            float dd0 = dds[cn     - (m0+g)   + 63];
            float dd1 = dds[cn + 1 - (m0+g)   + 63];
            float dd2 = dds[cn     - (m0+g+8) + 63];
            float dd3 = dds[cn + 1 - (m0+g+8) + 63];
            S[nj][0] = fmaf(S[nj][0], 0.125f, c0*dd0);
            S[nj][1] = fmaf(S[nj][1], 0.125f, c0*dd1);
            S[nj][2] = fmaf(S[nj][2], 0.125f, c1*dd2);
            S[nj][3] = fmaf(S[nj][3], 0.125f, c1*dd3);
        }
        #pragma unroll
        for (int i=0;i<2;i++){
            float mx = -3.0e38f;
            #pragma unroll
            for (int nj=0;nj<8;nj++) mx = fmaxf(mx, fmaxf(S[nj][2*i], S[nj][2*i+1]));
            mx = fmaxf(mx, __shfl_xor_sync(0xffffffffu, mx, 1));
            mx = fmaxf(mx, __shfl_xor_sync(0xffffffffu, mx, 2));
            float mo = fmaxf(m_run[i], mx);
            float alpha = __expf(m_run[i] - mo);
            m_run[i] = mo;
            float ls = 0.f;
            #pragma unroll
            for (int nj=0;nj<8;nj++){
                float p0 = __expf(S[nj][2*i]   - mo);
                float p1 = __expf(S[nj][2*i+1] - mo);
                S[nj][2*i] = p0; S[nj][2*i+1] = p1;
                ls += p0 + p1;
            }
            ls += __shfl_xor_sync(0xffffffffu, ls, 1);
            ls += __shfl_xor_sync(0xffffffffu, ls, 2);
            l_run[i] = l_run[i]*alpha + ls;
            #pragma unroll
            for (int nd=0;nd<8;nd++){ O[nd][2*i] *= alpha; O[nd][2*i+1] *= alpha; }
        }
        #pragma unroll
        for (int nj=0;nj<8;nj++){
            *(float2*)&Ps[(m0+g  )*68 + nj*8 + tg*2] = make_float2(S[nj][0], S[nj][1]);
            *(float2*)&Ps[(m0+g+8)*68 + nj*8 + tg*2] = make_float2(S[nj][2], S[nj][3]);
        }
        __syncwarp();
        #pragma unroll
        for (int ko=0;ko<8;ko++){
            float pa[4];
            pa[0] = Ps[(m0+g  )*68 + ko*8 + tg];
            pa[1] = Ps[(m0+g+8)*68 + ko*8 + tg];
            pa[2] = Ps[(m0+g  )*68 + ko*8 + tg + 4];
            pa[3] = Ps[(m0+g+8)*68 + ko*8 + tg + 4];
            #pragma unroll
            for (int nd=0;nd<8;nd++){
                float b0 = Vs[(ko*8+tg  )*72 + nd*8 + g];
                float b1 = Vs[(ko*8+tg+4)*72 + nd*8 + g];
                mma8(O[nd], pa, b0, b1);
            }
        }
    }
    float inv0 = 1.0f / l_run[0], inv1 = 1.0f / l_run[1];
    int r0 = t0 + m0 + g;
    #pragma unroll
    for (int nd=0;nd<8;nd++){
        int c = h*64 + nd*8 + tg*2;
        *(__half2*)&outh[((size_t)(b*1024 + r0  ))*512 + c] = __floats2half2_rn(O[nd][0]*inv0, O[nd][1]*inv0);
        *(__half2*)&outh[((size_t)(b*1024 + r0+8))*512 + c] = __floats2half2_rn(O[nd][2]*inv1, O[nd][3]*inv1);
    }
}

// ---------------- GroupNorm(1, C): deterministic 2-level reduction ----
__global__ void gn_partial_k(const float* __restrict__ x, float2* __restrict__ part){
    int b = blockIdx.x >> 8;
    int blk = blockIdx.x & 255;
    const float* p = x + (size_t)b*524288 + (size_t)blk*2048;
    float s=0.f, q=0.f;
    for (int i=threadIdx.x; i<512; i+=256){
        float4 v = *(const float4*)(p + i*4);
        s += v.x+v.y+v.z+v.w;
        q = fmaf(v.x,v.x,fmaf(v.y,v.y,fmaf(v.z,v.z,fmaf(v.w,v.w,q))));
    }
    __shared__ float ss[256], sq[256];
    ss[threadIdx.x]=s; sq[threadIdx.x]=q;
    __syncthreads();
    for (int o=128;o>0;o>>=1){
        if (threadIdx.x<o){ ss[threadIdx.x]+=ss[threadIdx.x+o]; sq[threadIdx.x]+=sq[threadIdx.x+o]; }
        __syncthreads();
    }
    if (threadIdx.x==0) part[blockIdx.x] = make_float2(ss[0], sq[0]);
}
__global__ void gn_final_k(const float2* __restrict__ part, float2* __restrict__ mv){
    int b = blockIdx.x;
    float2 v = part[b*256 + threadIdx.x];
    __shared__ float ss[256], sq[256];
    ss[threadIdx.x]=v.x; sq[threadIdx.x]=v.y;
    __syncthreads();
    for (int o=128;o>0;o>>=1){
        if (threadIdx.x<o){ ss[threadIdx.x]+=ss[threadIdx.x+o]; sq[threadIdx.x]+=sq[threadIdx.x+o]; }
        __syncthreads();
    }
    if (threadIdx.x==0){
        float mean = ss[0]*(1.0f/524288.0f);
        float var  = sq[0]*(1.0f/524288.0f) - mean*mean;
        mv[b] = make_float2(mean, rsqrtf(var + 1e-5f));
    }
}
template<bool SILU_>
__global__ void gn_apply_k(const float* __restrict__ x, const float2* __restrict__ mv,
                           const float* __restrict__ g, const float* __restrict__ be,
                           __half* __restrict__ y){
    size_t i4 = (size_t)blockIdx.x*256 + threadIdx.x;
    int b = (int)(i4 >> 17);
    int d = (int)((i4 & 127) << 2);
    float2 m = mv[b];
    float4 xv = *(const float4*)(x + i4*4);
    float4 gv = *(const float4*)(g + d);
    float4 bv = *(const float4*)(be + d);
    float4 o;
    o.x = (xv.x-m.x)*m.y*gv.x + bv.x;
    o.y = (xv.y-m.x)*m.y*gv.y + bv.y;
    o.z = (xv.z-m.x)*m.y*gv.z + bv.z;
    o.w = (xv.w-m.x)*m.y*gv.w + bv.w;
    if (SILU_){
        o.x *= sigm(o.x); o.y *= sigm(o.y); o.z *= sigm(o.z); o.w *= sigm(o.w);
    }
    __half2* yp = (__half2*)(y + i4*4);
    yp[0] = __floats2half2_rn(o.x, o.y);
    yp[1] = __floats2half2_rn(o.z, o.w);
}

// ---------------- depthwise conv ----------------
__global__ void dwconv_k(const float* __restrict__ in, const float* __restrict__ w,
                         const float* __restrict__ bias, float* __restrict__ out){
    int d = threadIdx.x;
    int t = blockIdx.x & 1023;
    int b = blockIdx.x >> 10;
    const float* base = in + (size_t)b*1024*512 + d;
    float acc = bias[d];
    #pragma unroll
    for (int k=0;k<31;k++){
        int tt = t + k - 15;
        if (tt >= 0 && tt < 1024)
            acc = fmaf(base[(size_t)tt*512], w[d*31+k], acc);
    }
    out[((size_t)b*1024 + t)*512 + d] = acc;
}

// ---------------- launch ----------------
extern "C" void kernel_launch(void* const* d_in, const int* in_sizes, int n_in,
                              void* d_out, int out_size) {
    const float* x      = (const float*)d_in[0];
    const float* ff1_w1 = (const float*)d_in[1];
    const float* ff1_b1 = (const float*)d_in[2];
    const float* ff1_w2 = (const float*)d_in[3];
    const float* ff1_b2 = (const float*)d_in[4];
    const float* qkv_w  = (const float*)d_in[5];
    const float* qkv_b  = (const float*)d_in[6];
    const float* out_w  = (const float*)d_in[7];
    const float* out_b  = (const float*)d_in[8];
    const float* gn1_g  = (const float*)d_in[9];
    const float* gn1_b  = (const float*)d_in[10];
    const float* pw1_w  = (const float*)d_in[11];
    const float* pw1_b  = (const float*)d_in[12];
    const float* dw_w   = (const float*)d_in[13];
    const float* dw_b   = (const float*)d_in[14];
    const float* gn2_g  = (const float*)d_in[15];
    const float* gn2_b  = (const float*)d_in[16];
    const float* pw2_w  = (const float*)d_in[17];
    const float* pw2_b  = (const float*)d_in[18];
    const float* ff2_w1 = (const float*)d_in[19];
    const float* ff2_b1 = (const float*)d_in[20];
    const float* ff2_w2 = (const float*)d_in[21];
    const float* ff2_b2 = (const float*)d_in[22];
    const float* rel_e  = (const float*)d_in[23];
    const float* gate_u = (const float*)d_in[24];
    const float* gate_w = (const float*)d_in[25];
    const float* gate_s = (const float*)d_in[26];

    float *S, *T1, *T2, *T3, *DDp, *BP;
    __half *Sh, *T1h, *T2h, *T3h, *W;
    float2 *PART, *MV;
    cudaGetSymbolAddress((void**)&S,  g_S);
    cudaGetSymbolAddress((void**)&T1, g_T1);
    cudaGetSymbolAddress((void**)&T2, g_T2);
    cudaGetSymbolAddress((void**)&T3, g_T3);
    cudaGetSymbolAddress((void**)&Sh, g_Sh);
    cudaGetSymbolAddress((void**)&T1h,g_T1h);
    cudaGetSymbolAddress((void**)&T2h,g_T2h);
    cudaGetSymbolAddress((void**)&T3h,g_T3h);
    cudaGetSymbolAddress((void**)&W,  g_W);
    cudaGetSymbolAddress((void**)&BP, g_BP);
    cudaGetSymbolAddress((void**)&DDp,g_DD);
    cudaGetSymbolAddress((void**)&PART, g_part);
    cudaGetSymbolAddress((void**)&MV,   g_mv);

    const int FLASH_SMEM = (64*68 + 64*72 + 64*72 + 64*68 + 128 + 64) * 4;
    cudaFuncSetAttribute((const void*)flash_mma_k,
                         cudaFuncAttributeMaxDynamicSharedMemorySize, FLASH_SMEM);
    const int GS256 = (4*128*40 + 4*256*40) * 2;   // 122880
    const int GS128 = (4*128*40 + 4*128*40) * 2;   // 81920
    cudaFuncSetAttribute(hgemm_k<256,0>, cudaFuncAttributeMaxDynamicSharedMemorySize, GS256);
    cudaFuncSetAttribute(hgemm_k<256,1>, cudaFuncAttributeMaxDynamicSharedMemorySize, GS256);
    cudaFuncSetAttribute(hgemm_k<256,3>, cudaFuncAttributeMaxDynamicSharedMemorySize, GS256);
    cudaFuncSetAttribute(hgemm_k<128,2>, cudaFuncAttributeMaxDynamicSharedMemorySize, GS128);

    dim3 tb(32,8);
    // prep: transposed fp16 weights (+ pw1 GLU permutation), tables, input transpose
    transpose_bdt_btd<<<dim3(32,16,4), tb>>>(x, S, Sh);
    build_dd_k<<<64,256>>>(rel_e, DDp);
    wconv_t<<<dim3(64,16), tb>>>(ff1_w1, W, 512, 2048, 0, W_FF1A, 1);
    wconv_t<<<dim3(16,64), tb>>>(ff1_w2, W, 2048, 512, 0, W_FF1B, 1);
    wconv_t<<<dim3(48,16), tb>>>(qkv_w,  W, 512, 1536, 0, W_QKV,  1);
    wconv_t<<<dim3(16,16), tb>>>(out_w,  W, 512,  512, 0, W_OUT,  1);
    wconv_t<<<dim3(16,16), tb>>>(pw1_w,  W, 512, 1024, 0,   W_PW1,       2);
    wconv_t<<<dim3(16,16), tb>>>(pw1_w,  W, 512, 1024, 512, W_PW1 + 512, 2);
    wconv_t<<<dim3(16,16), tb>>>(pw2_w,  W, 512,  512, 0, W_PW2,  1);
    wconv_t<<<dim3(64,16), tb>>>(ff2_w1, W, 512, 2048, 0, W_FF2A, 1);
    wconv_t<<<dim3(16,64), tb>>>(ff2_w2, W, 2048, 512, 0, W_FF2B, 1);
    bperm_k<<<4,256>>>(pw1_b, BP);

    // FFN1 (half-step)
    hgemm_k<256,1><<<dim3(8,32),256,GS256>>>(Sh,  W+W_FF1A, ff1_b1, nullptr, nullptr, T1h, 512, 0.f, 2048);
    hgemm_k<128,2><<<dim3(4,32),256,GS128>>>(T1h, W+W_FF1B, ff1_b2, S, S, Sh, 2048, 0.5f, 512);
    // QKV
    hgemm_k<256,0><<<dim3(6,32),256,GS256>>>(Sh,  W+W_QKV,  qkv_b,  nullptr, T1, nullptr, 512, 0.f, 1536);
    // attention
    flash_mma_k<<<dim3(16,8,4),128,FLASH_SMEM>>>(T1, gate_u, gate_w, gate_s, DDp, T2h);
    hgemm_k<128,2><<<dim3(4,32),256,GS128>>>(T2h, W+W_OUT,  out_b,  S, S, Sh, 512, 1.0f, 512);
    // conv module
    gn_partial_k<<<1024,256>>>(S, PART);
    gn_final_k<<<4,256>>>(PART, MV);
    gn_apply_k<false><<<2048,256>>>(S, MV, gn1_g, gn1_b, T2h);
    hgemm_k<256,3><<<dim3(4,32),256,GS256>>>(T2h, W+W_PW1, BP, nullptr, T3, nullptr, 512, 0.f, 512);
    dwconv_k<<<4096,512>>>(T3, dw_w, dw_b, T2);
    gn_partial_k<<<1024,256>>>(T2, PART);
    gn_final_k<<<4,256>>>(PART, MV);
    gn_apply_k<true><<<2048,256>>>(T2, MV, gn2_g, gn2_b, T3h);
    hgemm_k<128,2><<<dim3(4,32),256,GS128>>>(T3h, W+W_PW2,  pw2_b,  S, S, Sh, 512, 1.0f, 512);
    // FFN2 (half-step)
    hgemm_k<256,1><<<dim3(8,32),256,GS256>>>(Sh,  W+W_FF2A, ff2_b1, nullptr, nullptr, T1h, 512, 0.f, 2048);
    hgemm_k<128,2><<<dim3(4,32),256,GS128>>>(T1h, W+W_FF2B, ff2_b2, S, S, Sh, 2048, 0.5f, 512);
    // s -> out [B,D,T]
    transpose_btd_bdt<<<dim3(16,32,4), tb>>>(S, (float*)d_out);
}

// round 8
// speedup vs baseline: 3.9202x; 1.4664x over previous
#include <cuda_runtime.h>
#include <cuda_fp16.h>
#include <math.h>
#include <cstdint>

// ---------------- scratch (device globals; allocation-free rule) ----------------
__device__ float  g_S [4096*512];      // residual stream fp32 [B,T,D]
__device__ float  g_T2[4096*512];      // dwconv out (gn2 in)
__device__ float  g_T3[4096*512];      // GLU out (dwconv in)
__device__ __half g_Sh [4096*512];     // fp16 mirror of S
__device__ __half g_T1h[4096*2048];    // ffn hidden / qkv out fp16
__device__ __half g_T2h[4096*512];     // flash out / gn1 out fp16
__device__ __half g_T3h[4096*512];     // gn2 out fp16
__device__ __half g_W  [6029312];      // all transposed fp16 weights
__device__ float  g_BP [1024];         // permuted pw1 bias
__device__ float  g_DD [8*2047];       // rel-pos bias table
__device__ float2 g_part[1024];
__device__ float2 g_mv[4];

// weight offsets (halves)
#define W_FF1A 0u
#define W_FF1B 1048576u
#define W_QKV  2097152u
#define W_OUT  2883584u
#define W_PW1  3145728u
#define W_PW2  3670016u
#define W_FF2A 3932160u
#define W_FF2B 4980736u

__device__ __forceinline__ float gelu_f(float x){
    return 0.5f * x * (1.0f + erff(x * 0.70710678118654752440f));
}
__device__ __forceinline__ float sigm(float x){ return 1.0f/(1.0f + expf(-x)); }

// ---------------- async-copy helpers ----------------
__device__ __forceinline__ void cpasync16(uint32_t dst, const void* src){
    asm volatile("cp.async.ca.shared.global [%0], [%1], 16;" :: "r"(dst), "l"(src));
}
#define CP_COMMIT() asm volatile("cp.async.commit_group;" ::: "memory")
template<int N>
__device__ __forceinline__ void cp_wait(){
    asm volatile("cp.async.wait_group %0;" :: "n"(N) : "memory");
}

// fp16 warp MMA: D(16x8,f32) += A(16x16,f16) * B(16x8,f16)
__device__ __forceinline__ void mma16(float* c, const uint32_t* a, uint32_t b0, uint32_t b1){
    asm volatile(
        "mma.sync.aligned.m16n8k16.row.col.f32.f16.f16.f32 "
        "{%0,%1,%2,%3},{%4,%5,%6,%7},{%8,%9},{%0,%1,%2,%3};"
        : "+f"(c[0]), "+f"(c[1]), "+f"(c[2]), "+f"(c[3])
        : "r"(a[0]), "r"(a[1]), "r"(a[2]), "r"(a[3]), "r"(b0), "r"(b1));
}

// ---------------- fp16 tensor GEMM: C = epi(A[MxK] @ B^T + bias) -------------
// A fp16 [M][Kd]; B fp16 [N][Kd] (pre-transposed). CTA 128 x TN, 256 threads,
// 8 warps (2 row x 4 col), warp tile 64 x TN/4. K staged by 32 (2 k16 steps),
// 4-buffer cp.async pipeline.
// EPI: 0=bias->f16 | 1=bias+GELU->f16 | 2=bias+res->f32+f16 | 3=bias+GLU->f32
template<int TN, int EPI>
__global__ void __launch_bounds__(256,1) hgemm_k(
    const __half* __restrict__ A, const __half* __restrict__ B,
    const float* __restrict__ bias, const float* __restrict__ res,
    float* __restrict__ C, __half* __restrict__ Ch,
    int Kd, float rscale, int Cs)
{
    constexpr int WN   = TN/4;
    constexpr int NJ   = WN/8;
    constexpr int A_ST = 128*40;
    constexpr int B_ST = TN*40;

    extern __shared__ __align__(16) __half smh[];
    __half* Ash = smh;
    __half* Bsh = smh + 4*A_ST;

    int tid = threadIdx.x, lane = tid & 31, wid = tid >> 5;
    int wr = wid >> 2, wc = wid & 3;
    int g = lane >> 2, tg = lane & 3;
    int row0 = blockIdx.y*128, col0 = blockIdx.x*TN;

    const __half* Ag = A + (size_t)row0*Kd;
    const __half* Bg = B + (size_t)col0*Kd;
    uint32_t sA = (uint32_t)__cvta_generic_to_shared(Ash);
    uint32_t sB = (uint32_t)__cvta_generic_to_shared(Bsh);

    auto loadA = [&](int kt){
        int k0 = kt*32;
        uint32_t base = sA + (kt & 3)*(A_ST*2);
        #pragma unroll
        for (int i = 0; i < 2; i++){
            int f = tid + i*256;
            int m = f >> 2, seg = f & 3;
            cpasync16(base + (uint32_t)(m*80 + seg*16),
                      Ag + (size_t)m*Kd + k0 + seg*8);
        }
    };
    auto loadB = [&](int kt){
        int k0 = kt*32;
        uint32_t base = sB + (kt & 3)*(B_ST*2);
        #pragma unroll
        for (int i = 0; i < TN/64; i++){
            int f = tid + i*256;
            int n = f >> 2, seg = f & 3;
            cpasync16(base + (uint32_t)(n*80 + seg*16),
                      Bg + (size_t)n*Kd + k0 + seg*8);
        }
    };

    float acc[4][NJ][4];
    #pragma unroll
    for (int mi=0;mi<4;mi++)
        #pragma unroll
        for (int nj=0;nj<NJ;nj++)
            #pragma unroll
            for (int q=0;q<4;q++) acc[mi][nj][q]=0.f;

    int nk = Kd >> 5;
    loadA(0); loadB(0); CP_COMMIT();
    loadA(1); loadB(1); CP_COMMIT();
    loadA(2); loadB(2); CP_COMMIT();

    for (int kt = 0; kt < nk; ++kt){
        cp_wait<2>();
        __syncthreads();
        if (kt + 3 < nk){ loadA(kt+3); loadB(kt+3); }
        CP_COMMIT();

        int buf = kt & 3;
        const __half* Ab = Ash + buf*A_ST + (wr*64)*40;
        const __half* Bb = Bsh + buf*B_ST + (wc*WN)*40;
        #pragma unroll
        for (int ks = 0; ks < 2; ++ks){
            int k0h = ks*16;
            uint32_t a[4][4];
            #pragma unroll
            for (int mi=0;mi<4;mi++){
                const __half* ap = Ab + (mi*16+g)*40 + k0h + 2*tg;
                a[mi][0] = *(const uint32_t*)ap;
                a[mi][1] = *(const uint32_t*)(ap + 8*40);
                a[mi][2] = *(const uint32_t*)(ap + 8);
                a[mi][3] = *(const uint32_t*)(ap + 8*40 + 8);
            }
            #pragma unroll
            for (int nj=0;nj<NJ;nj++){
                const __half* bp = Bb + (nj*8+g)*40 + k0h + 2*tg;
                uint32_t b0 = *(const uint32_t*)bp;
                uint32_t b1 = *(const uint32_t*)(bp + 8);
                #pragma unroll
                for (int mi=0;mi<4;mi++)
                    mma16(acc[mi][nj], a[mi], b0, b1);
            }
        }
    }

    // epilogue
    #pragma unroll
    for (int nj=0;nj<NJ;nj++){
        int c = col0 + wc*WN + nj*8 + tg*2;
        float2 bi = *(const float2*)&bias[c];
        #pragma unroll
        for (int mi=0;mi<4;mi++){
            int r0 = row0 + wr*64 + mi*16 + g;
            float v0 = acc[mi][nj][0] + bi.x;
            float v1 = acc[mi][nj][1] + bi.y;
            float v2 = acc[mi][nj][2] + bi.x;
            float v3 = acc[mi][nj][3] + bi.y;
            if (EPI == 1){
                v0=gelu_f(v0); v1=gelu_f(v1); v2=gelu_f(v2); v3=gelu_f(v3);
                *(__half2*)&Ch[(size_t)r0*Cs + c]     = __floats2half2_rn(v0, v1);
                *(__half2*)&Ch[(size_t)(r0+8)*Cs + c] = __floats2half2_rn(v2, v3);
            } else if (EPI == 2){
                float2 r0v = *(const float2*)&res[(size_t)r0*Cs + c];
                float2 r1v = *(const float2*)&res[(size_t)(r0+8)*Cs + c];
                v0 = fmaf(rscale, v0, r0v.x); v1 = fmaf(rscale, v1, r0v.y);
                v2 = fmaf(rscale, v2, r1v.x); v3 = fmaf(rscale, v3, r1v.y);
                *(float2*)&C[(size_t)r0*Cs + c]     = make_float2(v0, v1);
                *(float2*)&C[(size_t)(r0+8)*Cs + c] = make_float2(v2, v3);
                *(__half2*)&Ch[(size_t)r0*Cs + c]     = __floats2half2_rn(v0, v1);
                *(__half2*)&Ch[(size_t)(r0+8)*Cs + c] = __floats2half2_rn(v2, v3);
            } else if (EPI == 3){
                int co = c >> 1;
                C[(size_t)r0*Cs + co]     = v0 * sigm(v1);
                C[(size_t)(r0+8)*Cs + co] = v2 * sigm(v3);
            } else {
                *(__half2*)&Ch[(size_t)r0*Cs + c]     = __floats2half2_rn(v0, v1);
                *(__half2*)&Ch[(size_t)(r0+8)*Cs + c] = __floats2half2_rn(v2, v3);
            }
        }
    }
}

// ---------------- merged weight transpose+convert (all 8 weights, 9 jobs) ------
__global__ void wconv_all(const float* __restrict__ ff1w1, const float* __restrict__ ff1w2,
                          const float* __restrict__ qkvw,  const float* __restrict__ outw,
                          const float* __restrict__ pw1w,  const float* __restrict__ pw2w,
                          const float* __restrict__ ff2w1, const float* __restrict__ ff2w2,
                          __half* __restrict__ W){
    __shared__ float t[32][33];
    int bI = blockIdx.x;
    const float* src; int K, N, cOff, rStr, tilesX; unsigned base;
    if      (bI < 1024){            src=ff1w1; K=512;  N=2048; cOff=0;   base=W_FF1A;     rStr=1; tilesX=64; }
    else if (bI < 2048){ bI-=1024;  src=ff1w2; K=2048; N=512;  cOff=0;   base=W_FF1B;     rStr=1; tilesX=16; }
    else if (bI < 2816){ bI-=2048;  src=qkvw;  K=512;  N=1536; cOff=0;   base=W_QKV;      rStr=1; tilesX=48; }
    else if (bI < 3072){ bI-=2816;  src=outw;  K=512;  N=512;  cOff=0;   base=W_OUT;      rStr=1; tilesX=16; }
    else if (bI < 3328){ bI-=3072;  src=pw1w;  K=512;  N=1024; cOff=0;   base=W_PW1;      rStr=2; tilesX=16; }
    else if (bI < 3584){ bI-=3328;  src=pw1w;  K=512;  N=1024; cOff=512; base=W_PW1+512u; rStr=2; tilesX=16; }
    else if (bI < 3840){ bI-=3584;  src=pw2w;  K=512;  N=512;  cOff=0;   base=W_PW2;      rStr=1; tilesX=16; }
    else if (bI < 4864){ bI-=3840;  src=ff2w1; K=512;  N=2048; cOff=0;   base=W_FF2A;     rStr=1; tilesX=64; }
    else               { bI-=4864;  src=ff2w2; K=2048; N=512;  cOff=0;   base=W_FF2B;     rStr=1; tilesX=16; }
    int n0 = (bI % tilesX)*32, k0 = (bI / tilesX)*32;
    int lx = threadIdx.x, ly = threadIdx.y;
    #pragma unroll
    for (int i=0;i<32;i+=8)
        t[ly+i][lx] = src[(size_t)(k0+ly+i)*N + cOff + n0 + lx];
    __syncthreads();
    #pragma unroll
    for (int i=0;i<32;i+=8)
        W[base + (size_t)(n0+ly+i)*K*rStr + k0 + lx] = __float2half(t[lx][ly+i]);
}
__global__ void bperm_k(const float* __restrict__ b, float* __restrict__ bp){
    int c = blockIdx.x*256 + threadIdx.x;
    if (c < 1024) bp[c] = b[(c>>1) + (c&1)*512];
}

// ---------------- transposes ----------------
__global__ void transpose_bdt_btd(const float* __restrict__ in, float* __restrict__ out,
                                  __half* __restrict__ outh){
    __shared__ float tile[32][33];
    int b = blockIdx.z;
    int t0 = blockIdx.x*32, d0 = blockIdx.y*32;
    int lx = threadIdx.x, ly = threadIdx.y;
    #pragma unroll
    for (int i=0;i<32;i+=8)
        tile[ly+i][lx] = in[((size_t)b*512 + d0+ly+i)*1024 + t0 + lx];
    __syncthreads();
    #pragma unroll
    for (int i=0;i<32;i+=8){
        float v = tile[lx][ly+i];
        size_t o = ((size_t)b*1024 + t0+ly+i)*512 + d0 + lx;
        out[o] = v;
        outh[o] = __float2half(v);
    }
}
__global__ void transpose_btd_bdt(const float* __restrict__ in, float* __restrict__ out){
    __shared__ float tile[32][33];
    int b = blockIdx.z;
    int d0 = blockIdx.x*32, t0 = blockIdx.y*32;
    int lx = threadIdx.x, ly = threadIdx.y;
    #pragma unroll
    for (int i=0;i<32;i+=8)
        tile[ly+i][lx] = in[((size_t)b*1024 + t0+ly+i)*512 + d0 + lx];
    __syncthreads();
    #pragma unroll
    for (int i=0;i<32;i+=8)
        out[((size_t)b*512 + d0+ly+i)*1024 + t0 + lx] = tile[lx][ly+i];
}

// ---------------- relative-position bias table ----------------
__global__ void build_dd_k(const float* __restrict__ rel_embed, float* __restrict__ ddt){
    int idx = blockIdx.x*256 + threadIdx.x;
    if (idx >= 8*2047) return;
    int h = idx / 2047;
    int rpos = idx % 2047;
    int rel = rpos - 1023;
    int sign = (rel >= 0) ? 1 : 0;
    int a = (rel >= 0) ? rel : -rel;
    int bucket;
    if (a < 80) bucket = a;
    else {
        float lr = logf((float)a / 80.0f) / logf(10.0f);
        int lp = 80 + (int)(lr * 80.0f);
        bucket = (lp < 159) ? lp : 159;
    }
    bucket += sign*160;
    if (bucket < 0) bucket = 0;
    if (bucket > 319) bucket = 319;
    ddt[h*2047 + rpos] = rel_embed[bucket*8 + h];
}

// ---------------- fp16 tensor-core flash attention with gated rel-pos bias -----
// probs = softmax_s( q.k/8 + coef[b,h,t] * dd[h, s-t] ).  All operands fp16 in
// smem (stride 72 halves -> conflict-free u32 frag reads), fp32 softmax/accum.
__global__ void __launch_bounds__(128) flash_h_k(
    const __half* __restrict__ qkv,    // [B,T,1536] fp16
    const float* __restrict__ gate_u, const float* __restrict__ gate_w,
    const float* __restrict__ gate_scale, const float* __restrict__ ddt,
    __half* __restrict__ outh)         // fp16 [B,T,512]
{
    extern __shared__ __align__(16) __half smh[];
    __half* Qs = smh;                  // [64 m][72 d]
    __half* Ks = Qs + 64*72;           // [64 s][72 d]
    __half* Vt = Ks + 64*72;           // [64 d][72 s]   (V transposed)
    __half* Ps = Vt + 64*72;           // [64 m][72 s]
    float* dds   = (float*)(Ps + 64*72);   // [128]
    float* coefs = dds + 128;              // [64]

    int tid = threadIdx.x, lane = tid & 31, wid = tid >> 5;
    int g = lane >> 2, tg = lane & 3;
    int t0 = blockIdx.x * 64;
    int h  = blockIdx.y;
    int b  = blockIdx.z;
    int m0 = wid * 16;

    const __half* qbase = qkv + (size_t)b*1024*1536 + h*64;
    const __half* kbase = qbase + 512;
    const __half* vbase = qbase + 1024;

    { // load Q tile
        int m = tid >> 1, hf = (tid & 1) * 32;
        const __half* qr = qbase + (size_t)(t0+m)*1536 + hf;
        #pragma unroll
        for (int i=0;i<4;i++)
            *(uint4*)&Qs[m*72 + hf + i*8] = *(const uint4*)(qr + i*8);
    }
    __syncthreads();
    if (tid < 64){ // per-query gate coefficient
        float du=0.f, dw=0.f;
        #pragma unroll
        for (int d=0; d<64; d++){
            float qv = __half2float(Qs[tid*72 + d]);
            du = fmaf(qv, gate_u[h*64+d], du);
            dw = fmaf(qv, gate_w[h*64+d], dw);
        }
        float gu = sigm(du), gr = sigm(dw);
        coefs[tid] = 1.0f + gu + (1.0f-gu)*gate_scale[h]*gr;
    }
    // register-resident Q fragments
    uint32_t qf[4][4];
    #pragma unroll
    for (int ks=0;ks<4;ks++){
        const __half* ap = Qs + (m0+g)*72 + ks*16 + 2*tg;
        qf[ks][0] = *(const uint32_t*)ap;
        qf[ks][1] = *(const uint32_t*)(ap + 8*72);
        qf[ks][2] = *(const uint32_t*)(ap + 8);
        qf[ks][3] = *(const uint32_t*)(ap + 8*72 + 8);
    }

    float m_run[2] = {-3.0e38f, -3.0e38f}, l_run[2] = {0.f, 0.f};
    float O[8][4];
    #pragma unroll
    for (int nd=0;nd<8;nd++)
        #pragma unroll
        for (int q=0;q<4;q++) O[nd][q]=0.f;

    for (int s0 = 0; s0 < 1024; s0 += 64){
        __syncthreads();
        { // load K direct + V transposed
            int m = tid >> 1, hf = (tid & 1) * 32;
            const __half* kr = kbase + (size_t)(s0+m)*1536 + hf;
            const __half* vr = vbase + (size_t)(s0+m)*1536 + hf;
            #pragma unroll
            for (int i=0;i<4;i++){
                *(uint4*)&Ks[m*72 + hf + i*8] = *(const uint4*)(kr + i*8);
                __half vv[8];
                *(uint4*)vv = *(const uint4*)(vr + i*8);
                #pragma unroll
                for (int j=0;j<8;j++)
                    Vt[(hf + i*8 + j)*72 + m] = vv[j];
            }
        }
        if (tid < 127) dds[tid] = ddt[h*2047 + 960 + (s0 - t0) + tid];
        __syncthreads();

        // S = Q K^T  (4 k16 steps over d)
        float S[8][4];
        #pragma unroll
        for (int nj=0;nj<8;nj++)
            #pragma unroll
            for (int q=0;q<4;q++) S[nj][q]=0.f;
        #pragma unroll
        for (int ks=0;ks<4;ks++){
            #pragma unroll
            for (int nj=0;nj<8;nj++){
                const __half* bp = Ks + (nj*8+g)*72 + ks*16 + 2*tg;
                uint32_t b0 = *(const uint32_t*)bp;
                uint32_t b1 = *(const uint32_t*)(bp + 8);
                mma16(S[nj], qf[ks], b0, b1);
            }
        }
        // bias: S*0.125 + coef[row]*dd[col-row+63]
        float c0 = coefs[m0+g], c1 = coefs[m0+g+8];
        #pragma unroll
        for (int nj=0;nj<8;nj++){
            int cn = nj*8 + tg*2;
            float dd0 = dds[cn     - (m0+g)   + 63];
            float dd1 = dds[cn + 1 - (m0+g)   + 63];
            float dd2 = dds[cn     - (m0+g+8) + 63];
            float dd3 = dds[cn + 1 - (m0+g+8) + 63];
            S[nj][0] = fmaf(S[nj][0], 0.125f, c0*dd0);
            S[nj][1] = fmaf(S[nj][1], 0.125f, c0*dd1);
            S[nj][2] = fmaf(S[nj][2], 0.125f, c1*dd2);
            S[nj][3] = fmaf(S[nj][3], 0.125f, c1*dd3);
        }
        // online softmax
        #pragma unroll
        for (int i=0;i<2;i++){
            float mx = -3.0e38f;
            #pragma unroll
            for (int nj=0;nj<8;nj++) mx = fmaxf(mx, fmaxf(S[nj][2*i], S[nj][2*i+1]));
            mx = fmaxf(mx, __shfl_xor_sync(0xffffffffu, mx, 1));
            mx = fmaxf(mx, __shfl_xor_sync(0xffffffffu, mx, 2));
            float mo = fmaxf(m_run[i], mx);
            float alpha = __expf(m_run[i] - mo);
            m_run[i] = mo;
            float ls = 0.f;
            #pragma unroll
            for (int nj=0;nj<8;nj++){
                float p0 = __expf(S[nj][2*i]   - mo);
                float p1 = __expf(S[nj][2*i+1] - mo);
                S[nj][2*i] = p0; S[nj][2*i+1] = p1;
                ls += p0 + p1;
            }
            ls += __shfl_xor_sync(0xffffffffu, ls, 1);
            ls += __shfl_xor_sync(0xffffffffu, ls, 2);
            l_run[i] = l_run[i]*alpha + ls;
            #pragma unroll
            for (int nd=0;nd<8;nd++){ O[nd][2*i] *= alpha; O[nd][2*i+1] *= alpha; }
        }
        // write P fp16 (per-warp region)
        #pragma unroll
        for (int nj=0;nj<8;nj++){
            *(__half2*)&Ps[(m0+g  )*72 + nj*8 + tg*2] = __floats2half2_rn(S[nj][0], S[nj][1]);
            *(__half2*)&Ps[(m0+g+8)*72 + nj*8 + tg*2] = __floats2half2_rn(S[nj][2], S[nj][3]);
        }
        __syncwarp();
        // O += P V  (4 k16 steps over keys)
        #pragma unroll
        for (int ko=0;ko<4;ko++){
            uint32_t pa[4];
            const __half* pp = Ps + (m0+g)*72 + ko*16 + 2*tg;
            pa[0] = *(const uint32_t*)pp;
            pa[1] = *(const uint32_t*)(pp + 8*72);
            pa[2] = *(const uint32_t*)(pp + 8);
            pa[3] = *(const uint32_t*)(pp + 8*72 + 8);
            #pragma unroll
            for (int nd=0;nd<8;nd++){
                const __half* vp = Vt + (nd*8+g)*72 + ko*16 + 2*tg;
                uint32_t b0 = *(const uint32_t*)vp;
                uint32_t b1 = *(const uint32_t*)(vp + 8);
                mma16(O[nd], pa, b0, b1);
            }
        }
    }
    float inv0 = 1.0f / l_run[0], inv1 = 1.0f / l_run[1];
    int r0 = t0 + m0 + g;
    #pragma unroll
    for (int nd=0;nd<8;nd++){
        int c = h*64 + nd*8 + tg*2;
        *(__half2*)&outh[((size_t)(b*1024 + r0  ))*512 + c] = __floats2half2_rn(O[nd][0]*inv0, O[nd][1]*inv0);
        *(__half2*)&outh[((size_t)(b*1024 + r0+8))*512 + c] = __floats2half2_rn(O[nd][2]*inv1, O[nd][3]*inv1);
    }
}

// ---------------- GroupNorm(1, C): deterministic 2-level reduction ----
__global__ void gn_partial_k(const float* __restrict__ x, float2* __restrict__ part){
    int b = blockIdx.x >> 8;
    int blk = blockIdx.x & 255;
    const float* p = x + (size_t)b*524288 + (size_t)blk*2048;
    float s=0.f, q=0.f;
    for (int i=threadIdx.x; i<512; i+=256){
        float4 v = *(const float4*)(p + i*4);
        s += v.x+v.y+v.z+v.w;
        q = fmaf(v.x,v.x,fmaf(v.y,v.y,fmaf(v.z,v.z,fmaf(v.w,v.w,q))));
    }
    __shared__ float ss[256], sq[256];
    ss[threadIdx.x]=s; sq[threadIdx.x]=q;
    __syncthreads();
    for (int o=128;o>0;o>>=1){
        if (threadIdx.x<o){ ss[threadIdx.x]+=ss[threadIdx.x+o]; sq[threadIdx.x]+=sq[threadIdx.x+o]; }
        __syncthreads();
    }
    if (threadIdx.x==0) part[blockIdx.x] = make_float2(ss[0], sq[0]);
}
__global__ void gn_final_k(const float2* __restrict__ part, float2* __restrict__ mv){
    int b = blockIdx.x;
    float2 v = part[b*256 + threadIdx.x];
    __shared__ float ss[256], sq[256];
    ss[threadIdx.x]=v.x; sq[threadIdx.x]=v.y;
    __syncthreads();
    for (int o=128;o>0;o>>=1){
        if (threadIdx.x<o){ ss[threadIdx.x]+=ss[threadIdx.x+o]; sq[threadIdx.x]+=sq[threadIdx.x+o]; }
        __syncthreads();
    }
    if (threadIdx.x==0){
        float mean = ss[0]*(1.0f/524288.0f);
        float var  = sq[0]*(1.0f/524288.0f) - mean*mean;
        mv[b] = make_float2(mean, rsqrtf(var + 1e-5f));
    }
}
template<bool SILU_>
__global__ void gn_apply_k(const float* __restrict__ x, const float2* __restrict__ mv,
                           const float* __restrict__ g, const float* __restrict__ be,
                           __half* __restrict__ y){
    size_t i4 = (size_t)blockIdx.x*256 + threadIdx.x;
    int b = (int)(i4 >> 17);
    int d = (int)((i4 & 127) << 2);
    float2 m = mv[b];
    float4 xv = *(const float4*)(x + i4*4);
    float4 gv = *(const float4*)(g + d);
    float4 bv = *(const float4*)(be + d);
    float4 o;
    o.x = (xv.x-m.x)*m.y*gv.x + bv.x;
    o.y = (xv.y-m.x)*m.y*gv.y + bv.y;
    o.z = (xv.z-m.x)*m.y*gv.z + bv.z;
    o.w = (xv.w-m.x)*m.y*gv.w + bv.w;
    if (SILU_){
        o.x *= sigm(o.x); o.y *= sigm(o.y); o.z *= sigm(o.z); o.w *= sigm(o.w);
    }
    __half2* yp = (__half2*)(y + i4*4);
    yp[0] = __floats2half2_rn(o.x, o.y);
    yp[1] = __floats2half2_rn(o.z, o.w);
}

// ---------------- depthwise conv (smem-tiled: 16 t x 512 d per block) ----------
__global__ void __launch_bounds__(512) dwconv_k(
    const float* __restrict__ in, const float* __restrict__ w,
    const float* __restrict__ bias, float* __restrict__ out)
{
    __shared__ float tile[46][512];
    int d = threadIdx.x;
    int tt0 = blockIdx.x * 16;
    int b = blockIdx.y;
    const float* base = in + (size_t)b*524288;
    #pragma unroll
    for (int i=0;i<46;i++){
        int t = tt0 - 15 + i;
        tile[i][d] = (t >= 0 && t < 1024) ? base[(size_t)t*512 + d] : 0.f;
    }
    float wr[31];
    #pragma unroll
    for (int k=0;k<31;k++) wr[k] = w[d*31+k];
    float bi = bias[d];
    __syncthreads();
    #pragma unroll
    for (int j=0;j<16;j++){
        float acc = bi;
        #pragma unroll
        for (int k=0;k<31;k++) acc = fmaf(tile[j+k][d], wr[k], acc);
        out[((size_t)b*1024 + tt0 + j)*512 + d] = acc;
    }
}

// ---------------- launch ----------------
extern "C" void kernel_launch(void* const* d_in, const int* in_sizes, int n_in,
                              void* d_out, int out_size) {
    const float* x      = (const float*)d_in[0];
    const float* ff1_w1 = (const float*)d_in[1];
    const float* ff1_b1 = (const float*)d_in[2];
    const float* ff1_w2 = (const float*)d_in[3];
    const float* ff1_b2 = (const float*)d_in[4];
    const float* qkv_w  = (const float*)d_in[5];
    const float* qkv_b  = (const float*)d_in[6];
    const float* out_w  = (const float*)d_in[7];
    const float* out_b  = (const float*)d_in[8];
    const float* gn1_g  = (const float*)d_in[9];
    const float* gn1_b  = (const float*)d_in[10];
    const float* pw1_w  = (const float*)d_in[11];
    const float* pw1_b  = (const float*)d_in[12];
    const float* dw_w   = (const float*)d_in[13];
    const float* dw_b   = (const float*)d_in[14];
    const float* gn2_g  = (const float*)d_in[15];
    const float* gn2_b  = (const float*)d_in[16];
    const float* pw2_w  = (const float*)d_in[17];
    const float* pw2_b  = (const float*)d_in[18];
    const float* ff2_w1 = (const float*)d_in[19];
    const float* ff2_b1 = (const float*)d_in[20];
    const float* ff2_w2 = (const float*)d_in[21];
    const float* ff2_b2 = (const float*)d_in[22];
    const float* rel_e  = (const float*)d_in[23];
    const float* gate_u = (const float*)d_in[24];
    const float* gate_w = (const float*)d_in[25];
    const float* gate_s = (const float*)d_in[26];

    float *S, *T2, *T3, *DDp, *BP;
    __half *Sh, *T1h, *T2h, *T3h, *W;
    float2 *PART, *MV;
    cudaGetSymbolAddress((void**)&S,  g_S);
    cudaGetSymbolAddress((void**)&T2, g_T2);
    cudaGetSymbolAddress((void**)&T3, g_T3);
    cudaGetSymbolAddress((void**)&Sh, g_Sh);
    cudaGetSymbolAddress((void**)&T1h,g_T1h);
    cudaGetSymbolAddress((void**)&T2h,g_T2h);
    cudaGetSymbolAddress((void**)&T3h,g_T3h);
    cudaGetSymbolAddress((void**)&W,  g_W);
    cudaGetSymbolAddress((void**)&BP, g_BP);
    cudaGetSymbolAddress((void**)&DDp,g_DD);
    cudaGetSymbolAddress((void**)&PART, g_part);
    cudaGetSymbolAddress((void**)&MV,   g_mv);

    const int FLASH_SMEM = 4*64*72*2 + 128*4 + 64*4;   // 37632
    cudaFuncSetAttribute((const void*)flash_h_k,
                         cudaFuncAttributeMaxDynamicSharedMemorySize, FLASH_SMEM);
    const int GS256 = (4*128*40 + 4*256*40) * 2;   // 122880
    const int GS128 = (4*128*40 + 4*128*40) * 2;   // 81920
    cudaFuncSetAttribute(hgemm_k<256,0>, cudaFuncAttributeMaxDynamicSharedMemorySize, GS256);
    cudaFuncSetAttribute(hgemm_k<256,1>, cudaFuncAttributeMaxDynamicSharedMemorySize, GS256);
    cudaFuncSetAttribute(hgemm_k<256,3>, cudaFuncAttributeMaxDynamicSharedMemorySize, GS256);
    cudaFuncSetAttribute(hgemm_k<128,2>, cudaFuncAttributeMaxDynamicSharedMemorySize, GS128);

    dim3 tb(32,8);
    // prep
    transpose_bdt_btd<<<dim3(32,16,4), tb>>>(x, S, Sh);
    build_dd_k<<<64,256>>>(rel_e, DDp);
    wconv_all<<<5888, tb>>>(ff1_w1, ff1_w2, qkv_w, out_w, pw1_w, pw2_w, ff2_w1, ff2_w2, W);
    bperm_k<<<4,256>>>(pw1_b, BP);

    // FFN1 (half-step)
    hgemm_k<256,1><<<dim3(8,32),256,GS256>>>(Sh,  W+W_FF1A, ff1_b1, nullptr, nullptr, T1h, 512, 0.f, 2048);
    hgemm_k<128,2><<<dim3(4,32),256,GS128>>>(T1h, W+W_FF1B, ff1_b2, S, S, Sh, 2048, 0.5f, 512);
    // QKV (fp16 out)
    hgemm_k<256,0><<<dim3(6,32),256,GS256>>>(Sh,  W+W_QKV,  qkv_b,  nullptr, nullptr, T1h, 512, 0.f, 1536);
    // attention (all fp16 operands)
    flash_h_k<<<dim3(16,8,4),128,FLASH_SMEM>>>(T1h, gate_u, gate_w, gate_s, DDp, T2h);
    hgemm_k<128,2><<<dim3(4,32),256,GS128>>>(T2h, W+W_OUT,  out_b,  S, S, Sh, 512, 1.0f, 512);
    // conv module
    gn_partial_k<<<1024,256>>>(S, PART);
    gn_final_k<<<4,256>>>(PART, MV);
    gn_apply_k<false><<<2048,256>>>(S, MV, gn1_g, gn1_b, T2h);
    hgemm_k<256,3><<<dim3(4,32),256,GS256>>>(T2h, W+W_PW1, BP, nullptr, T3, nullptr, 512, 0.f, 512);
    dwconv_k<<<dim3(64,4),512>>>(T3, dw_w, dw_b, T2);
    gn_partial_k<<<1024,256>>>(T2, PART);
    gn_final_k<<<4,256>>>(PART, MV);
    gn_apply_k<true><<<2048,256>>>(T2, MV, gn2_g, gn2_b, T3h);
    hgemm_k<128,2><<<dim3(4,32),256,GS128>>>(T3h, W+W_PW2,  pw2_b,  S, S, Sh, 512, 1.0f, 512);
    // FFN2 (half-step)
    hgemm_k<256,1><<<dim3(8,32),256,GS256>>>(Sh,  W+W_FF2A, ff2_b1, nullptr, nullptr, T1h, 512, 0.f, 2048);
    hgemm_k<128,2><<<dim3(4,32),256,GS128>>>(T1h, W+W_FF2B, ff2_b2, S, S, Sh, 2048, 0.5f, 512);
    // s -> out [B,D,T]
    transpose_btd_bdt<<<dim3(16,32,4), tb>>>(S, (float*)d_out);
}

// round 9
// speedup vs baseline: 4.2887x; 1.0940x over previous
#include <cuda_runtime.h>
#include <cuda_fp16.h>
#include <math.h>
#include <cstdint>

// ---------------- scratch (device globals; allocation-free rule) ----------------
__device__ float  g_S [4096*512];      // residual stream fp32 [B,T,D]
__device__ float  g_T2[4096*512];      // dwconv out (gn2 in)
__device__ float  g_T3[4096*512];      // GLU out (dwconv in)
__device__ __half g_Sh [4096*512];     // fp16 mirror of S
__device__ __half g_T1h[4096*2048];    // ffn hidden / qkv out fp16
__device__ __half g_T2h[4096*512];     // flash out / gn1 out fp16
__device__ __half g_T3h[4096*512];     // gn2 out fp16
__device__ __half g_W  [6029312];      // all transposed fp16 weights
__device__ float  g_BP [1024];         // permuted pw1 bias
__device__ float  g_DD [8*2047];       // rel-pos bias table
__device__ float2 g_part[1024];
__device__ float2 g_mv[4];

// weight offsets (halves)
#define W_FF1A 0u
#define W_FF1B 1048576u
#define W_QKV  2097152u
#define W_OUT  2883584u
#define W_PW1  3145728u
#define W_PW2  3670016u
#define W_FF2A 3932160u
#define W_FF2B 4980736u

__device__ __forceinline__ float gelu_f(float x){
    return 0.5f * x * (1.0f + erff(x * 0.70710678118654752440f));
}
__device__ __forceinline__ float sigm(float x){ return 1.0f/(1.0f + expf(-x)); }

// ---------------- async-copy / ldmatrix helpers ----------------
__device__ __forceinline__ void cpasync16(uint32_t dst, const void* src){
    asm volatile("cp.async.ca.shared.global [%0], [%1], 16;" :: "r"(dst), "l"(src));
}
#define CP_COMMIT() asm volatile("cp.async.commit_group;" ::: "memory")
template<int N>
__device__ __forceinline__ void cp_wait(){
    asm volatile("cp.async.wait_group %0;" :: "n"(N) : "memory");
}
__device__ __forceinline__ void ldsm4(uint32_t* r, uint32_t addr){
    asm volatile("ldmatrix.sync.aligned.m8n8.x4.shared.b16 {%0,%1,%2,%3}, [%4];"
        : "=r"(r[0]), "=r"(r[1]), "=r"(r[2]), "=r"(r[3]) : "r"(addr));
}
// fp16 warp MMA: D(16x8,f32) += A(16x16,f16) * B(16x8,f16)
__device__ __forceinline__ void mma16(float* c, const uint32_t* a, uint32_t b0, uint32_t b1){
    asm volatile(
        "mma.sync.aligned.m16n8k16.row.col.f32.f16.f16.f32 "
        "{%0,%1,%2,%3},{%4,%5,%6,%7},{%8,%9},{%0,%1,%2,%3};"
        : "+f"(c[0]), "+f"(c[1]), "+f"(c[2]), "+f"(c[3])
        : "r"(a[0]), "r"(a[1]), "r"(a[2]), "r"(a[3]), "r"(b0), "r"(b1));
}

// ---------------- fp16 tensor GEMM: C = epi(A[MxK] @ B^T + bias) -------------
// A fp16 [M][Kd]; B fp16 [N][Kd] (pre-transposed). CTA 128 x TN, 256 threads,
// 8 warps (2 row x 4 col), warp tile 64 x TN/4. K staged by 32 (2 k16 steps),
// 4-buffer cp.async pipeline, ldmatrix fragment feeds.
// EPI: 0=bias->f16 | 1=bias+GELU->f16 | 2=bias+res->f32+f16 | 3=bias+GLU->f32
//      4 = EPI2 + block sum/sumsq stats -> part[]
template<int TN, int EPI>
__global__ void __launch_bounds__(256,1) hgemm_k(
    const __half* __restrict__ A, const __half* __restrict__ B,
    const float* __restrict__ bias, const float* __restrict__ res,
    float* __restrict__ C, __half* __restrict__ Ch,
    int Kd, float rscale, int Cs, float2* __restrict__ part)
{
    constexpr int WN   = TN/4;
    constexpr int NJ   = WN/8;
    constexpr int A_ST = 128*40;
    constexpr int B_ST = TN*40;

    extern __shared__ __align__(16) __half smh[];
    __half* Ash = smh;
    __half* Bsh = smh + 4*A_ST;

    int tid = threadIdx.x, lane = tid & 31, wid = tid >> 5;
    int wr = wid >> 2, wc = wid & 3;
    int g = lane >> 2, tg = lane & 3;
    int row0 = blockIdx.y*128, col0 = blockIdx.x*TN;

    const __half* Ag = A + (size_t)row0*Kd;
    const __half* Bg = B + (size_t)col0*Kd;
    uint32_t sA = (uint32_t)__cvta_generic_to_shared(Ash);
    uint32_t sB = (uint32_t)__cvta_generic_to_shared(Bsh);

    auto loadA = [&](int kt){
        int k0 = kt*32;
        uint32_t base = sA + (kt & 3)*(A_ST*2);
        #pragma unroll
        for (int i = 0; i < 2; i++){
            int f = tid + i*256;
            int m = f >> 2, seg = f & 3;
            cpasync16(base + (uint32_t)(m*80 + seg*16),
                      Ag + (size_t)m*Kd + k0 + seg*8);
        }
    };
    auto loadB = [&](int kt){
        int k0 = kt*32;
        uint32_t base = sB + (kt & 3)*(B_ST*2);
        #pragma unroll
        for (int i = 0; i < TN/64; i++){
            int f = tid + i*256;
            int n = f >> 2, seg = f & 3;
            cpasync16(base + (uint32_t)(n*80 + seg*16),
                      Bg + (size_t)n*Kd + k0 + seg*8);
        }
    };

    // ldmatrix per-thread base addresses
    uint32_t aBase = sA + (uint32_t)(((wr*64 + (lane & 15))*40 + ((lane >> 4) << 3)) * 2);
    uint32_t bBase = sB + (uint32_t)(((wc*WN + ((lane >> 4) & 1)*8 + (lane & 7))*40
                                     + (((lane >> 3) & 1) << 3)) * 2);

    float acc[4][NJ][4];
    #pragma unroll
    for (int mi=0;mi<4;mi++)
        #pragma unroll
        for (int nj=0;nj<NJ;nj++)
            #pragma unroll
            for (int q=0;q<4;q++) acc[mi][nj][q]=0.f;

    int nk = Kd >> 5;
    loadA(0); loadB(0); CP_COMMIT();
    loadA(1); loadB(1); CP_COMMIT();
    loadA(2); loadB(2); CP_COMMIT();

    for (int kt = 0; kt < nk; ++kt){
        cp_wait<2>();
        __syncthreads();
        if (kt + 3 < nk){ loadA(kt+3); loadB(kt+3); }
        CP_COMMIT();

        int buf = kt & 3;
        uint32_t aB = aBase + (uint32_t)(buf*A_ST*2);
        uint32_t bB = bBase + (uint32_t)(buf*B_ST*2);
        #pragma unroll
        for (int ks = 0; ks < 2; ++ks){
            int k0h = ks*16;
            uint32_t a[4][4];
            #pragma unroll
            for (int mi=0;mi<4;mi++)
                ldsm4(a[mi], aB + (uint32_t)((mi*16*40 + k0h)*2));
            #pragma unroll
            for (int nj2=0;nj2<NJ/2;nj2++){
                uint32_t bb[4];
                ldsm4(bb, bB + (uint32_t)((nj2*16*40 + k0h)*2));
                #pragma unroll
                for (int mi=0;mi<4;mi++)
                    mma16(acc[mi][2*nj2  ], a[mi], bb[0], bb[1]);
                #pragma unroll
                for (int mi=0;mi<4;mi++)
                    mma16(acc[mi][2*nj2+1], a[mi], bb[2], bb[3]);
            }
        }
    }

    // epilogue
    float s_sum = 0.f, s_sq = 0.f;
    #pragma unroll
    for (int nj=0;nj<NJ;nj++){
        int c = col0 + wc*WN + nj*8 + tg*2;
        float2 bi = *(const float2*)&bias[c];
        #pragma unroll
        for (int mi=0;mi<4;mi++){
            int r0 = row0 + wr*64 + mi*16 + g;
            float v0 = acc[mi][nj][0] + bi.x;
            float v1 = acc[mi][nj][1] + bi.y;
            float v2 = acc[mi][nj][2] + bi.x;
            float v3 = acc[mi][nj][3] + bi.y;
            if (EPI == 1){
                v0=gelu_f(v0); v1=gelu_f(v1); v2=gelu_f(v2); v3=gelu_f(v3);
                *(__half2*)&Ch[(size_t)r0*Cs + c]     = __floats2half2_rn(v0, v1);
                *(__half2*)&Ch[(size_t)(r0+8)*Cs + c] = __floats2half2_rn(v2, v3);
            } else if (EPI == 2 || EPI == 4){
                float2 r0v = *(const float2*)&res[(size_t)r0*Cs + c];
                float2 r1v = *(const float2*)&res[(size_t)(r0+8)*Cs + c];
                v0 = fmaf(rscale, v0, r0v.x); v1 = fmaf(rscale, v1, r0v.y);
                v2 = fmaf(rscale, v2, r1v.x); v3 = fmaf(rscale, v3, r1v.y);
                *(float2*)&C[(size_t)r0*Cs + c]     = make_float2(v0, v1);
                *(float2*)&C[(size_t)(r0+8)*Cs + c] = make_float2(v2, v3);
                *(__half2*)&Ch[(size_t)r0*Cs + c]     = __floats2half2_rn(v0, v1);
                *(__half2*)&Ch[(size_t)(r0+8)*Cs + c] = __floats2half2_rn(v2, v3);
                if (EPI == 4){
                    s_sum += v0+v1+v2+v3;
                    s_sq  = fmaf(v0,v0,fmaf(v1,v1,fmaf(v2,v2,fmaf(v3,v3,s_sq))));
                }
            } else if (EPI == 3){
                int co = c >> 1;
                C[(size_t)r0*Cs + co]     = v0 * sigm(v1);
                C[(size_t)(r0+8)*Cs + co] = v2 * sigm(v3);
            } else {
                *(__half2*)&Ch[(size_t)r0*Cs + c]     = __floats2half2_rn(v0, v1);
                *(__half2*)&Ch[(size_t)(r0+8)*Cs + c] = __floats2half2_rn(v2, v3);
            }
        }
    }
    if (EPI == 4){
        __syncthreads();
        float* red = (float*)smh;
        red[tid] = s_sum; red[256 + tid] = s_sq;
        __syncthreads();
        for (int o=128;o>0;o>>=1){
            if (tid < o){ red[tid] += red[tid+o]; red[256+tid] += red[256+tid+o]; }
            __syncthreads();
        }
        if (tid == 0)
            part[blockIdx.y*gridDim.x + blockIdx.x] = make_float2(red[0], red[256]);
    }
}

// ---------------- merged prep: weight transpose+convert, dd table, pw1 bias ----
__global__ void wconv_all(const float* __restrict__ ff1w1, const float* __restrict__ ff1w2,
                          const float* __restrict__ qkvw,  const float* __restrict__ outw,
                          const float* __restrict__ pw1w,  const float* __restrict__ pw2w,
                          const float* __restrict__ ff2w1, const float* __restrict__ ff2w2,
                          __half* __restrict__ W,
                          const float* __restrict__ rel_embed, float* __restrict__ ddt,
                          const float* __restrict__ pw1b, float* __restrict__ bp){
    int bI = blockIdx.x;
    int ltid = threadIdx.y*32 + threadIdx.x;
    if (bI >= 5888){
        if (bI < 5952){ // dd table
            int idx = (bI - 5888)*256 + ltid;
            if (idx < 8*2047){
                int h = idx / 2047;
                int rpos = idx % 2047;
                int rel = rpos - 1023;
                int sign = (rel >= 0) ? 1 : 0;
                int a = (rel >= 0) ? rel : -rel;
                int bucket;
                if (a < 80) bucket = a;
                else {
                    float lr = logf((float)a / 80.0f) / logf(10.0f);
                    int lp = 80 + (int)(lr * 80.0f);
                    bucket = (lp < 159) ? lp : 159;
                }
                bucket += sign*160;
                if (bucket < 0) bucket = 0;
                if (bucket > 319) bucket = 319;
                ddt[idx] = rel_embed[bucket*8 + h];
            }
        } else {       // pw1 bias permutation
            #pragma unroll
            for (int i=0;i<4;i++){
                int c = ltid + i*256;
                bp[c] = pw1b[(c>>1) + (c&1)*512];
            }
        }
        return;
    }
    __shared__ float t[32][33];
    const float* src; int K, N, cOff, rStr, tilesX; unsigned base;
    if      (bI < 1024){            src=ff1w1; K=512;  N=2048; cOff=0;   base=W_FF1A;     rStr=1; tilesX=64; }
    else if (bI < 2048){ bI-=1024;  src=ff1w2; K=2048; N=512;  cOff=0;   base=W_FF1B;     rStr=1; tilesX=16; }
    else if (bI < 2816){ bI-=2048;  src=qkvw;  K=512;  N=1536; cOff=0;   base=W_QKV;      rStr=1; tilesX=48; }
    else if (bI < 3072){ bI-=2816;  src=outw;  K=512;  N=512;  cOff=0;   base=W_OUT;      rStr=1; tilesX=16; }
    else if (bI < 3328){ bI-=3072;  src=pw1w;  K=512;  N=1024; cOff=0;   base=W_PW1;      rStr=2; tilesX=16; }
    else if (bI < 3584){ bI-=3328;  src=pw1w;  K=512;  N=1024; cOff=512; base=W_PW1+512u; rStr=2; tilesX=16; }
    else if (bI < 3840){ bI-=3584;  src=pw2w;  K=512;  N=512;  cOff=0;   base=W_PW2;      rStr=1; tilesX=16; }
    else if (bI < 4864){ bI-=3840;  src=ff2w1; K=512;  N=2048; cOff=0;   base=W_FF2A;     rStr=1; tilesX=64; }
    else               { bI-=4864;  src=ff2w2; K=2048; N=512;  cOff=0;   base=W_FF2B;     rStr=1; tilesX=16; }
    int n0 = (bI % tilesX)*32, k0 = (bI / tilesX)*32;
    int lx = threadIdx.x, ly = threadIdx.y;
    #pragma unroll
    for (int i=0;i<32;i+=8)
        t[ly+i][lx] = src[(size_t)(k0+ly+i)*N + cOff + n0 + lx];
    __syncthreads();
    #pragma unroll
    for (int i=0;i<32;i+=8)
        W[base + (size_t)(n0+ly+i)*K*rStr + k0 + lx] = __float2half(t[lx][ly+i]);
}

// ---------------- transposes ----------------
__global__ void transpose_bdt_btd(const float* __restrict__ in, float* __restrict__ out,
                                  __half* __restrict__ outh){
    __shared__ float tile[32][33];
    int b = blockIdx.z;
    int t0 = blockIdx.x*32, d0 = blockIdx.y*32;
    int lx = threadIdx.x, ly = threadIdx.y;
    #pragma unroll
    for (int i=0;i<32;i+=8)
        tile[ly+i][lx] = in[((size_t)b*512 + d0+ly+i)*1024 + t0 + lx];
    __syncthreads();
    #pragma unroll
    for (int i=0;i<32;i+=8){
        float v = tile[lx][ly+i];
        size_t o = ((size_t)b*1024 + t0+ly+i)*512 + d0 + lx;
        out[o] = v;
        outh[o] = __float2half(v);
    }
}
__global__ void transpose_btd_bdt(const float* __restrict__ in, float* __restrict__ out){
    __shared__ float tile[32][33];
    int b = blockIdx.z;
    int d0 = blockIdx.x*32, t0 = blockIdx.y*32;
    int lx = threadIdx.x, ly = threadIdx.y;
    #pragma unroll
    for (int i=0;i<32;i+=8)
        tile[ly+i][lx] = in[((size_t)b*1024 + t0+ly+i)*512 + d0 + lx];
    __syncthreads();
    #pragma unroll
    for (int i=0;i<32;i+=8)
        out[((size_t)b*512 + d0+ly+i)*1024 + t0 + lx] = tile[lx][ly+i];
}

// ---------------- fp16 tensor-core flash attention with gated rel-pos bias -----
__global__ void __launch_bounds__(128) flash_h_k(
    const __half* __restrict__ qkv,    // [B,T,1536] fp16
    const float* __restrict__ gate_u, const float* __restrict__ gate_w,
    const float* __restrict__ gate_scale, const float* __restrict__ ddt,
    __half* __restrict__ outh)         // fp16 [B,T,512]
{
    extern __shared__ __align__(16) __half smh[];
    __half* Qs = smh;                  // [64 m][72 d]
    __half* Ks = Qs + 64*72;           // [64 s][72 d]
    __half* Vt = Ks + 64*72;           // [64 d][72 s]
    __half* Ps = Vt + 64*72;           // [64 m][72 s]
    float* dds   = (float*)(Ps + 64*72);
    float* coefs = dds + 128;

    int tid = threadIdx.x, lane = tid & 31, wid = tid >> 5;
    int g = lane >> 2, tg = lane & 3;
    int t0 = blockIdx.x * 64;
    int h  = blockIdx.y;
    int b  = blockIdx.z;
    int m0 = wid * 16;

    const __half* qbase = qkv + (size_t)b*1024*1536 + h*64;
    const __half* kbase = qbase + 512;
    const __half* vbase = qbase + 1024;

    uint32_t sQ = (uint32_t)__cvta_generic_to_shared(Qs);
    uint32_t sK = (uint32_t)__cvta_generic_to_shared(Ks);
    uint32_t sV = (uint32_t)__cvta_generic_to_shared(Vt);
    uint32_t sP = (uint32_t)__cvta_generic_to_shared(Ps);
    // per-thread ldmatrix offsets (stride 72 halves)
    uint32_t offA = (uint32_t)((((lane & 15))*72 + ((lane >> 4) << 3)) * 2);   // + m0 row base
    uint32_t offB = (uint32_t)(((((lane >> 4) & 1)*8 + (lane & 7))*72
                                + (((lane >> 3) & 1) << 3)) * 2);

    { // load Q tile
        int m = tid >> 1, hf = (tid & 1) * 32;
        const __half* qr = qbase + (size_t)(t0+m)*1536 + hf;
        #pragma unroll
        for (int i=0;i<4;i++)
            *(uint4*)&Qs[m*72 + hf + i*8] = *(const uint4*)(qr + i*8);
    }
    __syncthreads();
    if (tid < 64){ // per-query gate coefficient
        float du=0.f, dw=0.f;
        #pragma unroll
        for (int d=0; d<64; d++){
            float qv = __half2float(Qs[tid*72 + d]);
            du = fmaf(qv, gate_u[h*64+d], du);
            dw = fmaf(qv, gate_w[h*64+d], dw);
        }
        float gu = sigm(du), gr = sigm(dw);
        coefs[tid] = 1.0f + gu + (1.0f-gu)*gate_scale[h]*gr;
    }
    // register-resident Q fragments via ldmatrix
    uint32_t qf[4][4];
    #pragma unroll
    for (int ks=0;ks<4;ks++)
        ldsm4(qf[ks], sQ + (uint32_t)(m0*72*2) + offA + (uint32_t)(ks*16*2));

    float m_run[2] = {-3.0e38f, -3.0e38f}, l_run[2] = {0.f, 0.f};
    float O[8][4];
    #pragma unroll
    for (int nd=0;nd<8;nd++)
        #pragma unroll
        for (int q=0;q<4;q++) O[nd][q]=0.f;

    for (int s0 = 0; s0 < 1024; s0 += 64){
        __syncthreads();
        { // load K direct + V transposed
            int m = tid >> 1, hf = (tid & 1) * 32;
            const __half* kr = kbase + (size_t)(s0+m)*1536 + hf;
            const __half* vr = vbase + (size_t)(s0+m)*1536 + hf;
            #pragma unroll
            for (int i=0;i<4;i++){
                *(uint4*)&Ks[m*72 + hf + i*8] = *(const uint4*)(kr + i*8);
                __half vv[8];
                *(uint4*)vv = *(const uint4*)(vr + i*8);
                #pragma unroll
                for (int j=0;j<8;j++)
                    Vt[(hf + i*8 + j)*72 + m] = vv[j];
            }
        }
        if (tid < 127) dds[tid] = ddt[h*2047 + 960 + (s0 - t0) + tid];
        __syncthreads();

        // S = Q K^T  (4 k16 steps over d; B frags via ldmatrix x4 = 2 nj at once)
        float S[8][4];
        #pragma unroll
        for (int nj=0;nj<8;nj++)
            #pragma unroll
            for (int q=0;q<4;q++) S[nj][q]=0.f;
        #pragma unroll
        for (int ks=0;ks<4;ks++){
            #pragma unroll
            for (int nj2=0;nj2<4;nj2++){
                uint32_t bb[4];
                ldsm4(bb, sK + offB + (uint32_t)((nj2*16*72 + ks*16)*2));
                mma16(S[2*nj2  ], qf[ks], bb[0], bb[1]);
                mma16(S[2*nj2+1], qf[ks], bb[2], bb[3]);
            }
        }
        // bias: S*0.125 + coef[row]*dd[col-row+63]
        float c0 = coefs[m0+g], c1 = coefs[m0+g+8];
        #pragma unroll
        for (int nj=0;nj<8;nj++){
            int cn = nj*8 + tg*2;
            float dd0 = dds[cn     - (m0+g)   + 63];
            float dd1 = dds[cn + 1 - (m0+g)   + 63];
            float dd2 = dds[cn     - (m0+g+8) + 63];
            float dd3 = dds[cn + 1 - (m0+g+8) + 63];
            S[nj][0] = fmaf(S[nj][0], 0.125f, c0*dd0);
            S[nj][1] = fmaf(S[nj][1], 0.125f, c0*dd1);
            S[nj][2] = fmaf(S[nj][2], 0.125f, c1*dd2);
            S[nj][3] = fmaf(S[nj][3], 0.125f, c1*dd3);
        }
        // online softmax
        #pragma unroll
        for (int i=0;i<2;i++){
            float mx = -3.0e38f;
            #pragma unroll
            for (int nj=0;nj<8;nj++) mx = fmaxf(mx, fmaxf(S[nj][2*i], S[nj][2*i+1]));
            mx = fmaxf(mx, __shfl_xor_sync(0xffffffffu, mx, 1));
            mx = fmaxf(mx, __shfl_xor_sync(0xffffffffu, mx, 2));
            float mo = fmaxf(m_run[i], mx);
            float alpha = __expf(m_run[i] - mo);
            m_run[i] = mo;
            float ls = 0.f;
            #pragma unroll
            for (int nj=0;nj<8;nj++){
                float p0 = __expf(S[nj][2*i]   - mo);
                float p1 = __expf(S[nj][2*i+1] - mo);
                S[nj][2*i] = p0; S[nj][2*i+1] = p1;
                ls += p0 + p1;
            }
            ls += __shfl_xor_sync(0xffffffffu, ls, 1);
            ls += __shfl_xor_sync(0xffffffffu, ls, 2);
            l_run[i] = l_run[i]*alpha + ls;
            #pragma unroll
            for (int nd=0;nd<8;nd++){ O[nd][2*i] *= alpha; O[nd][2*i+1] *= alpha; }
        }
        // write P fp16 (per-warp region)
        #pragma unroll
        for (int nj=0;nj<8;nj++){
            *(__half2*)&Ps[(m0+g  )*72 + nj*8 + tg*2] = __floats2half2_rn(S[nj][0], S[nj][1]);
            *(__half2*)&Ps[(m0+g+8)*72 + nj*8 + tg*2] = __floats2half2_rn(S[nj][2], S[nj][3]);
        }
        __syncwarp();
        // O += P V  (4 k16 steps over keys; P/V frags via ldmatrix)
        #pragma unroll
        for (int ko=0;ko<4;ko++){
            uint32_t pa[4];
            ldsm4(pa, sP + (uint32_t)(m0*72*2) + offA + (uint32_t)(ko*16*2));
            #pragma unroll
            for (int nd2=0;nd2<4;nd2++){
                uint32_t bb[4];
                ldsm4(bb, sV + offB + (uint32_t)((nd2*16*72 + ko*16)*2));
                mma16(O[2*nd2  ], pa, bb[0], bb[1]);
                mma16(O[2*nd2+1], pa, bb[2], bb[3]);
            }
        }
    }
    float inv0 = 1.0f / l_run[0], inv1 = 1.0f / l_run[1];
    int r0 = t0 + m0 + g;
    #pragma unroll
    for (int nd=0;nd<8;nd++){
        int c = h*64 + nd*8 + tg*2;
        *(__half2*)&outh[((size_t)(b*1024 + r0  ))*512 + c] = __floats2half2_rn(O[nd][0]*inv0, O[nd][1]*inv0);
        *(__half2*)&outh[((size_t)(b*1024 + r0+8))*512 + c] = __floats2half2_rn(O[nd][2]*inv1, O[nd][3]*inv1);
    }
}

// ---------------- GroupNorm finalize + apply ----------------
__global__ void gn_final_k(const float2* __restrict__ part, float2* __restrict__ mv, int n){
    int b = blockIdx.x;
    float2 v = (threadIdx.x < n) ? part[b*n + threadIdx.x] : make_float2(0.f, 0.f);
    __shared__ float ss[256], sq[256];
    ss[threadIdx.x]=v.x; sq[threadIdx.x]=v.y;
    __syncthreads();
    for (int o=128;o>0;o>>=1){
        if (threadIdx.x<o){ ss[threadIdx.x]+=ss[threadIdx.x+o]; sq[threadIdx.x]+=sq[threadIdx.x+o]; }
        __syncthreads();
    }
    if (threadIdx.x==0){
        float mean = ss[0]*(1.0f/524288.0f);
        float var  = sq[0]*(1.0f/524288.0f) - mean*mean;
        mv[b] = make_float2(mean, rsqrtf(var + 1e-5f));
    }
}
template<bool SILU_>
__global__ void gn_apply_k(const float* __restrict__ x, const float2* __restrict__ mv,
                           const float* __restrict__ g, const float* __restrict__ be,
                           __half* __restrict__ y){
    size_t i4 = (size_t)blockIdx.x*256 + threadIdx.x;
    int b = (int)(i4 >> 17);
    int d = (int)((i4 & 127) << 2);
    float2 m = mv[b];
    float4 xv = *(const float4*)(x + i4*4);
    float4 gv = *(const float4*)(g + d);
    float4 bv = *(const float4*)(be + d);
    float4 o;
    o.x = (xv.x-m.x)*m.y*gv.x + bv.x;
    o.y = (xv.y-m.x)*m.y*gv.y + bv.y;
    o.z = (xv.z-m.x)*m.y*gv.z + bv.z;
    o.w = (xv.w-m.x)*m.y*gv.w + bv.w;
    if (SILU_){
        o.x *= sigm(o.x); o.y *= sigm(o.y); o.z *= sigm(o.z); o.w *= sigm(o.w);
    }
    __half2* yp = (__half2*)(y + i4*4);
    yp[0] = __floats2half2_rn(o.x, o.y);
    yp[1] = __floats2half2_rn(o.z, o.w);
}

// ---------------- depthwise conv (smem-tiled) + fused GN2 partial stats --------
__global__ void __launch_bounds__(512) dwconv_k(
    const float* __restrict__ in, const float* __restrict__ w,
    const float* __restrict__ bias, float* __restrict__ out,
    float2* __restrict__ part)
{
    __shared__ float tile[46][512];
    int d = threadIdx.x;
    int tt0 = blockIdx.x * 16;
    int b = blockIdx.y;
    const float* base = in + (size_t)b*524288;
    #pragma unroll
    for (int i=0;i<46;i++){
        int t = tt0 - 15 + i;
        tile[i][d] = (t >= 0 && t < 1024) ? base[(size_t)t*512 + d] : 0.f;
    }
    float wr[31];
    #pragma unroll
    for (int k=0;k<31;k++) wr[k] = w[d*31+k];
    float bi = bias[d];
    __syncthreads();
    float s_sum = 0.f, s_sq = 0.f;
    #pragma unroll
    for (int j=0;j<16;j++){
        float acc = bi;
        #pragma unroll
        for (int k=0;k<31;k++) acc = fmaf(tile[j+k][d], wr[k], acc);
        out[((size_t)b*1024 + tt0 + j)*512 + d] = acc;
        s_sum += acc;
        s_sq = fmaf(acc, acc, s_sq);
    }
    __syncthreads();
    float* red = &tile[0][0];
    red[d] = s_sum; red[512 + d] = s_sq;
    __syncthreads();
    for (int o=256;o>0;o>>=1){
        if (d < o){ red[d] += red[d+o]; red[512+d] += red[512+d+o]; }
        __syncthreads();
    }
    if (d == 0) part[b*64 + blockIdx.x] = make_float2(red[0], red[512]);
}

// ---------------- launch ----------------
extern "C" void kernel_launch(void* const* d_in, const int* in_sizes, int n_in,
                              void* d_out, int out_size) {
    const float* x      = (const float*)d_in[0];
    const float* ff1_w1 = (const float*)d_in[1];
    const float* ff1_b1 = (const float*)d_in[2];
    const float* ff1_w2 = (const float*)d_in[3];
    const float* ff1_b2 = (const float*)d_in[4];
    const float* qkv_w  = (const float*)d_in[5];
    const float* qkv_b  = (const float*)d_in[6];
    const float* out_w  = (const float*)d_in[7];
    const float* out_b  = (const float*)d_in[8];
    const float* gn1_g  = (const float*)d_in[9];
    const float* gn1_b  = (const float*)d_in[10];
    const float* pw1_w  = (const float*)d_in[11];
    const float* pw1_b  = (const float*)d_in[12];
    const float* dw_w   = (const float*)d_in[13];
    const float* dw_b   = (const float*)d_in[14];
    const float* gn2_g  = (const float*)d_in[15];
    const float* gn2_b  = (const float*)d_in[16];
    const float* pw2_w  = (const float*)d_in[17];
    const float* pw2_b  = (const float*)d_in[18];
    const float* ff2_w1 = (const float*)d_in[19];
    const float* ff2_b1 = (const float*)d_in[20];
    const float* ff2_w2 = (const float*)d_in[21];
    const float* ff2_b2 = (const float*)d_in[22];
    const float* rel_e  = (const float*)d_in[23];
    const float* gate_u = (const float*)d_in[24];
    const float* gate_w = (const float*)d_in[25];
    const float* gate_s = (const float*)d_in[26];

    float *S, *T2, *T3, *DDp, *BP;
    __half *Sh, *T1h, *T2h, *T3h, *W;
    float2 *PART, *MV;
    cudaGetSymbolAddress((void**)&S,  g_S);
    cudaGetSymbolAddress((void**)&T2, g_T2);
    cudaGetSymbolAddress((void**)&T3, g_T3);
    cudaGetSymbolAddress((void**)&Sh, g_Sh);
    cudaGetSymbolAddress((void**)&T1h,g_T1h);
    cudaGetSymbolAddress((void**)&T2h,g_T2h);
    cudaGetSymbolAddress((void**)&T3h,g_T3h);
    cudaGetSymbolAddress((void**)&W,  g_W);
    cudaGetSymbolAddress((void**)&BP, g_BP);
    cudaGetSymbolAddress((void**)&DDp,g_DD);
    cudaGetSymbolAddress((void**)&PART, g_part);
    cudaGetSymbolAddress((void**)&MV,   g_mv);

    const int FLASH_SMEM = 4*64*72*2 + 128*4 + 64*4;   // 37632
    cudaFuncSetAttribute((const void*)flash_h_k,
                         cudaFuncAttributeMaxDynamicSharedMemorySize, FLASH_SMEM);
    const int GS256 = (4*128*40 + 4*256*40) * 2;   // 122880
    const int GS128 = (4*128*40 + 4*128*40) * 2;   // 81920
    cudaFuncSetAttribute(hgemm_k<256,0>, cudaFuncAttributeMaxDynamicSharedMemorySize, GS256);
    cudaFuncSetAttribute(hgemm_k<256,1>, cudaFuncAttributeMaxDynamicSharedMemorySize, GS256);
    cudaFuncSetAttribute(hgemm_k<256,3>, cudaFuncAttributeMaxDynamicSharedMemorySize, GS256);
    cudaFuncSetAttribute(hgemm_k<128,2>, cudaFuncAttributeMaxDynamicSharedMemorySize, GS128);
    cudaFuncSetAttribute(hgemm_k<128,4>, cudaFuncAttributeMaxDynamicSharedMemorySize, GS128);

    dim3 tb(32,8);
    // prep (one merged kernel + input transpose)
    transpose_bdt_btd<<<dim3(32,16,4), tb>>>(x, S, Sh);
    wconv_all<<<5953, tb>>>(ff1_w1, ff1_w2, qkv_w, out_w, pw1_w, pw2_w, ff2_w1, ff2_w2,
                            W, rel_e, DDp, pw1_b, BP);

    // FFN1 (half-step)
    hgemm_k<256,1><<<dim3(8,32),256,GS256>>>(Sh,  W+W_FF1A, ff1_b1, nullptr, nullptr, T1h, 512, 0.f, 2048, nullptr);
    hgemm_k<128,2><<<dim3(4,32),256,GS128>>>(T1h, W+W_FF1B, ff1_b2, S, S, Sh, 2048, 0.5f, 512, nullptr);
    // QKV (fp16 out)
    hgemm_k<256,0><<<dim3(6,32),256,GS256>>>(Sh,  W+W_QKV,  qkv_b,  nullptr, nullptr, T1h, 512, 0.f, 1536, nullptr);
    // attention
    flash_h_k<<<dim3(16,8,4),128,FLASH_SMEM>>>(T1h, gate_u, gate_w, gate_s, DDp, T2h);
    // out-proj + residual + fused GN1 stats
    hgemm_k<128,4><<<dim3(4,32),256,GS128>>>(T2h, W+W_OUT,  out_b,  S, S, Sh, 512, 1.0f, 512, PART);
    gn_final_k<<<4,256>>>(PART, MV, 32);
    gn_apply_k<false><<<2048,256>>>(S, MV, gn1_g, gn1_b, T2h);
    // pw1 + fused GLU
    hgemm_k<256,3><<<dim3(4,32),256,GS256>>>(T2h, W+W_PW1, BP, nullptr, T3, nullptr, 512, 0.f, 512, nullptr);
    // dwconv + fused GN2 stats
    dwconv_k<<<dim3(64,4),512>>>(T3, dw_w, dw_b, T2, PART);
    gn_final_k<<<4,256>>>(PART, MV, 64);
    gn_apply_k<true><<<2048,256>>>(T2, MV, gn2_g, gn2_b, T3h);
    hgemm_k<128,2><<<dim3(4,32),256,GS128>>>(T3h, W+W_PW2,  pw2_b,  S, S, Sh, 512, 1.0f, 512, nullptr);
    // FFN2 (half-step)
    hgemm_k<256,1><<<dim3(8,32),256,GS256>>>(Sh,  W+W_FF2A, ff2_b1, nullptr, nullptr, T1h, 512, 0.f, 2048, nullptr);
    hgemm_k<128,2><<<dim3(4,32),256,GS128>>>(T1h, W+W_FF2B, ff2_b2, S, S, Sh, 2048, 0.5f, 512, nullptr);
    // s -> out [B,D,T]
    transpose_btd_bdt<<<dim3(16,32,4), tb>>>(S, (float*)d_out);
}

// round 10
// speedup vs baseline: 4.5954x; 1.0715x over previous
#include <cuda_runtime.h>
#include <cuda_fp16.h>
#include <math.h>
#include <cstdint>

// ---------------- scratch (device globals; allocation-free rule) ----------------
__device__ float  g_S [4096*512];      // residual stream fp32 [B,T,D]
__device__ float  g_T2[4096*512];      // dwconv out (gn2 in)
__device__ float  g_T3[4096*512];      // GLU out (dwconv in)
__device__ __half g_Sh [4096*512];     // fp16 mirror of S
__device__ __half g_T1h[4096*2048];    // ffn hidden / qkv out fp16
__device__ __half g_T2h[4096*512];     // flash out / gn1 out fp16
__device__ __half g_T3h[4096*512];     // gn2 out fp16
__device__ __half g_W  [6029312];      // all transposed fp16 weights
__device__ float  g_BP [1024];         // permuted pw1 bias
__device__ float  g_DD [8*2047];       // rel-pos bias table
__device__ float2 g_part[1024];
__device__ float2 g_mv[4];

// weight offsets (halves)
#define W_FF1A 0u
#define W_FF1B 1048576u
#define W_QKV  2097152u
#define W_OUT  2883584u
#define W_PW1  3145728u
#define W_PW2  3670016u
#define W_FF2A 3932160u
#define W_FF2B 4980736u

__device__ __forceinline__ float gelu_f(float x){
    return 0.5f * x * (1.0f + erff(x * 0.70710678118654752440f));
}
__device__ __forceinline__ float sigm(float x){ return 1.0f/(1.0f + expf(-x)); }

// ---------------- async-copy / ldmatrix helpers ----------------
__device__ __forceinline__ void cpasync16(uint32_t dst, const void* src){
    asm volatile("cp.async.ca.shared.global [%0], [%1], 16;" :: "r"(dst), "l"(src));
}
#define CP_COMMIT() asm volatile("cp.async.commit_group;" ::: "memory")
template<int N>
__device__ __forceinline__ void cp_wait(){
    asm volatile("cp.async.wait_group %0;" :: "n"(N) : "memory");
}
__device__ __forceinline__ void ldsm4(uint32_t* r, uint32_t addr){
    asm volatile("ldmatrix.sync.aligned.m8n8.x4.shared.b16 {%0,%1,%2,%3}, [%4];"
        : "=r"(r[0]), "=r"(r[1]), "=r"(r[2]), "=r"(r[3]) : "r"(addr));
}
// fp16 warp MMA: D(16x8,f32) += A(16x16,f16) * B(16x8,f16)
__device__ __forceinline__ void mma16(float* c, const uint32_t* a, uint32_t b0, uint32_t b1){
    asm volatile(
        "mma.sync.aligned.m16n8k16.row.col.f32.f16.f16.f32 "
        "{%0,%1,%2,%3},{%4,%5,%6,%7},{%8,%9},{%0,%1,%2,%3};"
        : "+f"(c[0]), "+f"(c[1]), "+f"(c[2]), "+f"(c[3])
        : "r"(a[0]), "r"(a[1]), "r"(a[2]), "r"(a[3]), "r"(b0), "r"(b1));
}

// ---------------- fp16 tensor GEMM: C = epi(A[MxK] @ B^T + bias) -------------
// A fp16 [M][Kd]; B fp16 [N][Kd] (pre-transposed). CTA 128x128, 256 threads,
// 8 warps (2 row x 4 col), warp tile 64x32. K staged by 32 (2 k16 steps),
// 3-stage cp.async pipeline, ldmatrix feeds, 2 CTAs/SM.
// EPI: 0=bias->f16 | 1=bias+GELU->f16 | 2=bias+res->f32+f16 | 3=bias+GLU->f32
//      4 = EPI2 + block sum/sumsq stats -> part[]
template<int EPI>
__global__ void __launch_bounds__(256,2) hgemm_k(
    const __half* __restrict__ A, const __half* __restrict__ B,
    const float* __restrict__ bias, const float* __restrict__ res,
    float* __restrict__ C, __half* __restrict__ Ch,
    int Kd, float rscale, int Cs, float2* __restrict__ part)
{
    constexpr int NJ   = 4;
    constexpr int A_ST = 128*40;
    constexpr int B_ST = 128*40;

    extern __shared__ __align__(16) __half smh[];
    __half* Ash = smh;                 // [3][128][40]
    __half* Bsh = smh + 3*A_ST;        // [3][128][40]

    int tid = threadIdx.x, lane = tid & 31, wid = tid >> 5;
    int wr = wid >> 2, wc = wid & 3;
    int g = lane >> 2, tg = lane & 3;
    int row0 = blockIdx.y*128, col0 = blockIdx.x*128;

    const __half* Ag = A + (size_t)row0*Kd;
    const __half* Bg = B + (size_t)col0*Kd;
    uint32_t sA = (uint32_t)__cvta_generic_to_shared(Ash);
    uint32_t sB = (uint32_t)__cvta_generic_to_shared(Bsh);

    auto loadA = [&](int kt, int buf){
        int k0 = kt*32;
        uint32_t base = sA + (uint32_t)(buf*(A_ST*2));
        #pragma unroll
        for (int i = 0; i < 2; i++){
            int f = tid + i*256;
            int m = f >> 2, seg = f & 3;
            cpasync16(base + (uint32_t)(m*80 + seg*16),
                      Ag + (size_t)m*Kd + k0 + seg*8);
        }
    };
    auto loadB = [&](int kt, int buf){
        int k0 = kt*32;
        uint32_t base = sB + (uint32_t)(buf*(B_ST*2));
        #pragma unroll
        for (int i = 0; i < 2; i++){
            int f = tid + i*256;
            int n = f >> 2, seg = f & 3;
            cpasync16(base + (uint32_t)(n*80 + seg*16),
                      Bg + (size_t)n*Kd + k0 + seg*8);
        }
    };

    uint32_t aBase = sA + (uint32_t)(((wr*64 + (lane & 15))*40 + ((lane >> 4) << 3)) * 2);
    uint32_t bBase = sB + (uint32_t)(((wc*32 + ((lane >> 4) & 1)*8 + (lane & 7))*40
                                     + (((lane >> 3) & 1) << 3)) * 2);

    float acc[4][NJ][4];
    #pragma unroll
    for (int mi=0;mi<4;mi++)
        #pragma unroll
        for (int nj=0;nj<NJ;nj++)
            #pragma unroll
            for (int q=0;q<4;q++) acc[mi][nj][q]=0.f;

    int nk = Kd >> 5;
    loadA(0,0); loadB(0,0); CP_COMMIT();
    loadA(1,1); loadB(1,1); CP_COMMIT();

    int buf = 0, nbuf = 2;
    for (int kt = 0; kt < nk; ++kt){
        cp_wait<1>();
        __syncthreads();
        if (kt + 2 < nk){ loadA(kt+2, nbuf); loadB(kt+2, nbuf); }
        CP_COMMIT();

        uint32_t aB = aBase + (uint32_t)(buf*A_ST*2);
        uint32_t bB = bBase + (uint32_t)(buf*B_ST*2);
        #pragma unroll
        for (int ks = 0; ks < 2; ++ks){
            int k0h = ks*16;
            uint32_t a[4][4];
            #pragma unroll
            for (int mi=0;mi<4;mi++)
                ldsm4(a[mi], aB + (uint32_t)((mi*16*40 + k0h)*2));
            #pragma unroll
            for (int nj2=0;nj2<NJ/2;nj2++){
                uint32_t bb[4];
                ldsm4(bb, bB + (uint32_t)((nj2*16*40 + k0h)*2));
                #pragma unroll
                for (int mi=0;mi<4;mi++)
                    mma16(acc[mi][2*nj2  ], a[mi], bb[0], bb[1]);
                #pragma unroll
                for (int mi=0;mi<4;mi++)
                    mma16(acc[mi][2*nj2+1], a[mi], bb[2], bb[3]);
            }
        }
        buf = (buf == 2) ? 0 : buf+1;
        nbuf = (nbuf == 2) ? 0 : nbuf+1;
    }

    // epilogue
    float s_sum = 0.f, s_sq = 0.f;
    #pragma unroll
    for (int nj=0;nj<NJ;nj++){
        int c = col0 + wc*32 + nj*8 + tg*2;
        float2 bi = *(const float2*)&bias[c];
        #pragma unroll
        for (int mi=0;mi<4;mi++){
            int r0 = row0 + wr*64 + mi*16 + g;
            float v0 = acc[mi][nj][0] + bi.x;
            float v1 = acc[mi][nj][1] + bi.y;
            float v2 = acc[mi][nj][2] + bi.x;
            float v3 = acc[mi][nj][3] + bi.y;
            if (EPI == 1){
                v0=gelu_f(v0); v1=gelu_f(v1); v2=gelu_f(v2); v3=gelu_f(v3);
                *(__half2*)&Ch[(size_t)r0*Cs + c]     = __floats2half2_rn(v0, v1);
                *(__half2*)&Ch[(size_t)(r0+8)*Cs + c] = __floats2half2_rn(v2, v3);
            } else if (EPI == 2 || EPI == 4){
                float2 r0v = *(const float2*)&res[(size_t)r0*Cs + c];
                float2 r1v = *(const float2*)&res[(size_t)(r0+8)*Cs + c];
                v0 = fmaf(rscale, v0, r0v.x); v1 = fmaf(rscale, v1, r0v.y);
                v2 = fmaf(rscale, v2, r1v.x); v3 = fmaf(rscale, v3, r1v.y);
                *(float2*)&C[(size_t)r0*Cs + c]     = make_float2(v0, v1);
                *(float2*)&C[(size_t)(r0+8)*Cs + c] = make_float2(v2, v3);
                *(__half2*)&Ch[(size_t)r0*Cs + c]     = __floats2half2_rn(v0, v1);
                *(__half2*)&Ch[(size_t)(r0+8)*Cs + c] = __floats2half2_rn(v2, v3);
                if (EPI == 4){
                    s_sum += v0+v1+v2+v3;
                    s_sq  = fmaf(v0,v0,fmaf(v1,v1,fmaf(v2,v2,fmaf(v3,v3,s_sq))));
                }
            } else if (EPI == 3){
                int co = c >> 1;
                C[(size_t)r0*Cs + co]     = v0 * sigm(v1);
                C[(size_t)(r0+8)*Cs + co] = v2 * sigm(v3);
            } else {
                *(__half2*)&Ch[(size_t)r0*Cs + c]     = __floats2half2_rn(v0, v1);
                *(__half2*)&Ch[(size_t)(r0+8)*Cs + c] = __floats2half2_rn(v2, v3);
            }
        }
    }
    if (EPI == 4){
        __syncthreads();
        float* red = (float*)smh;
        red[tid] = s_sum; red[256 + tid] = s_sq;
        __syncthreads();
        for (int o=128;o>0;o>>=1){
            if (tid < o){ red[tid] += red[tid+o]; red[256+tid] += red[256+tid+o]; }
            __syncthreads();
        }
        if (tid == 0)
            part[blockIdx.y*gridDim.x + blockIdx.x] = make_float2(red[0], red[256]);
    }
}

// ---------------- merged prep: weight transpose+convert, dd table, pw1 bias ----
__global__ void wconv_all(const float* __restrict__ ff1w1, const float* __restrict__ ff1w2,
                          const float* __restrict__ qkvw,  const float* __restrict__ outw,
                          const float* __restrict__ pw1w,  const float* __restrict__ pw2w,
                          const float* __restrict__ ff2w1, const float* __restrict__ ff2w2,
                          __half* __restrict__ W,
                          const float* __restrict__ rel_embed, float* __restrict__ ddt,
                          const float* __restrict__ pw1b, float* __restrict__ bp){
    int bI = blockIdx.x;
    int ltid = threadIdx.y*32 + threadIdx.x;
    if (bI >= 5888){
        if (bI < 5952){ // dd table
            int idx = (bI - 5888)*256 + ltid;
            if (idx < 8*2047){
                int h = idx / 2047;
                int rpos = idx % 2047;
                int rel = rpos - 1023;
                int sign = (rel >= 0) ? 1 : 0;
                int a = (rel >= 0) ? rel : -rel;
                int bucket;
                if (a < 80) bucket = a;
                else {
                    float lr = logf((float)a / 80.0f) / logf(10.0f);
                    int lp = 80 + (int)(lr * 80.0f);
                    bucket = (lp < 159) ? lp : 159;
                }
                bucket += sign*160;
                if (bucket < 0) bucket = 0;
                if (bucket > 319) bucket = 319;
                ddt[idx] = rel_embed[bucket*8 + h];
            }
        } else {       // pw1 bias permutation
            #pragma unroll
            for (int i=0;i<4;i++){
                int c = ltid + i*256;
                bp[c] = pw1b[(c>>1) + (c&1)*512];
            }
        }
        return;
    }
    __shared__ float t[32][33];
    const float* src; int K, N, cOff, rStr, tilesX; unsigned base;
    if      (bI < 1024){            src=ff1w1; K=512;  N=2048; cOff=0;   base=W_FF1A;     rStr=1; tilesX=64; }
    else if (bI < 2048){ bI-=1024;  src=ff1w2; K=2048; N=512;  cOff=0;   base=W_FF1B;     rStr=1; tilesX=16; }
    else if (bI < 2816){ bI-=2048;  src=qkvw;  K=512;  N=1536; cOff=0;   base=W_QKV;      rStr=1; tilesX=48; }
    else if (bI < 3072){ bI-=2816;  src=outw;  K=512;  N=512;  cOff=0;   base=W_OUT;      rStr=1; tilesX=16; }
    else if (bI < 3328){ bI-=3072;  src=pw1w;  K=512;  N=1024; cOff=0;   base=W_PW1;      rStr=2; tilesX=16; }
    else if (bI < 3584){ bI-=3328;  src=pw1w;  K=512;  N=1024; cOff=512; base=W_PW1+512u; rStr=2; tilesX=16; }
    else if (bI < 3840){ bI-=3584;  src=pw2w;  K=512;  N=512;  cOff=0;   base=W_PW2;      rStr=1; tilesX=16; }
    else if (bI < 4864){ bI-=3840;  src=ff2w1; K=512;  N=2048; cOff=0;   base=W_FF2A;     rStr=1; tilesX=64; }
    else               { bI-=4864;  src=ff2w2; K=2048; N=512;  cOff=0;   base=W_FF2B;     rStr=1; tilesX=16; }
    int n0 = (bI % tilesX)*32, k0 = (bI / tilesX)*32;
    int lx = threadIdx.x, ly = threadIdx.y;
    #pragma unroll
    for (int i=0;i<32;i+=8)
        t[ly+i][lx] = src[(size_t)(k0+ly+i)*N + cOff + n0 + lx];
    __syncthreads();
    #pragma unroll
    for (int i=0;i<32;i+=8)
        W[base + (size_t)(n0+ly+i)*K*rStr + k0 + lx] = __float2half(t[lx][ly+i]);
}

// ---------------- transposes ----------------
__global__ void transpose_bdt_btd(const float* __restrict__ in, float* __restrict__ out,
                                  __half* __restrict__ outh){
    __shared__ float tile[32][33];
    int b = blockIdx.z;
    int t0 = blockIdx.x*32, d0 = blockIdx.y*32;
    int lx = threadIdx.x, ly = threadIdx.y;
    #pragma unroll
    for (int i=0;i<32;i+=8)
        tile[ly+i][lx] = in[((size_t)b*512 + d0+ly+i)*1024 + t0 + lx];
    __syncthreads();
    #pragma unroll
    for (int i=0;i<32;i+=8){
        float v = tile[lx][ly+i];
        size_t o = ((size_t)b*1024 + t0+ly+i)*512 + d0 + lx;
        out[o] = v;
        outh[o] = __float2half(v);
    }
}
__global__ void transpose_btd_bdt(const float* __restrict__ in, float* __restrict__ out){
    __shared__ float tile[32][33];
    int b = blockIdx.z;
    int d0 = blockIdx.x*32, t0 = blockIdx.y*32;
    int lx = threadIdx.x, ly = threadIdx.y;
    #pragma unroll
    for (int i=0;i<32;i+=8)
        tile[ly+i][lx] = in[((size_t)b*1024 + t0+ly+i)*512 + d0 + lx];
    __syncthreads();
    #pragma unroll
    for (int i=0;i<32;i+=8)
        out[((size_t)b*512 + d0+ly+i)*1024 + t0 + lx] = tile[lx][ly+i];
}

// ---------------- fp16 tensor-core flash attention with gated rel-pos bias -----
__global__ void __launch_bounds__(128) flash_h_k(
    const __half* __restrict__ qkv,    // [B,T,1536] fp16
    const float* __restrict__ gate_u, const float* __restrict__ gate_w,
    const float* __restrict__ gate_scale, const float* __restrict__ ddt,
    __half* __restrict__ outh)         // fp16 [B,T,512]
{
    extern __shared__ __align__(16) __half smh[];
    __half* Qs = smh;                  // [64 m][72 d]
    __half* Ks = Qs + 64*72;           // [64 s][72 d]
    __half* Vt = Ks + 64*72;           // [64 d][72 s]
    __half* Ps = Vt + 64*72;           // [64 m][72 s]
    float* dds   = (float*)(Ps + 64*72);
    float* coefs = dds + 128;

    int tid = threadIdx.x, lane = tid & 31, wid = tid >> 5;
    int g = lane >> 2, tg = lane & 3;
    int t0 = blockIdx.x * 64;
    int h  = blockIdx.y;
    int b  = blockIdx.z;
    int m0 = wid * 16;

    const __half* qbase = qkv + (size_t)b*1024*1536 + h*64;
    const __half* kbase = qbase + 512;
    const __half* vbase = qbase + 1024;

    uint32_t sQ = (uint32_t)__cvta_generic_to_shared(Qs);
    uint32_t sK = (uint32_t)__cvta_generic_to_shared(Ks);
    uint32_t sV = (uint32_t)__cvta_generic_to_shared(Vt);
    uint32_t sP = (uint32_t)__cvta_generic_to_shared(Ps);
    uint32_t offA = (uint32_t)((((lane & 15))*72 + ((lane >> 4) << 3)) * 2);
    uint32_t offB = (uint32_t)(((((lane >> 4) & 1)*8 + (lane & 7))*72
                                + (((lane >> 3) & 1) << 3)) * 2);

    { // load Q tile
        int m = tid >> 1, hf = (tid & 1) * 32;
        const __half* qr = qbase + (size_t)(t0+m)*1536 + hf;
        #pragma unroll
        for (int i=0;i<4;i++)
            *(uint4*)&Qs[m*72 + hf + i*8] = *(const uint4*)(qr + i*8);
    }
    __syncthreads();
    if (tid < 64){ // per-query gate coefficient
        float du=0.f, dw=0.f;
        #pragma unroll
        for (int d=0; d<64; d++){
            float qv = __half2float(Qs[tid*72 + d]);
            du = fmaf(qv, gate_u[h*64+d], du);
            dw = fmaf(qv, gate_w[h*64+d], dw);
        }
        float gu = sigm(du), gr = sigm(dw);
        coefs[tid] = 1.0f + gu + (1.0f-gu)*gate_scale[h]*gr;
    }
    uint32_t qf[4][4];
    #pragma unroll
    for (int ks=0;ks<4;ks++)
        ldsm4(qf[ks], sQ + (uint32_t)(m0*72*2) + offA + (uint32_t)(ks*16*2));

    float m_run[2] = {-3.0e38f, -3.0e38f}, l_run[2] = {0.f, 0.f};
    float O[8][4];
    #pragma unroll
    for (int nd=0;nd<8;nd++)
        #pragma unroll
        for (int q=0;q<4;q++) O[nd][q]=0.f;

    for (int s0 = 0; s0 < 1024; s0 += 64){
        __syncthreads();
        { // load K direct + V transposed
            int m = tid >> 1, hf = (tid & 1) * 32;
            const __half* kr = kbase + (size_t)(s0+m)*1536 + hf;
            const __half* vr = vbase + (size_t)(s0+m)*1536 + hf;
            #pragma unroll
            for (int i=0;i<4;i++){
                *(uint4*)&Ks[m*72 + hf + i*8] = *(const uint4*)(kr + i*8);
                __half vv[8];
                *(uint4*)vv = *(const uint4*)(vr + i*8);
                #pragma unroll
                for (int j=0;j<8;j++)
                    Vt[(hf + i*8 + j)*72 + m] = vv[j];
            }
        }
        if (tid < 127) dds[tid] = ddt[h*2047 + 960 + (s0 - t0) + tid];
        __syncthreads();

        float S[8][4];
        #pragma unroll
        for (int nj=0;nj<8;nj++)
            #pragma unroll
            for (int q=0;q<4;q++) S[nj][q]=0.f;
        #pragma unroll
        for (int ks=0;ks<4;ks++){
            #pragma unroll
            for (int nj2=0;nj2<4;nj2++){
                uint32_t bb[4];
                ldsm4(bb, sK + offB + (uint32_t)((nj2*16*72 + ks*16)*2));
                mma16(S[2*nj2  ], qf[ks], bb[0], bb[1]);
                mma16(S[2*nj2+1], qf[ks], bb[2], bb[3]);
            }
        }
        float c0 = coefs[m0+g], c1 = coefs[m0+g+8];
        #pragma unroll
        for (int nj=0;nj<8;nj++){
            int cn = nj*8 + tg*2;
            float dd0 = dds[cn     - (m0+g)   + 63];
            float dd1 = dds[cn + 1 - (m0+g)   + 63];
            float dd2 = dds[cn     - (m0+g+8) + 63];
            float dd3 = dds[cn + 1 - (m0+g+8) + 63];
            S[nj][0] = fmaf(S[nj][0], 0.125f, c0*dd0);
            S[nj][1] = fmaf(S[nj][1], 0.125f, c0*dd1);
            S[nj][2] = fmaf(S[nj][2], 0.125f, c1*dd2);
            S[nj][3] = fmaf(S[nj][3], 0.125f, c1*dd3);
        }
        #pragma unroll
        for (int i=0;i<2;i++){
            float mx = -3.0e38f;
            #pragma unroll
            for (int nj=0;nj<8;nj++) mx = fmaxf(mx, fmaxf(S[nj][2*i], S[nj][2*i+1]));
            mx = fmaxf(mx, __shfl_xor_sync(0xffffffffu, mx, 1));
            mx = fmaxf(mx, __shfl_xor_sync(0xffffffffu, mx, 2));
            float mo = fmaxf(m_run[i], mx);
            float alpha = __expf(m_run[i] - mo);
            m_run[i] = mo;
            float ls = 0.f;
            #pragma unroll
            for (int nj=0;nj<8;nj++){
                float p0 = __expf(S[nj][2*i]   - mo);
                float p1 = __expf(S[nj][2*i+1] - mo);
                S[nj][2*i] = p0; S[nj][2*i+1] = p1;
                ls += p0 + p1;
            }
            ls += __shfl_xor_sync(0xffffffffu, ls, 1);
            ls += __shfl_xor_sync(0xffffffffu, ls, 2);
            l_run[i] = l_run[i]*alpha + ls;
            #pragma unroll
            for (int nd=0;nd<8;nd++){ O[nd][2*i] *= alpha; O[nd][2*i+1] *= alpha; }
        }
        #pragma unroll
        for (int nj=0;nj<8;nj++){
            *(__half2*)&Ps[(m0+g  )*72 + nj*8 + tg*2] = __floats2half2_rn(S[nj][0], S[nj][1]);
            *(__half2*)&Ps[(m0+g+8)*72 + nj*8 + tg*2] = __floats2half2_rn(S[nj][2], S[nj][3]);
        }
        __syncwarp();
        #pragma unroll
        for (int ko=0;ko<4;ko++){
            uint32_t pa[4];
            ldsm4(pa, sP + (uint32_t)(m0*72*2) + offA + (uint32_t)(ko*16*2));
            #pragma unroll
            for (int nd2=0;nd2<4;nd2++){
                uint32_t bb[4];
                ldsm4(bb, sV + offB + (uint32_t)((nd2*16*72 + ko*16)*2));
                mma16(O[2*nd2  ], pa, bb[0], bb[1]);
                mma16(O[2*nd2+1], pa, bb[2], bb[3]);
            }
        }
    }
    float inv0 = 1.0f / l_run[0], inv1 = 1.0f / l_run[1];
    int r0 = t0 + m0 + g;
    #pragma unroll
    for (int nd=0;nd<8;nd++){
        int c = h*64 + nd*8 + tg*2;
        *(__half2*)&outh[((size_t)(b*1024 + r0  ))*512 + c] = __floats2half2_rn(O[nd][0]*inv0, O[nd][1]*inv0);
        *(__half2*)&outh[((size_t)(b*1024 + r0+8))*512 + c] = __floats2half2_rn(O[nd][2]*inv1, O[nd][3]*inv1);
    }
}

// ---------------- GroupNorm finalize + apply ----------------
__global__ void gn_final_k(const float2* __restrict__ part, float2* __restrict__ mv, int n){
    int b = blockIdx.x;
    float2 v = (threadIdx.x < n) ? part[b*n + threadIdx.x] : make_float2(0.f, 0.f);
    __shared__ float ss[256], sq[256];
    ss[threadIdx.x]=v.x; sq[threadIdx.x]=v.y;
    __syncthreads();
    for (int o=128;o>0;o>>=1){
        if (threadIdx.x<o){ ss[threadIdx.x]+=ss[threadIdx.x+o]; sq[threadIdx.x]+=sq[threadIdx.x+o]; }
        __syncthreads();
    }
    if (threadIdx.x==0){
        float mean = ss[0]*(1.0f/524288.0f);
        float var  = sq[0]*(1.0f/524288.0f) - mean*mean;
        mv[b] = make_float2(mean, rsqrtf(var + 1e-5f));
    }
}
template<bool SILU_>
__global__ void gn_apply_k(const float* __restrict__ x, const float2* __restrict__ mv,
                           const float* __restrict__ g, const float* __restrict__ be,
                           __half* __restrict__ y){
    size_t i4 = (size_t)blockIdx.x*256 + threadIdx.x;
    int b = (int)(i4 >> 17);
    int d = (int)((i4 & 127) << 2);
    float2 m = mv[b];
    float4 xv = *(const float4*)(x + i4*4);
    float4 gv = *(const float4*)(g + d);
    float4 bv = *(const float4*)(be + d);
    float4 o;
    o.x = (xv.x-m.x)*m.y*gv.x + bv.x;
    o.y = (xv.y-m.x)*m.y*gv.y + bv.y;
    o.z = (xv.z-m.x)*m.y*gv.z + bv.z;
    o.w = (xv.w-m.x)*m.y*gv.w + bv.w;
    if (SILU_){
        o.x *= sigm(o.x); o.y *= sigm(o.y); o.z *= sigm(o.z); o.w *= sigm(o.w);
    }
    __half2* yp = (__half2*)(y + i4*4);
    yp[0] = __floats2half2_rn(o.x, o.y);
    yp[1] = __floats2half2_rn(o.z, o.w);
}

// ---------------- depthwise conv (smem-tiled) + fused GN2 partial stats --------
__global__ void __launch_bounds__(512) dwconv_k(
    const float* __restrict__ in, const float* __restrict__ w,
    const float* __restrict__ bias, float* __restrict__ out,
    float2* __restrict__ part)
{
    __shared__ float tile[46][512];
    int d = threadIdx.x;
    int tt0 = blockIdx.x * 16;
    int b = blockIdx.y;
    const float* base = in + (size_t)b*524288;
    #pragma unroll
    for (int i=0;i<46;i++){
        int t = tt0 - 15 + i;
        tile[i][d] = (t >= 0 && t < 1024) ? base[(size_t)t*512 + d] : 0.f;
    }
    float wr[31];
    #pragma unroll
    for (int k=0;k<31;k++) wr[k] = w[d*31+k];
    float bi = bias[d];
    __syncthreads();
    float s_sum = 0.f, s_sq = 0.f;
    #pragma unroll
    for (int j=0;j<16;j++){
        float acc = bi;
        #pragma unroll
        for (int k=0;k<31;k++) acc = fmaf(tile[j+k][d], wr[k], acc);
        out[((size_t)b*1024 + tt0 + j)*512 + d] = acc;
        s_sum += acc;
        s_sq = fmaf(acc, acc, s_sq);
    }
    __syncthreads();
    float* red = &tile[0][0];
    red[d] = s_sum; red[512 + d] = s_sq;
    __syncthreads();
    for (int o=256;o>0;o>>=1){
        if (d < o){ red[d] += red[d+o]; red[512+d] += red[512+d+o]; }
        __syncthreads();
    }
    if (d == 0) part[b*64 + blockIdx.x] = make_float2(red[0], red[512]);
}

// ---------------- launch ----------------
extern "C" void kernel_launch(void* const* d_in, const int* in_sizes, int n_in,
                              void* d_out, int out_size) {
    const float* x      = (const float*)d_in[0];
    const float* ff1_w1 = (const float*)d_in[1];
    const float* ff1_b1 = (const float*)d_in[2];
    const float* ff1_w2 = (const float*)d_in[3];
    const float* ff1_b2 = (const float*)d_in[4];
    const float* qkv_w  = (const float*)d_in[5];
    const float* qkv_b  = (const float*)d_in[6];
    const float* out_w  = (const float*)d_in[7];
    const float* out_b  = (const float*)d_in[8];
    const float* gn1_g  = (const float*)d_in[9];
    const float* gn1_b  = (const float*)d_in[10];
    const float* pw1_w  = (const float*)d_in[11];
    const float* pw1_b  = (const float*)d_in[12];
    const float* dw_w   = (const float*)d_in[13];
    const float* dw_b   = (const float*)d_in[14];
    const float* gn2_g  = (const float*)d_in[15];
    const float* gn2_b  = (const float*)d_in[16];
    const float* pw2_w  = (const float*)d_in[17];
    const float* pw2_b  = (const float*)d_in[18];
    const float* ff2_w1 = (const float*)d_in[19];
    const float* ff2_b1 = (const float*)d_in[20];
    const float* ff2_w2 = (const float*)d_in[21];
    const float* ff2_b2 = (const float*)d_in[22];
    const float* rel_e  = (const float*)d_in[23];
    const float* gate_u = (const float*)d_in[24];
    const float* gate_w = (const float*)d_in[25];
    const float* gate_s = (const float*)d_in[26];

    float *S, *T2, *T3, *DDp, *BP;
    __half *Sh, *T1h, *T2h, *T3h, *W;
    float2 *PART, *MV;
    cudaGetSymbolAddress((void**)&S,  g_S);
    cudaGetSymbolAddress((void**)&T2, g_T2);
    cudaGetSymbolAddress((void**)&T3, g_T3);
    cudaGetSymbolAddress((void**)&Sh, g_Sh);
    cudaGetSymbolAddress((void**)&T1h,g_T1h);
    cudaGetSymbolAddress((void**)&T2h,g_T2h);
    cudaGetSymbolAddress((void**)&T3h,g_T3h);
    cudaGetSymbolAddress((void**)&W,  g_W);
    cudaGetSymbolAddress((void**)&BP, g_BP);
    cudaGetSymbolAddress((void**)&DDp,g_DD);
    cudaGetSymbolAddress((void**)&PART, g_part);
    cudaGetSymbolAddress((void**)&MV,   g_mv);

    const int FLASH_SMEM = 4*64*72*2 + 128*4 + 64*4;   // 37632
    cudaFuncSetAttribute((const void*)flash_h_k,
                         cudaFuncAttributeMaxDynamicSharedMemorySize, FLASH_SMEM);
    const int GS = 3*2*(128*40)*2;   // 61440
    cudaFuncSetAttribute(hgemm_k<0>, cudaFuncAttributeMaxDynamicSharedMemorySize, GS);
    cudaFuncSetAttribute(hgemm_k<1>, cudaFuncAttributeMaxDynamicSharedMemorySize, GS);
    cudaFuncSetAttribute(hgemm_k<2>, cudaFuncAttributeMaxDynamicSharedMemorySize, GS);
    cudaFuncSetAttribute(hgemm_k<3>, cudaFuncAttributeMaxDynamicSharedMemorySize, GS);
    cudaFuncSetAttribute(hgemm_k<4>, cudaFuncAttributeMaxDynamicSharedMemorySize, GS);

    dim3 tb(32,8);
    // prep (one merged kernel + input transpose)
    transpose_bdt_btd<<<dim3(32,16,4), tb>>>(x, S, Sh);
    wconv_all<<<5953, tb>>>(ff1_w1, ff1_w2, qkv_w, out_w, pw1_w, pw2_w, ff2_w1, ff2_w2,
                            W, rel_e, DDp, pw1_b, BP);

    // FFN1 (half-step)
    hgemm_k<1><<<dim3(16,32),256,GS>>>(Sh,  W+W_FF1A, ff1_b1, nullptr, nullptr, T1h, 512, 0.f, 2048, nullptr);
    hgemm_k<2><<<dim3( 4,32),256,GS>>>(T1h, W+W_FF1B, ff1_b2, S, S, Sh, 2048, 0.5f, 512, nullptr);
    // QKV (fp16 out)
    hgemm_k<0><<<dim3(12,32),256,GS>>>(Sh,  W+W_QKV,  qkv_b,  nullptr, nullptr, T1h, 512, 0.f, 1536, nullptr);
    // attention
    flash_h_k<<<dim3(16,8,4),128,FLASH_SMEM>>>(T1h, gate_u, gate_w, gate_s, DDp, T2h);
    // out-proj + residual + fused GN1 stats
    hgemm_k<4><<<dim3( 4,32),256,GS>>>(T2h, W+W_OUT,  out_b,  S, S, Sh, 512, 1.0f, 512, PART);
    gn_final_k<<<4,256>>>(PART, MV, 32);
    gn_apply_k<false><<<2048,256>>>(S, MV, gn1_g, gn1_b, T2h);
    // pw1 + fused GLU
    hgemm_k<3><<<dim3( 8,32),256,GS>>>(T2h, W+W_PW1, BP, nullptr, T3, nullptr, 512, 0.f, 512, nullptr);
    // dwconv + fused GN2 stats
    dwconv_k<<<dim3(64,4),512>>>(T3, dw_w, dw_b, T2, PART);
    gn_final_k<<<4,256>>>(PART, MV, 64);
    gn_apply_k<true><<<2048,256>>>(T2, MV, gn2_g, gn2_b, T3h);
    hgemm_k<2><<<dim3( 4,32),256,GS>>>(T3h, W+W_PW2,  pw2_b,  S, S, Sh, 512, 1.0f, 512, nullptr);
    // FFN2 (half-step)
    hgemm_k<1><<<dim3(16,32),256,GS>>>(Sh,  W+W_FF2A, ff2_b1, nullptr, nullptr, T1h, 512, 0.f, 2048, nullptr);
    hgemm_k<2><<<dim3( 4,32),256,GS>>>(T1h, W+W_FF2B, ff2_b2, S, S, Sh, 2048, 0.5f, 512, nullptr);
    // s -> out [B,D,T]
    transpose_btd_bdt<<<dim3(16,32,4), tb>>>(S, (float*)d_out);
}